// round 1
// baseline (speedup 1.0000x reference)
#include <cuda_runtime.h>
#include <math.h>

#define N_NODES 4096
#define D_FEAT  2048

// ---- scratch (allocation-free rule: __device__ globals) ----
__device__ float g_h[(size_t)N_NODES * D_FEAT];          // 32 MB
__device__ float g_s1[N_NODES];
__device__ float g_s2[N_NODES];
__device__ float g_P[(size_t)N_NODES * N_NODES];         // 64 MB: logits -> attention

// ============================================================
// Generic NN GEMM: C = A(MxK) @ B(KxNc), row-major.
// EPI = 0: plain store. EPI = 1: ELU.
// 128x128 tile, BK=16, 256 threads, 8x8 per thread.
// ============================================================
template<int EPI>
__global__ __launch_bounds__(256) void gemm_nn(
    const float* __restrict__ A, const float* __restrict__ B,
    float* __restrict__ C, int M, int K, int Nc) {
  __shared__ float As[16][132];   // stored transposed [k][m], padded
  __shared__ float Bs[16][128];   // [k][n]

  const int bm = blockIdx.y * 128;
  const int bn = blockIdx.x * 128;
  const int tid = threadIdx.x;
  const int tr = (tid >> 4) * 8;
  const int tc = (tid & 15) * 8;
  const int aRow = tid >> 2;         // 0..63 (+64)
  const int aCol = (tid & 3) * 4;    // 0,4,8,12
  const int bRow = tid >> 5;         // 0..7 (+8)
  const int bCol = (tid & 31) * 4;   // 0..124

  float acc[8][8];
#pragma unroll
  for (int i = 0; i < 8; i++)
#pragma unroll
    for (int j = 0; j < 8; j++) acc[i][j] = 0.f;

  for (int k0 = 0; k0 < K; k0 += 16) {
#pragma unroll
    for (int t = 0; t < 2; t++) {
      int r = aRow + t * 64;
      float4 v = *reinterpret_cast<const float4*>(
          &A[(size_t)(bm + r) * K + k0 + aCol]);
      As[aCol + 0][r] = v.x;
      As[aCol + 1][r] = v.y;
      As[aCol + 2][r] = v.z;
      As[aCol + 3][r] = v.w;
    }
#pragma unroll
    for (int t = 0; t < 2; t++) {
      int r = bRow + t * 8;
      *reinterpret_cast<float4*>(&Bs[r][bCol]) =
          *reinterpret_cast<const float4*>(&B[(size_t)(k0 + r) * Nc + bn + bCol]);
    }
    __syncthreads();

#pragma unroll
    for (int k = 0; k < 16; k++) {
      float ar[8], br[8];
#pragma unroll
      for (int i = 0; i < 8; i++) ar[i] = As[k][tr + i];
#pragma unroll
      for (int j = 0; j < 8; j++) br[j] = Bs[k][tc + j];
#pragma unroll
      for (int i = 0; i < 8; i++)
#pragma unroll
        for (int j = 0; j < 8; j++) acc[i][j] = fmaf(ar[i], br[j], acc[i][j]);
    }
    __syncthreads();
  }

#pragma unroll
  for (int i = 0; i < 8; i++) {
#pragma unroll
    for (int j = 0; j < 8; j++) {
      float v = acc[i][j];
      if (EPI == 1) v = (v > 0.f) ? v : expm1f(v);
      C[(size_t)(bm + tr + i) * Nc + bn + tc + j] = v;
    }
  }
}

// ============================================================
// NT GEMM with fused logits epilogue:
//   dot[i][j] = sum_k X[i][k]*X[j][k]
//   e = leaky_relu(s1[i] + s2[j], 0.1)
//   P[i][j] = (adj[i][j]*dot > 0) ? e : -9e15
// ============================================================
__global__ __launch_bounds__(256) void gemm_xxt_logits(
    const float* __restrict__ X, const float* __restrict__ adj,
    const float* __restrict__ s1, const float* __restrict__ s2,
    float* __restrict__ P) {
  __shared__ float As[16][132];
  __shared__ float Bs[16][132];

  const int bm = blockIdx.y * 128;
  const int bn = blockIdx.x * 128;
  const int tid = threadIdx.x;
  const int tr = (tid >> 4) * 8;
  const int tc = (tid & 15) * 8;
  const int aRow = tid >> 2;
  const int aCol = (tid & 3) * 4;

  float acc[8][8];
#pragma unroll
  for (int i = 0; i < 8; i++)
#pragma unroll
    for (int j = 0; j < 8; j++) acc[i][j] = 0.f;

  for (int k0 = 0; k0 < D_FEAT; k0 += 16) {
#pragma unroll
    for (int t = 0; t < 2; t++) {
      int r = aRow + t * 64;
      float4 va = *reinterpret_cast<const float4*>(
          &X[(size_t)(bm + r) * D_FEAT + k0 + aCol]);
      As[aCol + 0][r] = va.x;
      As[aCol + 1][r] = va.y;
      As[aCol + 2][r] = va.z;
      As[aCol + 3][r] = va.w;
      float4 vb = *reinterpret_cast<const float4*>(
          &X[(size_t)(bn + r) * D_FEAT + k0 + aCol]);
      Bs[aCol + 0][r] = vb.x;
      Bs[aCol + 1][r] = vb.y;
      Bs[aCol + 2][r] = vb.z;
      Bs[aCol + 3][r] = vb.w;
    }
    __syncthreads();

#pragma unroll
    for (int k = 0; k < 16; k++) {
      float ar[8], br[8];
#pragma unroll
      for (int i = 0; i < 8; i++) ar[i] = As[k][tr + i];
#pragma unroll
      for (int j = 0; j < 8; j++) br[j] = Bs[k][tc + j];
#pragma unroll
      for (int i = 0; i < 8; i++)
#pragma unroll
        for (int j = 0; j < 8; j++) acc[i][j] = fmaf(ar[i], br[j], acc[i][j]);
    }
    __syncthreads();
  }

  float s1v[8], s2v[8];
#pragma unroll
  for (int i = 0; i < 8; i++) s1v[i] = s1[bm + tr + i];
#pragma unroll
  for (int j = 0; j < 8; j++) s2v[j] = s2[bn + tc + j];

#pragma unroll
  for (int i = 0; i < 8; i++) {
    const size_t rowoff = (size_t)(bm + tr + i) * N_NODES + bn + tc;
#pragma unroll
    for (int j = 0; j < 8; j++) {
      float av = adj[rowoff + j];
      float e = s1v[i] + s2v[j];
      e = (e > 0.f) ? e : 0.1f * e;
      P[rowoff + j] = (av * acc[i][j] > 0.f) ? e : -9.0e15f;
    }
  }
}

// ============================================================
// s1[i] = h[i,:]@a1 ; s2[i] = h[i,:]@a2   (one block per row)
// ============================================================
__global__ __launch_bounds__(256) void compute_s12(
    const float* __restrict__ h, const float* __restrict__ a,
    float* __restrict__ s1, float* __restrict__ s2) {
  const int row = blockIdx.x;
  const float* hr = h + (size_t)row * D_FEAT;
  float p1 = 0.f, p2 = 0.f;
  for (int d = threadIdx.x; d < D_FEAT; d += 256) {
    float hv = hr[d];
    p1 = fmaf(hv, a[d], p1);
    p2 = fmaf(hv, a[D_FEAT + d], p2);
  }
#pragma unroll
  for (int off = 16; off; off >>= 1) {
    p1 += __shfl_down_sync(0xffffffffu, p1, off);
    p2 += __shfl_down_sync(0xffffffffu, p2, off);
  }
  __shared__ float r1[8], r2[8];
  const int warp = threadIdx.x >> 5, lane = threadIdx.x & 31;
  if (lane == 0) { r1[warp] = p1; r2[warp] = p2; }
  __syncthreads();
  if (threadIdx.x == 0) {
    float t1 = 0.f, t2 = 0.f;
#pragma unroll
    for (int w = 0; w < 8; w++) { t1 += r1[w]; t2 += r2[w]; }
    s1[row] = t1;
    s2[row] = t2;
  }
}

// ============================================================
// In-place row softmax over P (4096 per row, 256 thr, 16/thread)
// ============================================================
__global__ __launch_bounds__(256) void softmax_rows(float* __restrict__ P) {
  const int tid = threadIdx.x;
  float* pr = P + (size_t)blockIdx.x * N_NODES;
  __shared__ float red[256];

  float vals[16];
  float m = -INFINITY;
#pragma unroll
  for (int t = 0; t < 16; t++) {
    vals[t] = pr[tid + t * 256];
    m = fmaxf(m, vals[t]);
  }
  red[tid] = m;
  __syncthreads();
  for (int s = 128; s; s >>= 1) {
    if (tid < s) red[tid] = fmaxf(red[tid], red[tid + s]);
    __syncthreads();
  }
  m = red[0];
  __syncthreads();

  float sum = 0.f;
#pragma unroll
  for (int t = 0; t < 16; t++) {
    vals[t] = __expf(vals[t] - m);
    sum += vals[t];
  }
  red[tid] = sum;
  __syncthreads();
  for (int s = 128; s; s >>= 1) {
    if (tid < s) red[tid] += red[tid + s];
    __syncthreads();
  }
  const float inv = 1.f / red[0];
#pragma unroll
  for (int t = 0; t < 16; t++) pr[tid + t * 256] = vals[t] * inv;
}

// ============================================================
extern "C" void kernel_launch(void* const* d_in, const int* in_sizes, int n_in,
                              void* d_out, int out_size) {
  const float* x   = (const float*)d_in[0];  // (4096, 2048)
  const float* adj = (const float*)d_in[1];  // (4096, 4096)
  const float* W   = (const float*)d_in[2];  // (2048, 2048)
  const float* a   = (const float*)d_in[3];  // (4096, 1)
  float* out = (float*)d_out;                // (4096, 2048)

  float *h, *s1, *s2, *P;
  cudaGetSymbolAddress((void**)&h,  g_h);
  cudaGetSymbolAddress((void**)&s1, g_s1);
  cudaGetSymbolAddress((void**)&s2, g_s2);
  cudaGetSymbolAddress((void**)&P,  g_P);

  // 1) h = x @ W                       (4096 x 2048 x 2048)
  {
    dim3 grid(D_FEAT / 128, N_NODES / 128);
    gemm_nn<0><<<grid, 256>>>(x, W, h, N_NODES, D_FEAT, D_FEAT);
  }
  // 2) s1 = h@a1, s2 = h@a2
  compute_s12<<<N_NODES, 256>>>(h, a, s1, s2);
  // 3) logits: dot = x@x^T, mask by sign(adj*dot), leaky_relu(s1+s2)
  {
    dim3 grid(N_NODES / 128, N_NODES / 128);
    gemm_xxt_logits<<<grid, 256>>>(x, adj, s1, s2, P);
  }
  // 4) row softmax (in place)
  softmax_rows<<<N_NODES, 256>>>(P);
  // 5) out = elu(attention @ h)        (4096 x 2048 x 4096)
  {
    dim3 grid(D_FEAT / 128, N_NODES / 128);
    gemm_nn<1><<<grid, 256>>>(P, h, out, N_NODES, N_NODES, D_FEAT);
  }
}

// round 4
// speedup vs baseline: 2.4478x; 2.4478x over previous
#include <cuda_runtime.h>
#include <cuda_bf16.h>
#include <math.h>
#include <stdint.h>

#define NN 4096   // nodes
#define DD 2048   // features
#define DOT_THR 0.05f
#define MAX_FIX (1 << 22)

// ================= scratch (__device__ globals; no allocs allowed) ==========
__device__ __nv_bfloat16 g_xhi[(size_t)NN * DD];   // 16 MB
__device__ __nv_bfloat16 g_xlo[(size_t)NN * DD];   // 16 MB
__device__ __nv_bfloat16 g_wthi[(size_t)DD * DD];  // 8 MB   W^T split
__device__ __nv_bfloat16 g_wtlo[(size_t)DD * DD];  // 8 MB
__device__ __nv_bfloat16 g_hthi[(size_t)DD * NN];  // 16 MB  h^T split
__device__ __nv_bfloat16 g_htlo[(size_t)DD * NN];  // 16 MB
__device__ float         g_P[(size_t)NN * NN];     // 64 MB  logits
__device__ __nv_bfloat16 g_phi[(size_t)NN * NN];   // 32 MB  attention split
__device__ __nv_bfloat16 g_plo[(size_t)NN * NN];   // 32 MB
__device__ float g_s1[NN], g_s2[NN];
__device__ int g_cnt;                               // fixup worklist
__device__ int g_list[MAX_FIX];                     // 16 MB

// ================= PTX helpers ==============================================
__device__ __forceinline__ uint32_t smem_u32(const void* p) {
  uint32_t a;
  asm("{ .reg .u64 t; cvta.to.shared.u64 t, %1; cvt.u32.u64 %0, t; }"
      : "=r"(a) : "l"(p));
  return a;
}
__device__ __forceinline__ void cp16(uint32_t dst, const void* src) {
  asm volatile("cp.async.cg.shared.global [%0], [%1], 16;" :: "r"(dst), "l"(src));
}
#define CP_COMMIT() asm volatile("cp.async.commit_group;" ::: "memory")
#define CP_WAIT1()  asm volatile("cp.async.wait_group 1;" ::: "memory")
#define CP_WAIT0()  asm volatile("cp.async.wait_group 0;" ::: "memory")

__device__ __forceinline__ void ldm4(uint32_t* r, uint32_t addr) {
  asm volatile("ldmatrix.sync.aligned.m8n8.x4.shared.b16 {%0,%1,%2,%3}, [%4];"
               : "=r"(r[0]), "=r"(r[1]), "=r"(r[2]), "=r"(r[3]) : "r"(addr));
}
__device__ __forceinline__ void mma_bf16(float* d, const uint32_t* a,
                                         const uint32_t* b) {
  asm volatile(
      "mma.sync.aligned.m16n8k16.row.col.f32.bf16.bf16.f32 "
      "{%0,%1,%2,%3}, {%4,%5,%6,%7}, {%8,%9}, {%0,%1,%2,%3};"
      : "+f"(d[0]), "+f"(d[1]), "+f"(d[2]), "+f"(d[3])
      : "r"(a[0]), "r"(a[1]), "r"(a[2]), "r"(a[3]), "r"(b[0]), "r"(b[1]));
}

// ================= tiled HMMA GEMM ==========================================
// D[m][n] = sum_k A[m][k]*B[n][k]  (both K-major, split hi/lo, 3-pass)
// 128x128 block tile, BK=32, 2-stage cp.async, 8 warps (2x4), warp 64x32.
// EPI 0: write h^T split bf16 (transposed, coalesced over m)
// EPI 1: logits -> P fp32 (adj-sign mask + leaky_relu(s1+s2)) + fixup worklist
// EPI 2: elu -> out fp32
struct EpiArgs {
  const float* adj; const float* s1; const float* s2;
  float* fout; __nv_bfloat16* ohi; __nv_bfloat16* olo; int ldC;
};

#define RSTRIDE 80                    // 40 bf16 per row: conflict-free ldmatrix
#define TILE_B  (128 * RSTRIDE)       // 10240 B per operand tile
#define STAGE_B (4 * TILE_B)          // Ahi,Alo,Bhi,Blo
#define SMEM_BYTES (2 * STAGE_B)      // 81920 (epilogue stage reuses: 66048)

template <int EPI>
__global__ __launch_bounds__(256, 2)
void gemm_tc(const __nv_bfloat16* __restrict__ Ahi, const __nv_bfloat16* __restrict__ Alo,
             const __nv_bfloat16* __restrict__ Bhi, const __nv_bfloat16* __restrict__ Blo,
             int K, int ldA, int ldB, EpiArgs ep) {
  extern __shared__ __align__(16) char smraw[];
  const uint32_t smBase = smem_u32(smraw);

  const int tid = threadIdx.x, wid = tid >> 5, lane = tid & 31;
  const int wm = wid >> 2;        // 0..1  -> 64-row slab
  const int wn = wid & 3;         // 0..3  -> 32-col slab
  const int bm = blockIdx.y * 128, bn = blockIdx.x * 128;

  float acc[4][4][4];
#pragma unroll
  for (int i = 0; i < 4; i++)
#pragma unroll
    for (int j = 0; j < 4; j++)
#pragma unroll
      for (int v = 0; v < 4; v++) acc[i][j][v] = 0.f;

  // ---- async chunk loader: 4x (128 rows x 64B) ----
  auto load_chunk = [&](int k0, int s) {
    const uint32_t stg = smBase + (uint32_t)s * STAGE_B;
#pragma unroll
    for (int it = 0; it < 2; it++) {
      int c = tid + it * 256;            // 0..511
      int row = c >> 2, chk = c & 3;     // 4 x 16B per 64B row
      uint32_t so = row * RSTRIDE + chk * 16;
      cp16(stg + so,
           (const char*)(Ahi + (size_t)(bm + row) * ldA + k0) + chk * 16);
      cp16(stg + TILE_B + so,
           (const char*)(Alo + (size_t)(bm + row) * ldA + k0) + chk * 16);
      cp16(stg + 2 * TILE_B + so,
           (const char*)(Bhi + (size_t)(bn + row) * ldB + k0) + chk * 16);
      cp16(stg + 3 * TILE_B + so,
           (const char*)(Blo + (size_t)(bn + row) * ldB + k0) + chk * 16);
    }
    CP_COMMIT();
  };

  const int nch = K / 32;
  load_chunk(0, 0);
  load_chunk(32, 1);

  // per-lane fragment address offsets (within a tile)
  const uint32_t aoff =
      (uint32_t)((wm * 64 + (lane & 15)) * RSTRIDE + (lane >> 4) * 16);
  const uint32_t boff =
      (uint32_t)((wn * 32 + (lane >> 4) * 8 + (lane & 7)) * RSTRIDE +
                 ((lane >> 3) & 1) * 16);

  for (int i = 0; i < nch; i++) {
    if (i + 1 < nch) CP_WAIT1(); else CP_WAIT0();
    __syncthreads();

    const uint32_t stg = smBase + (uint32_t)(i & 1) * STAGE_B;
#pragma unroll
    for (int ks = 0; ks < 2; ks++) {
      const uint32_t kso = (uint32_t)(ks * 32);
      uint32_t ah[4][4], bh[2][4];
#pragma unroll
      for (int mi = 0; mi < 4; mi++)
        ldm4(ah[mi], stg + aoff + kso + mi * 16 * RSTRIDE);
#pragma unroll
      for (int nb = 0; nb < 2; nb++)
        ldm4(bh[nb], stg + 2 * TILE_B + boff + kso + nb * 16 * RSTRIDE);
      // pass 1: hi*hi
#pragma unroll
      for (int mi = 0; mi < 4; mi++)
#pragma unroll
        for (int ni = 0; ni < 4; ni++)
          mma_bf16(acc[mi][ni], ah[mi], &bh[ni >> 1][(ni & 1) * 2]);
      // pass 2: hi*lo
      {
        uint32_t bl[2][4];
#pragma unroll
        for (int nb = 0; nb < 2; nb++)
          ldm4(bl[nb], stg + 3 * TILE_B + boff + kso + nb * 16 * RSTRIDE);
#pragma unroll
        for (int mi = 0; mi < 4; mi++)
#pragma unroll
          for (int ni = 0; ni < 4; ni++)
            mma_bf16(acc[mi][ni], ah[mi], &bl[ni >> 1][(ni & 1) * 2]);
      }
      // pass 3: lo*hi
      {
        uint32_t al[4][4];
#pragma unroll
        for (int mi = 0; mi < 4; mi++)
          ldm4(al[mi], stg + TILE_B + aoff + kso + mi * 16 * RSTRIDE);
#pragma unroll
        for (int mi = 0; mi < 4; mi++)
#pragma unroll
          for (int ni = 0; ni < 4; ni++)
            mma_bf16(acc[mi][ni], al[mi], &bh[ni >> 1][(ni & 1) * 2]);
      }
    }
    __syncthreads();
    if (i + 2 < nch) load_chunk((i + 2) * 32, i & 1);
  }

  // ---- epilogue: stage fp32 tile to smem (padded 129), then coalesced ----
  float* st = (float*)smraw;
  {
    const int r0 = wm * 64 + (lane >> 2);
    const int c0 = wn * 32 + (lane & 3) * 2;
#pragma unroll
    for (int mi = 0; mi < 4; mi++)
#pragma unroll
      for (int ni = 0; ni < 4; ni++) {
        int r = r0 + mi * 16, c = c0 + ni * 8;
        st[r * 129 + c]           = acc[mi][ni][0];
        st[r * 129 + c + 1]       = acc[mi][ni][1];
        st[(r + 8) * 129 + c]     = acc[mi][ni][2];
        st[(r + 8) * 129 + c + 1] = acc[mi][ni][3];
      }
  }
  __syncthreads();

  if (EPI == 0) {
    // transposed split write: h_t[n][m], coalesced along m
#pragma unroll 4
    for (int s = 0; s < 64; s++) {
      int idx = s * 256 + tid;
      int n = idx >> 7, m = idx & 127;
      float v = st[m * 129 + n];
      __nv_bfloat16 h = __float2bfloat16(v);
      size_t off = (size_t)(bn + n) * ep.ldC + bm + m;
      ep.ohi[off] = h;
      ep.olo[off] = __float2bfloat16(v - __bfloat162float(h));
    }
  } else {
#pragma unroll 4
    for (int s = 0; s < 64; s++) {
      int idx = s * 256 + tid;
      int rr = idx >> 7, cc = idx & 127;
      float v = st[rr * 129 + cc];
      int gm = bm + rr, gn = bn + cc;
      if (EPI == 1) {
        float av = ep.adj[(size_t)gm * NN + gn];
        float e = ep.s1[gm] + ep.s2[gn];
        e = (e > 0.f) ? e : 0.1f * e;
        ep.fout[(size_t)gm * NN + gn] = (av * v > 0.f) ? e : -9.0e15f;
        // sign of dot uncertain near zero -> queue exact fp32 recompute
        if (fabsf(v) < DOT_THR) {
          int slot = atomicAdd(&g_cnt, 1);
          if (slot < MAX_FIX) g_list[slot] = (gm << 12) | gn;
        }
      } else {
        float o = (v > 0.f) ? v : expm1f(v);
        ep.fout[(size_t)gm * ep.ldC + gn] = o;
      }
    }
  }
}

// ================= fixup: exact fp32 dot for near-zero entries =============
__global__ __launch_bounds__(256) void fixup_kernel(
    const float* __restrict__ x, const float* __restrict__ adj,
    const float* __restrict__ s1, const float* __restrict__ s2,
    float* __restrict__ P) {
  const int n = min(g_cnt, MAX_FIX);
  const int warps = gridDim.x * (blockDim.x >> 5);
  const int w0 = blockIdx.x * (blockDim.x >> 5) + (threadIdx.x >> 5);
  const int lane = threadIdx.x & 31;
  for (int idx = w0; idx < n; idx += warps) {
    const int code = g_list[idx];
    const int i = code >> 12, j = code & 4095;
    const float* xi = x + (size_t)i * DD;
    const float* xj = x + (size_t)j * DD;
    float s = 0.f;
#pragma unroll 4
    for (int k = lane; k < DD; k += 32) s = fmaf(xi[k], xj[k], s);
#pragma unroll
    for (int off = 16; off; off >>= 1) s += __shfl_xor_sync(0xffffffffu, s, off);
    if (lane == 0) {
      float av = adj[(size_t)i * NN + j];
      float e = s1[i] + s2[j];
      e = (e > 0.f) ? e : 0.1f * e;
      P[(size_t)i * NN + j] = (av * s > 0.f) ? e : -9.0e15f;
    }
  }
}

// ================= support kernels ==========================================
__global__ __launch_bounds__(256) void split_x(const float* __restrict__ x,
    __nv_bfloat16* __restrict__ xhi, __nv_bfloat16* __restrict__ xlo,
    float* __restrict__ s1, float* __restrict__ s2) {
  size_t i = (size_t)blockIdx.x * 256 + threadIdx.x;
  float v = x[i];
  __nv_bfloat16 h = __float2bfloat16(v);
  xhi[i] = h;
  xlo[i] = __float2bfloat16(v - __bfloat162float(h));
  if (i < NN) { s1[i] = 0.f; s2[i] = 0.f; }
  if (i == 0) g_cnt = 0;
}

__global__ __launch_bounds__(256) void trans_split_w(const float* __restrict__ W,
    __nv_bfloat16* __restrict__ wthi, __nv_bfloat16* __restrict__ wtlo) {
  __shared__ float t[32][33];
  const int bx = blockIdx.x * 32, by = blockIdx.y * 32;  // bx: n, by: k
  const int tx = threadIdx.x, ty = threadIdx.y;          // block (32,8)
#pragma unroll
  for (int rep = 0; rep < 4; rep++)
    t[ty + rep * 8][tx] = W[(size_t)(by + ty + rep * 8) * DD + bx + tx];
  __syncthreads();
#pragma unroll
  for (int rep = 0; rep < 4; rep++) {
    float v = t[tx][ty + rep * 8];
    __nv_bfloat16 h = __float2bfloat16(v);
    size_t off = (size_t)(bx + ty + rep * 8) * DD + by + tx;
    wthi[off] = h;
    wtlo[off] = __float2bfloat16(v - __bfloat162float(h));
  }
}

__global__ __launch_bounds__(128) void s12_kernel(
    const __nv_bfloat16* __restrict__ hthi, const __nv_bfloat16* __restrict__ htlo,
    const float* __restrict__ a, float* __restrict__ s1, float* __restrict__ s2) {
  const int m = blockIdx.x * 128 + threadIdx.x;
  const int k0 = blockIdx.y * 256;
  float p1 = 0.f, p2 = 0.f;
#pragma unroll 4
  for (int k = k0; k < k0 + 256; k++) {
    float hv = __bfloat162float(hthi[(size_t)k * NN + m]) +
               __bfloat162float(htlo[(size_t)k * NN + m]);
    p1 = fmaf(hv, a[k], p1);
    p2 = fmaf(hv, a[DD + k], p2);
  }
  atomicAdd(&s1[m], p1);
  atomicAdd(&s2[m], p2);
}

__global__ __launch_bounds__(256) void softmax_rows(const float* __restrict__ P,
    __nv_bfloat16* __restrict__ phi, __nv_bfloat16* __restrict__ plo) {
  const int tid = threadIdx.x;
  const size_t rowbase = (size_t)blockIdx.x * NN;
  const float* pr = P + rowbase;
  __shared__ float red[256];

  float vals[16];
  float m = -INFINITY;
#pragma unroll
  for (int t = 0; t < 16; t++) {
    vals[t] = pr[tid + t * 256];
    m = fmaxf(m, vals[t]);
  }
  red[tid] = m;
  __syncthreads();
  for (int s = 128; s; s >>= 1) {
    if (tid < s) red[tid] = fmaxf(red[tid], red[tid + s]);
    __syncthreads();
  }
  m = red[0];
  __syncthreads();
  float sum = 0.f;
#pragma unroll
  for (int t = 0; t < 16; t++) {
    vals[t] = __expf(vals[t] - m);
    sum += vals[t];
  }
  red[tid] = sum;
  __syncthreads();
  for (int s = 128; s; s >>= 1) {
    if (tid < s) red[tid] += red[tid + s];
    __syncthreads();
  }
  const float inv = 1.f / red[0];
#pragma unroll
  for (int t = 0; t < 16; t++) {
    float att = vals[t] * inv;
    __nv_bfloat16 h = __float2bfloat16(att);
    size_t off = rowbase + tid + t * 256;
    phi[off] = h;
    plo[off] = __float2bfloat16(att - __bfloat162float(h));
  }
}

// ================= launch ====================================================
extern "C" void kernel_launch(void* const* d_in, const int* in_sizes, int n_in,
                              void* d_out, int out_size) {
  const float* x   = (const float*)d_in[0];  // (4096, 2048)
  const float* adj = (const float*)d_in[1];  // (4096, 4096)
  const float* W   = (const float*)d_in[2];  // (2048, 2048)
  const float* a   = (const float*)d_in[3];  // (4096, 1)
  float* out = (float*)d_out;                // (4096, 2048)

  __nv_bfloat16 *xhi, *xlo, *wthi, *wtlo, *hthi, *htlo, *phi, *plo;
  float *P, *s1, *s2;
  cudaGetSymbolAddress((void**)&xhi,  g_xhi);
  cudaGetSymbolAddress((void**)&xlo,  g_xlo);
  cudaGetSymbolAddress((void**)&wthi, g_wthi);
  cudaGetSymbolAddress((void**)&wtlo, g_wtlo);
  cudaGetSymbolAddress((void**)&hthi, g_hthi);
  cudaGetSymbolAddress((void**)&htlo, g_htlo);
  cudaGetSymbolAddress((void**)&P,    g_P);
  cudaGetSymbolAddress((void**)&phi,  g_phi);
  cudaGetSymbolAddress((void**)&plo,  g_plo);
  cudaGetSymbolAddress((void**)&s1,   g_s1);
  cudaGetSymbolAddress((void**)&s2,   g_s2);

  cudaFuncSetAttribute(gemm_tc<0>, cudaFuncAttributeMaxDynamicSharedMemorySize, SMEM_BYTES);
  cudaFuncSetAttribute(gemm_tc<1>, cudaFuncAttributeMaxDynamicSharedMemorySize, SMEM_BYTES);
  cudaFuncSetAttribute(gemm_tc<2>, cudaFuncAttributeMaxDynamicSharedMemorySize, SMEM_BYTES);

  // 1) split x -> bf16 hi/lo; zero s1/s2; reset fixup counter
  split_x<<<(NN * DD) / 256, 256>>>(x, xhi, xlo, s1, s2);
  // 2) W -> W^T split
  trans_split_w<<<dim3(DD / 32, DD / 32), dim3(32, 8)>>>(W, wthi, wtlo);
  // 3) h = x @ W  (epilogue: h^T split bf16)
  {
    EpiArgs ep{}; ep.ohi = hthi; ep.olo = htlo; ep.ldC = NN;
    gemm_tc<0><<<dim3(DD / 128, NN / 128), 256, SMEM_BYTES>>>(
        xhi, xlo, wthi, wtlo, DD, DD, DD, ep);
  }
  // 4) s1 = h@a1, s2 = h@a2 (from h^T, k-split + atomics)
  s12_kernel<<<dim3(NN / 128, DD / 256), 128>>>(hthi, htlo, a, s1, s2);
  // 5) logits: dot = x@x^T, fused mask/leaky-relu -> P fp32 (+worklist)
  {
    EpiArgs ep{}; ep.adj = adj; ep.s1 = s1; ep.s2 = s2; ep.fout = P; ep.ldC = NN;
    gemm_tc<1><<<dim3(NN / 128, NN / 128), 256, SMEM_BYTES>>>(
        xhi, xlo, xhi, xlo, DD, DD, DD, ep);
  }
  // 5b) exact fp32 recompute of near-zero dots
  fixup_kernel<<<1024, 256>>>(x, adj, s1, s2, P);
  // 6) row softmax -> attention split bf16
  softmax_rows<<<NN, 256>>>(P, phi, plo);
  // 7) out = elu(attention @ h)
  {
    EpiArgs ep{}; ep.fout = out; ep.ldC = DD;
    gemm_tc<2><<<dim3(DD / 128, NN / 128), 256, SMEM_BYTES>>>(
        phi, plo, hthi, htlo, NN, NN, NN, ep);
  }
}

// round 5
// speedup vs baseline: 2.8181x; 1.1513x over previous
#include <cuda_runtime.h>
#include <cuda_bf16.h>
#include <math.h>
#include <stdint.h>

#define NN 4096   // nodes
#define DD 2048   // features
#define DOT_THR 0.015f
#define MAX_FIX (1 << 22)

// ================= scratch (__device__ globals; no allocs allowed) ==========
__device__ __nv_bfloat16 g_xhi[(size_t)NN * DD];   // 16 MB
__device__ __nv_bfloat16 g_xlo[(size_t)NN * DD];   // 16 MB
__device__ __nv_bfloat16 g_wthi[(size_t)DD * DD];  // 8 MB   W^T split
__device__ __nv_bfloat16 g_wtlo[(size_t)DD * DD];  // 8 MB
__device__ __nv_bfloat16 g_hthi[(size_t)DD * NN];  // 16 MB  h^T split
__device__ __nv_bfloat16 g_htlo[(size_t)DD * NN];  // 16 MB
__device__ float         g_P[(size_t)NN * NN];     // 64 MB  logits
__device__ __nv_bfloat16 g_phi[(size_t)NN * NN];   // 32 MB  attention split
__device__ __nv_bfloat16 g_plo[(size_t)NN * NN];   // 32 MB
__device__ float g_s1[NN], g_s2[NN];
__device__ float g_wa1[DD], g_wa2[DD];
__device__ int g_cnt;                               // fixup worklist
__device__ int g_list[MAX_FIX];                     // 16 MB

// ================= PTX helpers ==============================================
__device__ __forceinline__ uint32_t smem_u32(const void* p) {
  uint32_t a;
  asm("{ .reg .u64 t; cvta.to.shared.u64 t, %1; cvt.u32.u64 %0, t; }"
      : "=r"(a) : "l"(p));
  return a;
}
__device__ __forceinline__ void cp16(uint32_t dst, const void* src) {
  asm volatile("cp.async.cg.shared.global [%0], [%1], 16;" :: "r"(dst), "l"(src));
}
#define CP_COMMIT() asm volatile("cp.async.commit_group;" ::: "memory")
#define CP_WAIT1()  asm volatile("cp.async.wait_group 1;" ::: "memory")
#define CP_WAIT0()  asm volatile("cp.async.wait_group 0;" ::: "memory")

__device__ __forceinline__ void ldm4(uint32_t* r, uint32_t addr) {
  asm volatile("ldmatrix.sync.aligned.m8n8.x4.shared.b16 {%0,%1,%2,%3}, [%4];"
               : "=r"(r[0]), "=r"(r[1]), "=r"(r[2]), "=r"(r[3]) : "r"(addr));
}
__device__ __forceinline__ void mma_bf16(float* d, const uint32_t* a,
                                         const uint32_t* b) {
  asm volatile(
      "mma.sync.aligned.m16n8k16.row.col.f32.bf16.bf16.f32 "
      "{%0,%1,%2,%3}, {%4,%5,%6,%7}, {%8,%9}, {%0,%1,%2,%3};"
      : "+f"(d[0]), "+f"(d[1]), "+f"(d[2]), "+f"(d[3])
      : "r"(a[0]), "r"(a[1]), "r"(a[2]), "r"(a[3]), "r"(b[0]), "r"(b[1]));
}

// ================= tiled HMMA GEMM ==========================================
// D[m][n] = sum_k A[m][k]*B[n][k]  (both K-major, split hi/lo, 3-pass)
// 128x128 block tile, BK=32, 2-stage cp.async, 8 warps (2x4), warp 64x32.
// EPI 0: write h^T split bf16 (transposed, coalesced over m)
// EPI 1: symmetric x@x^T; triangular grid; writes P[i][j] AND P[j][i]
// EPI 2: elu -> out fp32
struct EpiArgs {
  const float* adj; const float* s1; const float* s2;
  float* fout; __nv_bfloat16* ohi; __nv_bfloat16* olo; int ldC;
};

#define RSTRIDE 80                    // 40 bf16 per row: conflict-free ldmatrix
#define TILE_B  (128 * RSTRIDE)       // 10240 B per operand tile
#define STAGE_B (4 * TILE_B)          // Ahi,Alo,Bhi,Blo
#define SMEM_BYTES (2 * STAGE_B)      // 81920 (epilogue stage reuses: 66048)

template <int EPI>
__global__ __launch_bounds__(256, 2)
void gemm_tc(const __nv_bfloat16* __restrict__ Ahi, const __nv_bfloat16* __restrict__ Alo,
             const __nv_bfloat16* __restrict__ Bhi, const __nv_bfloat16* __restrict__ Blo,
             int K, int ldA, int ldB, EpiArgs ep) {
  extern __shared__ __align__(16) char smraw[];
  const uint32_t smBase = smem_u32(smraw);

  const int tid = threadIdx.x, wid = tid >> 5, lane = tid & 31;
  const int wm = wid >> 2;        // 0..1  -> 64-row slab
  const int wn = wid & 3;         // 0..3  -> 32-col slab

  int bm, bn;
  if (EPI == 1) {
    // triangular tile decode: t -> (bi, bj), bi <= bj, 32x32 tile grid
    int rem = blockIdx.x, bi = 0;
    while (rem >= 32 - bi) { rem -= 32 - bi; bi++; }
    bm = bi * 128;
    bn = (bi + rem) * 128;
  } else {
    bm = blockIdx.y * 128;
    bn = blockIdx.x * 128;
  }

  float acc[4][4][4];
#pragma unroll
  for (int i = 0; i < 4; i++)
#pragma unroll
    for (int j = 0; j < 4; j++)
#pragma unroll
      for (int v = 0; v < 4; v++) acc[i][j][v] = 0.f;

  // ---- async chunk loader: 4x (128 rows x 64B) ----
  auto load_chunk = [&](int k0, int s) {
    const uint32_t stg = smBase + (uint32_t)s * STAGE_B;
#pragma unroll
    for (int it = 0; it < 2; it++) {
      int c = tid + it * 256;            // 0..511
      int row = c >> 2, chk = c & 3;     // 4 x 16B per 64B row
      uint32_t so = row * RSTRIDE + chk * 16;
      cp16(stg + so,
           (const char*)(Ahi + (size_t)(bm + row) * ldA + k0) + chk * 16);
      cp16(stg + TILE_B + so,
           (const char*)(Alo + (size_t)(bm + row) * ldA + k0) + chk * 16);
      cp16(stg + 2 * TILE_B + so,
           (const char*)(Bhi + (size_t)(bn + row) * ldB + k0) + chk * 16);
      cp16(stg + 3 * TILE_B + so,
           (const char*)(Blo + (size_t)(bn + row) * ldB + k0) + chk * 16);
    }
    CP_COMMIT();
  };

  const int nch = K / 32;
  load_chunk(0, 0);
  load_chunk(32, 1);

  // per-lane fragment address offsets (within a tile)
  const uint32_t aoff =
      (uint32_t)((wm * 64 + (lane & 15)) * RSTRIDE + (lane >> 4) * 16);
  const uint32_t boff =
      (uint32_t)((wn * 32 + (lane >> 4) * 8 + (lane & 7)) * RSTRIDE +
                 ((lane >> 3) & 1) * 16);

  for (int i = 0; i < nch; i++) {
    if (i + 1 < nch) CP_WAIT1(); else CP_WAIT0();
    __syncthreads();

    const uint32_t stg = smBase + (uint32_t)(i & 1) * STAGE_B;
#pragma unroll
    for (int ks = 0; ks < 2; ks++) {
      const uint32_t kso = (uint32_t)(ks * 32);
      uint32_t ah[4][4], bh[2][4];
#pragma unroll
      for (int mi = 0; mi < 4; mi++)
        ldm4(ah[mi], stg + aoff + kso + mi * 16 * RSTRIDE);
#pragma unroll
      for (int nb = 0; nb < 2; nb++)
        ldm4(bh[nb], stg + 2 * TILE_B + boff + kso + nb * 16 * RSTRIDE);
      // pass 1: hi*hi
#pragma unroll
      for (int mi = 0; mi < 4; mi++)
#pragma unroll
        for (int ni = 0; ni < 4; ni++)
          mma_bf16(acc[mi][ni], ah[mi], &bh[ni >> 1][(ni & 1) * 2]);
      // pass 2: hi*lo
      {
        uint32_t bl[2][4];
#pragma unroll
        for (int nb = 0; nb < 2; nb++)
          ldm4(bl[nb], stg + 3 * TILE_B + boff + kso + nb * 16 * RSTRIDE);
#pragma unroll
        for (int mi = 0; mi < 4; mi++)
#pragma unroll
          for (int ni = 0; ni < 4; ni++)
            mma_bf16(acc[mi][ni], ah[mi], &bl[ni >> 1][(ni & 1) * 2]);
      }
      // pass 3: lo*hi
      {
        uint32_t al[4][4];
#pragma unroll
        for (int mi = 0; mi < 4; mi++)
          ldm4(al[mi], stg + TILE_B + aoff + kso + mi * 16 * RSTRIDE);
#pragma unroll
        for (int mi = 0; mi < 4; mi++)
#pragma unroll
          for (int ni = 0; ni < 4; ni++)
            mma_bf16(acc[mi][ni], al[mi], &bh[ni >> 1][(ni & 1) * 2]);
      }
    }
    __syncthreads();
    if (i + 2 < nch) load_chunk((i + 2) * 32, i & 1);
  }

  // ---- epilogue: stage fp32 tile to smem (padded 129), then coalesced ----
  float* st = (float*)smraw;
  {
    const int r0 = wm * 64 + (lane >> 2);
    const int c0 = wn * 32 + (lane & 3) * 2;
#pragma unroll
    for (int mi = 0; mi < 4; mi++)
#pragma unroll
      for (int ni = 0; ni < 4; ni++) {
        int r = r0 + mi * 16, c = c0 + ni * 8;
        st[r * 129 + c]           = acc[mi][ni][0];
        st[r * 129 + c + 1]       = acc[mi][ni][1];
        st[(r + 8) * 129 + c]     = acc[mi][ni][2];
        st[(r + 8) * 129 + c + 1] = acc[mi][ni][3];
      }
  }
  __syncthreads();

  if (EPI == 0) {
    // transposed split write: h_t[n][m], coalesced along m
#pragma unroll 4
    for (int s = 0; s < 64; s++) {
      int idx = s * 256 + tid;
      int n = idx >> 7, m = idx & 127;
      float v = st[m * 129 + n];
      __nv_bfloat16 h = __float2bfloat16(v);
      size_t off = (size_t)(bn + n) * ep.ldC + bm + m;
      ep.ohi[off] = h;
      ep.olo[off] = __float2bfloat16(v - __bfloat162float(h));
    }
  } else if (EPI == 1) {
    // upper tile write
#pragma unroll 4
    for (int s = 0; s < 64; s++) {
      int idx = s * 256 + tid;
      int rr = idx >> 7, cc = idx & 127;
      float v = st[rr * 129 + cc];
      int gm = bm + rr, gn = bn + cc;
      float av = ep.adj[(size_t)gm * NN + gn];
      float e = ep.s1[gm] + ep.s2[gn];
      e = (e > 0.f) ? e : 0.1f * e;
      ep.fout[(size_t)gm * NN + gn] = (av * v > 0.f) ? e : -9.0e15f;
      if (fabsf(v) < DOT_THR) {
        int slot = atomicAdd(&g_cnt, 1);
        if (slot < MAX_FIX) g_list[slot] = (gm << 12) | gn;
      }
    }
    // mirrored tile write (off-diagonal blocks only): dot is symmetric
    if (bm != bn) {
#pragma unroll 4
      for (int s = 0; s < 64; s++) {
        int idx = s * 256 + tid;
        int rr = idx >> 7, cc = idx & 127;
        float v = st[cc * 129 + rr];   // transposed read; stride 129 -> no conflicts
        int gm = bn + rr, gn = bm + cc;
        float av = ep.adj[(size_t)gm * NN + gn];
        float e = ep.s1[gm] + ep.s2[gn];
        e = (e > 0.f) ? e : 0.1f * e;
        ep.fout[(size_t)gm * NN + gn] = (av * v > 0.f) ? e : -9.0e15f;
        if (fabsf(v) < DOT_THR) {
          int slot = atomicAdd(&g_cnt, 1);
          if (slot < MAX_FIX) g_list[slot] = (gm << 12) | gn;
        }
      }
    }
  } else {
#pragma unroll 4
    for (int s = 0; s < 64; s++) {
      int idx = s * 256 + tid;
      int rr = idx >> 7, cc = idx & 127;
      float v = st[rr * 129 + cc];
      int gm = bm + rr, gn = bn + cc;
      float o = (v > 0.f) ? v : expm1f(v);
      ep.fout[(size_t)gm * ep.ldC + gn] = o;
    }
  }
}

// ================= fixup: exact fp32 dot for near-zero entries =============
__global__ __launch_bounds__(256) void fixup_kernel(
    const float* __restrict__ x, const float* __restrict__ adj,
    const float* __restrict__ s1, const float* __restrict__ s2,
    float* __restrict__ P) {
  const int n = min(g_cnt, MAX_FIX);
  const int warps = gridDim.x * (blockDim.x >> 5);
  const int w0 = blockIdx.x * (blockDim.x >> 5) + (threadIdx.x >> 5);
  const int lane = threadIdx.x & 31;
  for (int idx = w0; idx < n; idx += warps) {
    const int code = g_list[idx];
    const int i = code >> 12, j = code & 4095;
    const float4* xi = (const float4*)(x + (size_t)i * DD);
    const float4* xj = (const float4*)(x + (size_t)j * DD);
    float s = 0.f;
#pragma unroll 4
    for (int k = lane; k < DD / 4; k += 32) {
      float4 a = xi[k], b = xj[k];
      s = fmaf(a.x, b.x, s);
      s = fmaf(a.y, b.y, s);
      s = fmaf(a.z, b.z, s);
      s = fmaf(a.w, b.w, s);
    }
#pragma unroll
    for (int off = 16; off; off >>= 1) s += __shfl_xor_sync(0xffffffffu, s, off);
    if (lane == 0) {
      float av = adj[(size_t)i * NN + j];
      float e = s1[i] + s2[j];
      e = (e > 0.f) ? e : 0.1f * e;
      P[(size_t)i * NN + j] = (av * s > 0.f) ? e : -9.0e15f;
    }
  }
}

// ================= support kernels ==========================================
__global__ __launch_bounds__(256) void split_x(const float* __restrict__ x,
    __nv_bfloat16* __restrict__ xhi, __nv_bfloat16* __restrict__ xlo) {
  size_t i = (size_t)blockIdx.x * 256 + threadIdx.x;
  float v = x[i];
  __nv_bfloat16 h = __float2bfloat16(v);
  xhi[i] = h;
  xlo[i] = __float2bfloat16(v - __bfloat162float(h));
  if (i == 0) g_cnt = 0;
}

__global__ __launch_bounds__(256) void trans_split_w(const float* __restrict__ W,
    __nv_bfloat16* __restrict__ wthi, __nv_bfloat16* __restrict__ wtlo) {
  __shared__ float t[32][33];
  const int bx = blockIdx.x * 32, by = blockIdx.y * 32;  // bx: n, by: k
  const int tx = threadIdx.x, ty = threadIdx.y;          // block (32,8)
#pragma unroll
  for (int rep = 0; rep < 4; rep++)
    t[ty + rep * 8][tx] = W[(size_t)(by + ty + rep * 8) * DD + bx + tx];
  __syncthreads();
#pragma unroll
  for (int rep = 0; rep < 4; rep++) {
    float v = t[tx][ty + rep * 8];
    __nv_bfloat16 h = __float2bfloat16(v);
    size_t off = (size_t)(bx + ty + rep * 8) * DD + by + tx;
    wthi[off] = h;
    wtlo[off] = __float2bfloat16(v - __bfloat162float(h));
  }
}

// rows x D fp32 GEMV, 2 RHS: o1 = M@v1, o2 = M@v2 (one warp per row)
__global__ __launch_bounds__(256) void gemv2(const float* __restrict__ M,
    const float* __restrict__ v1, const float* __restrict__ v2,
    float* __restrict__ o1, float* __restrict__ o2) {
  const int row = blockIdx.x * 8 + (threadIdx.x >> 5);
  const int lane = threadIdx.x & 31;
  const float4* mr = (const float4*)(M + (size_t)row * DD);
  const float4* a1 = (const float4*)v1;
  const float4* a2 = (const float4*)v2;
  float p1 = 0.f, p2 = 0.f;
#pragma unroll 4
  for (int k = lane; k < DD / 4; k += 32) {
    float4 m = mr[k], b1 = a1[k], b2 = a2[k];
    p1 = fmaf(m.x, b1.x, p1); p1 = fmaf(m.y, b1.y, p1);
    p1 = fmaf(m.z, b1.z, p1); p1 = fmaf(m.w, b1.w, p1);
    p2 = fmaf(m.x, b2.x, p2); p2 = fmaf(m.y, b2.y, p2);
    p2 = fmaf(m.z, b2.z, p2); p2 = fmaf(m.w, b2.w, p2);
  }
#pragma unroll
  for (int off = 16; off; off >>= 1) {
    p1 += __shfl_xor_sync(0xffffffffu, p1, off);
    p2 += __shfl_xor_sync(0xffffffffu, p2, off);
  }
  if (lane == 0) { o1[row] = p1; o2[row] = p2; }
}

__global__ __launch_bounds__(256) void softmax_rows(const float* __restrict__ P,
    __nv_bfloat16* __restrict__ phi, __nv_bfloat16* __restrict__ plo) {
  const int tid = threadIdx.x;
  const size_t rowbase = (size_t)blockIdx.x * NN;
  const float* pr = P + rowbase;
  __shared__ float red[256];

  float vals[16];
  float m = -INFINITY;
#pragma unroll
  for (int t = 0; t < 16; t++) {
    vals[t] = pr[tid + t * 256];
    m = fmaxf(m, vals[t]);
  }
  red[tid] = m;
  __syncthreads();
  for (int s = 128; s; s >>= 1) {
    if (tid < s) red[tid] = fmaxf(red[tid], red[tid + s]);
    __syncthreads();
  }
  m = red[0];
  __syncthreads();
  float sum = 0.f;
#pragma unroll
  for (int t = 0; t < 16; t++) {
    vals[t] = __expf(vals[t] - m);
    sum += vals[t];
  }
  red[tid] = sum;
  __syncthreads();
  for (int s = 128; s; s >>= 1) {
    if (tid < s) red[tid] += red[tid + s];
    __syncthreads();
  }
  const float inv = 1.f / red[0];
#pragma unroll
  for (int t = 0; t < 16; t++) {
    float att = vals[t] * inv;
    __nv_bfloat16 h = __float2bfloat16(att);
    size_t off = rowbase + tid + t * 256;
    phi[off] = h;
    plo[off] = __float2bfloat16(att - __bfloat162float(h));
  }
}

// ================= launch ====================================================
extern "C" void kernel_launch(void* const* d_in, const int* in_sizes, int n_in,
                              void* d_out, int out_size) {
  const float* x   = (const float*)d_in[0];  // (4096, 2048)
  const float* adj = (const float*)d_in[1];  // (4096, 4096)
  const float* W   = (const float*)d_in[2];  // (2048, 2048)
  const float* a   = (const float*)d_in[3];  // (4096, 1)
  float* out = (float*)d_out;                // (4096, 2048)

  __nv_bfloat16 *xhi, *xlo, *wthi, *wtlo, *hthi, *htlo, *phi, *plo;
  float *P, *s1, *s2, *wa1, *wa2;
  cudaGetSymbolAddress((void**)&xhi,  g_xhi);
  cudaGetSymbolAddress((void**)&xlo,  g_xlo);
  cudaGetSymbolAddress((void**)&wthi, g_wthi);
  cudaGetSymbolAddress((void**)&wtlo, g_wtlo);
  cudaGetSymbolAddress((void**)&hthi, g_hthi);
  cudaGetSymbolAddress((void**)&htlo, g_htlo);
  cudaGetSymbolAddress((void**)&P,    g_P);
  cudaGetSymbolAddress((void**)&phi,  g_phi);
  cudaGetSymbolAddress((void**)&plo,  g_plo);
  cudaGetSymbolAddress((void**)&s1,   g_s1);
  cudaGetSymbolAddress((void**)&s2,   g_s2);
  cudaGetSymbolAddress((void**)&wa1,  g_wa1);
  cudaGetSymbolAddress((void**)&wa2,  g_wa2);

  cudaFuncSetAttribute(gemm_tc<0>, cudaFuncAttributeMaxDynamicSharedMemorySize, SMEM_BYTES);
  cudaFuncSetAttribute(gemm_tc<1>, cudaFuncAttributeMaxDynamicSharedMemorySize, SMEM_BYTES);
  cudaFuncSetAttribute(gemm_tc<2>, cudaFuncAttributeMaxDynamicSharedMemorySize, SMEM_BYTES);

  // 1) split x -> bf16 hi/lo; reset fixup counter
  split_x<<<(NN * DD) / 256, 256>>>(x, xhi, xlo);
  // 2) W -> W^T split
  trans_split_w<<<dim3(DD / 32, DD / 32), dim3(32, 8)>>>(W, wthi, wtlo);
  // 3) wa1 = W@a1, wa2 = W@a2 (associativity: s = (xW)a = x(Wa))
  gemv2<<<DD / 8, 256>>>(W, a, a + DD, wa1, wa2);
  // 4) s1 = x@wa1, s2 = x@wa2
  gemv2<<<NN / 8, 256>>>(x, wa1, wa2, s1, s2);
  // 5) logits: dot = x@x^T (symmetric, triangular grid), fused mask -> P
  {
    EpiArgs ep{}; ep.adj = adj; ep.s1 = s1; ep.s2 = s2; ep.fout = P; ep.ldC = NN;
    gemm_tc<1><<<528, 256, SMEM_BYTES>>>(xhi, xlo, xhi, xlo, DD, DD, DD, ep);
  }
  // 5b) exact fp32 recompute of near-zero dots
  fixup_kernel<<<1024, 256>>>(x, adj, s1, s2, P);
  // 6) row softmax -> attention split bf16
  softmax_rows<<<NN, 256>>>(P, phi, plo);
  // 7) h = x @ W  (epilogue: h^T split bf16)
  {
    EpiArgs ep{}; ep.ohi = hthi; ep.olo = htlo; ep.ldC = NN;
    gemm_tc<0><<<dim3(DD / 128, NN / 128), 256, SMEM_BYTES>>>(
        xhi, xlo, wthi, wtlo, DD, DD, DD, ep);
  }
  // 8) out = elu(attention @ h)
  {
    EpiArgs ep{}; ep.fout = out; ep.ldC = DD;
    gemm_tc<2><<<dim3(DD / 128, NN / 128), 256, SMEM_BYTES>>>(
        phi, plo, hthi, htlo, NN, NN, NN, ep);
  }
}

// round 6
// speedup vs baseline: 3.0760x; 1.0915x over previous
#include <cuda_runtime.h>
#include <cuda_bf16.h>
#include <math.h>
#include <stdint.h>

#define NN 4096   // nodes
#define DD 2048   // features
#define DOT_THR 0.015f
#define MAX_FIX (1 << 22)

// ================= scratch (__device__ globals; no allocs allowed) ==========
__device__ __nv_bfloat16 g_xhi[(size_t)NN * DD];   // 16 MB
__device__ __nv_bfloat16 g_xlo[(size_t)NN * DD];   // 16 MB
__device__ __nv_bfloat16 g_wthi[(size_t)DD * DD];  // 8 MB   W^T split
__device__ __nv_bfloat16 g_wtlo[(size_t)DD * DD];  // 8 MB
__device__ __nv_bfloat16 g_hthi[(size_t)DD * NN];  // 16 MB  h^T split
__device__ __nv_bfloat16 g_htlo[(size_t)DD * NN];  // 16 MB
__device__ float         g_P[(size_t)NN * NN];     // 64 MB  logits
__device__ __nv_bfloat16 g_phi[(size_t)NN * NN];   // 32 MB  attention split
__device__ __nv_bfloat16 g_plo[(size_t)NN * NN];   // 32 MB
__device__ float g_s1[NN], g_s2[NN];
__device__ float g_wa1[DD], g_wa2[DD];
__device__ int g_cnt;                               // fixup worklist
__device__ int g_list[MAX_FIX];                     // 16 MB

// ================= PTX helpers ==============================================
__device__ __forceinline__ uint32_t smem_u32(const void* p) {
  uint32_t a;
  asm("{ .reg .u64 t; cvta.to.shared.u64 t, %1; cvt.u32.u64 %0, t; }"
      : "=r"(a) : "l"(p));
  return a;
}
__device__ __forceinline__ void cp16(uint32_t dst, const void* src) {
  asm volatile("cp.async.cg.shared.global [%0], [%1], 16;" :: "r"(dst), "l"(src));
}
#define CP_COMMIT() asm volatile("cp.async.commit_group;" ::: "memory")
#define CP_WAIT1()  asm volatile("cp.async.wait_group 1;" ::: "memory")
#define CP_WAIT0()  asm volatile("cp.async.wait_group 0;" ::: "memory")

__device__ __forceinline__ void ldm4(uint32_t* r, uint32_t addr) {
  asm volatile("ldmatrix.sync.aligned.m8n8.x4.shared.b16 {%0,%1,%2,%3}, [%4];"
               : "=r"(r[0]), "=r"(r[1]), "=r"(r[2]), "=r"(r[3]) : "r"(addr));
}
__device__ __forceinline__ void mma_bf16(float* d, const uint32_t* a,
                                         const uint32_t* b) {
  asm volatile(
      "mma.sync.aligned.m16n8k16.row.col.f32.bf16.bf16.f32 "
      "{%0,%1,%2,%3}, {%4,%5,%6,%7}, {%8,%9}, {%0,%1,%2,%3};"
      : "+f"(d[0]), "+f"(d[1]), "+f"(d[2]), "+f"(d[3])
      : "r"(a[0]), "r"(a[1]), "r"(a[2]), "r"(a[3]), "r"(b[0]), "r"(b[1]));
}

#define RSTRIDE 80                    // 40 bf16 per row: conflict-free ldmatrix
#define TILE_B  (128 * RSTRIDE)       // 10240 B per operand tile
#define STAGE_B (4 * TILE_B)          // Ahi,Alo,Bhi,Blo
#define SMEM_BYTES (2 * STAGE_B)      // 81920

// ---- shared mainloop: 3-pass split-bf16, prefetch-reordered ----------------
// acc[4][4][4]; returns after full K sweep. Ahi/Alo rows at bm, Bhi/Blo at bn.
#define GEMM_MAINLOOP(Ahi, Alo, Bhi, Blo, K, ldA, ldB, bm, bn)                  \
  {                                                                             \
    auto load_chunk = [&](int k0, int s) {                                      \
      const uint32_t stg = smBase + (uint32_t)s * STAGE_B;                      \
      _Pragma("unroll")                                                         \
      for (int it = 0; it < 2; it++) {                                          \
        int c = tid + it * 256;                                                 \
        int row = c >> 2, chk = c & 3;                                          \
        uint32_t so = row * RSTRIDE + chk * 16;                                 \
        cp16(stg + so,                                                          \
             (const char*)(Ahi + (size_t)(bm + row) * ldA + k0) + chk * 16);    \
        cp16(stg + TILE_B + so,                                                 \
             (const char*)(Alo + (size_t)(bm + row) * ldA + k0) + chk * 16);    \
        cp16(stg + 2 * TILE_B + so,                                             \
             (const char*)(Bhi + (size_t)(bn + row) * ldB + k0) + chk * 16);    \
        cp16(stg + 3 * TILE_B + so,                                             \
             (const char*)(Blo + (size_t)(bn + row) * ldB + k0) + chk * 16);    \
      }                                                                         \
      CP_COMMIT();                                                              \
    };                                                                          \
    const int nch = (K) / 32;                                                   \
    load_chunk(0, 0);                                                           \
    load_chunk(32, 1);                                                          \
    for (int i = 0; i < nch; i++) {                                             \
      if (i + 1 < nch) CP_WAIT1(); else CP_WAIT0();                             \
      __syncthreads();                                                          \
      const uint32_t stg = smBase + (uint32_t)(i & 1) * STAGE_B;                \
      _Pragma("unroll")                                                         \
      for (int ks = 0; ks < 2; ks++) {                                          \
        const uint32_t kso = (uint32_t)(ks * 32);                               \
        uint32_t ah[4][4], bh[2][4], bl[2][4], al[4][4];                        \
        _Pragma("unroll")                                                       \
        for (int mi = 0; mi < 4; mi++)                                          \
          ldm4(ah[mi], stg + aoff + kso + mi * 16 * RSTRIDE);                   \
        _Pragma("unroll")                                                       \
        for (int nb = 0; nb < 2; nb++)                                          \
          ldm4(bh[nb], stg + 2 * TILE_B + boff + kso + nb * 16 * RSTRIDE);      \
        _Pragma("unroll")                                                       \
        for (int nb = 0; nb < 2; nb++)  /* prefetch pass-2 B before pass-1 */   \
          ldm4(bl[nb], stg + 3 * TILE_B + boff + kso + nb * 16 * RSTRIDE);      \
        _Pragma("unroll")                                                       \
        for (int mi = 0; mi < 4; mi++)                                          \
          _Pragma("unroll")                                                     \
          for (int ni = 0; ni < 4; ni++)                                        \
            mma_bf16(acc[mi][ni], ah[mi], &bh[ni >> 1][(ni & 1) * 2]);          \
        _Pragma("unroll")                                                       \
        for (int mi = 0; mi < 4; mi++)  /* prefetch pass-3 A before pass-2 */   \
          ldm4(al[mi], stg + TILE_B + aoff + kso + mi * 16 * RSTRIDE);          \
        _Pragma("unroll")                                                       \
        for (int mi = 0; mi < 4; mi++)                                          \
          _Pragma("unroll")                                                     \
          for (int ni = 0; ni < 4; ni++)                                        \
            mma_bf16(acc[mi][ni], ah[mi], &bl[ni >> 1][(ni & 1) * 2]);          \
        _Pragma("unroll")                                                       \
        for (int mi = 0; mi < 4; mi++)                                          \
          _Pragma("unroll")                                                     \
          for (int ni = 0; ni < 4; ni++)                                        \
            mma_bf16(acc[mi][ni], al[mi], &bh[ni >> 1][(ni & 1) * 2]);          \
      }                                                                         \
      __syncthreads();                                                          \
      if (i + 2 < nch) load_chunk((i + 2) * 32, i & 1);                         \
    }                                                                           \
  }

#define ACC_TO_SMEM()                                                           \
  {                                                                             \
    const int r0 = wm * 64 + (lane >> 2);                                       \
    const int c0 = wn * 32 + (lane & 3) * 2;                                    \
    _Pragma("unroll")                                                           \
    for (int mi = 0; mi < 4; mi++)                                              \
      _Pragma("unroll")                                                         \
      for (int ni = 0; ni < 4; ni++) {                                          \
        int r = r0 + mi * 16, c = c0 + ni * 8;                                  \
        st[r * 129 + c]           = acc[mi][ni][0];                             \
        st[r * 129 + c + 1]       = acc[mi][ni][1];                             \
        st[(r + 8) * 129 + c]     = acc[mi][ni][2];                             \
        st[(r + 8) * 129 + c + 1] = acc[mi][ni][3];                             \
      }                                                                         \
  }

// ================= fused GEMM: logits (528 blocks) + h (512 blocks) =========
__global__ __launch_bounds__(256, 2)
void gemm_fused(const __nv_bfloat16* __restrict__ xhi, const __nv_bfloat16* __restrict__ xlo,
                const __nv_bfloat16* __restrict__ wthi, const __nv_bfloat16* __restrict__ wtlo,
                const float* __restrict__ adj, const float* __restrict__ s1,
                const float* __restrict__ s2, float* __restrict__ P,
                __nv_bfloat16* __restrict__ hthi, __nv_bfloat16* __restrict__ htlo) {
  extern __shared__ __align__(16) char smraw[];
  const uint32_t smBase = smem_u32(smraw);
  const int tid = threadIdx.x, wid = tid >> 5, lane = tid & 31;
  const int wm = wid >> 2, wn = wid & 3;

  const int bid = blockIdx.x;
  const bool logits = bid < 528;
  int bm, bn;
  const __nv_bfloat16 *Bh, *Bl;
  if (logits) {
    int rem = bid, bi = 0;
    while (rem >= 32 - bi) { rem -= 32 - bi; bi++; }
    bm = bi * 128; bn = (bi + rem) * 128;
    Bh = xhi; Bl = xlo;
  } else {
    int t = bid - 528;                     // 512 blocks: 32 m-tiles x 16 n-tiles
    int group = t >> 7;                    // 8-row supergroups (8*16=128)
    int rem = t & 127;
    bm = (group * 8 + (rem & 7)) * 128;
    bn = (rem >> 3) * 128;
    Bh = wthi; Bl = wtlo;
  }

  float acc[4][4][4];
#pragma unroll
  for (int i = 0; i < 4; i++)
#pragma unroll
    for (int j = 0; j < 4; j++)
#pragma unroll
      for (int v = 0; v < 4; v++) acc[i][j][v] = 0.f;

  const uint32_t aoff =
      (uint32_t)((wm * 64 + (lane & 15)) * RSTRIDE + (lane >> 4) * 16);
  const uint32_t boff =
      (uint32_t)((wn * 32 + (lane >> 4) * 8 + (lane & 7)) * RSTRIDE +
                 ((lane >> 3) & 1) * 16);

  GEMM_MAINLOOP(xhi, xlo, Bh, Bl, DD, DD, DD, bm, bn);

  float* st = (float*)smraw;
  ACC_TO_SMEM();
  __syncthreads();

  if (logits) {
#pragma unroll 4
    for (int s = 0; s < 64; s++) {
      int idx = s * 256 + tid;
      int rr = idx >> 7, cc = idx & 127;
      float v = st[rr * 129 + cc];
      int gm = bm + rr, gn = bn + cc;
      float av = adj[(size_t)gm * NN + gn];
      float e = s1[gm] + s2[gn];
      e = (e > 0.f) ? e : 0.1f * e;
      P[(size_t)gm * NN + gn] = (av * v > 0.f) ? e : -9.0e15f;
      if (fabsf(v) < DOT_THR) {
        int slot = atomicAdd(&g_cnt, 1);
        if (slot < MAX_FIX) g_list[slot] = (gm << 12) | gn;
      }
    }
    if (bm != bn) {
#pragma unroll 4
      for (int s = 0; s < 64; s++) {
        int idx = s * 256 + tid;
        int rr = idx >> 7, cc = idx & 127;
        float v = st[cc * 129 + rr];
        int gm = bn + rr, gn = bm + cc;
        float av = adj[(size_t)gm * NN + gn];
        float e = s1[gm] + s2[gn];
        e = (e > 0.f) ? e : 0.1f * e;
        P[(size_t)gm * NN + gn] = (av * v > 0.f) ? e : -9.0e15f;
        if (fabsf(v) < DOT_THR) {
          int slot = atomicAdd(&g_cnt, 1);
          if (slot < MAX_FIX) g_list[slot] = (gm << 12) | gn;
        }
      }
    }
  } else {
    // transposed split write: h_t[n][m], coalesced along m
#pragma unroll 4
    for (int s = 0; s < 64; s++) {
      int idx = s * 256 + tid;
      int n = idx >> 7, m = idx & 127;
      float v = st[m * 129 + n];
      __nv_bfloat16 h = __float2bfloat16(v);
      size_t off = (size_t)(bn + n) * NN + bm + m;
      hthi[off] = h;
      htlo[off] = __float2bfloat16(v - __bfloat162float(h));
    }
  }
}

// ================= out GEMM: out = elu(attention @ h) =======================
__global__ __launch_bounds__(256, 2)
void gemm_out(const __nv_bfloat16* __restrict__ phi, const __nv_bfloat16* __restrict__ plo,
              const __nv_bfloat16* __restrict__ hthi, const __nv_bfloat16* __restrict__ htlo,
              float* __restrict__ out) {
  extern __shared__ __align__(16) char smraw[];
  const uint32_t smBase = smem_u32(smraw);
  const int tid = threadIdx.x, wid = tid >> 5, lane = tid & 31;
  const int wm = wid >> 2, wn = wid & 3;

  // 8-row supergroup swizzle over 32 m-tiles x 16 n-tiles
  const int t = blockIdx.x;
  const int group = t >> 7;
  const int rem = t & 127;
  const int bm = (group * 8 + (rem & 7)) * 128;
  const int bn = (rem >> 3) * 128;

  float acc[4][4][4];
#pragma unroll
  for (int i = 0; i < 4; i++)
#pragma unroll
    for (int j = 0; j < 4; j++)
#pragma unroll
      for (int v = 0; v < 4; v++) acc[i][j][v] = 0.f;

  const uint32_t aoff =
      (uint32_t)((wm * 64 + (lane & 15)) * RSTRIDE + (lane >> 4) * 16);
  const uint32_t boff =
      (uint32_t)((wn * 32 + (lane >> 4) * 8 + (lane & 7)) * RSTRIDE +
                 ((lane >> 3) & 1) * 16);

  GEMM_MAINLOOP(phi, plo, hthi, htlo, NN, NN, NN, bm, bn);

  float* st = (float*)smraw;
  ACC_TO_SMEM();
  __syncthreads();

#pragma unroll 4
  for (int s = 0; s < 64; s++) {
    int idx = s * 256 + tid;
    int rr = idx >> 7, cc = idx & 127;
    float v = st[rr * 129 + cc];
    float o = (v > 0.f) ? v : expm1f(v);
    out[(size_t)(bm + rr) * DD + bn + cc] = o;
  }
}

// ================= fixup: exact fp32 dot for near-zero entries =============
__global__ __launch_bounds__(256) void fixup_kernel(
    const float* __restrict__ x, const float* __restrict__ adj,
    const float* __restrict__ s1, const float* __restrict__ s2,
    float* __restrict__ P) {
  const int n = min(g_cnt, MAX_FIX);
  const int warps = gridDim.x * (blockDim.x >> 5);
  const int w0 = blockIdx.x * (blockDim.x >> 5) + (threadIdx.x >> 5);
  const int lane = threadIdx.x & 31;
  for (int idx = w0; idx < n; idx += warps) {
    const int code = g_list[idx];
    const int i = code >> 12, j = code & 4095;
    const float4* xi = (const float4*)(x + (size_t)i * DD);
    const float4* xj = (const float4*)(x + (size_t)j * DD);
    float s = 0.f;
#pragma unroll 4
    for (int k = lane; k < DD / 4; k += 32) {
      float4 a = xi[k], b = xj[k];
      s = fmaf(a.x, b.x, s);
      s = fmaf(a.y, b.y, s);
      s = fmaf(a.z, b.z, s);
      s = fmaf(a.w, b.w, s);
    }
#pragma unroll
    for (int off = 16; off; off >>= 1) s += __shfl_xor_sync(0xffffffffu, s, off);
    if (lane == 0) {
      float av = adj[(size_t)i * NN + j];
      float e = s1[i] + s2[j];
      e = (e > 0.f) ? e : 0.1f * e;
      P[(size_t)i * NN + j] = (av * s > 0.f) ? e : -9.0e15f;
    }
  }
}

// ================= support kernels ==========================================
__global__ __launch_bounds__(256) void split_x(const float* __restrict__ x,
    __nv_bfloat16* __restrict__ xhi, __nv_bfloat16* __restrict__ xlo) {
  size_t i = (size_t)blockIdx.x * 256 + threadIdx.x;
  float v = x[i];
  __nv_bfloat16 h = __float2bfloat16(v);
  xhi[i] = h;
  xlo[i] = __float2bfloat16(v - __bfloat162float(h));
  if (i == 0) g_cnt = 0;
}

__global__ __launch_bounds__(256) void trans_split_w(const float* __restrict__ W,
    __nv_bfloat16* __restrict__ wthi, __nv_bfloat16* __restrict__ wtlo) {
  __shared__ float t[32][33];
  const int bx = blockIdx.x * 32, by = blockIdx.y * 32;  // bx: n, by: k
  const int tx = threadIdx.x, ty = threadIdx.y;          // block (32,8)
#pragma unroll
  for (int rep = 0; rep < 4; rep++)
    t[ty + rep * 8][tx] = W[(size_t)(by + ty + rep * 8) * DD + bx + tx];
  __syncthreads();
#pragma unroll
  for (int rep = 0; rep < 4; rep++) {
    float v = t[tx][ty + rep * 8];
    __nv_bfloat16 h = __float2bfloat16(v);
    size_t off = (size_t)(bx + ty + rep * 8) * DD + by + tx;
    wthi[off] = h;
    wtlo[off] = __float2bfloat16(v - __bfloat162float(h));
  }
}

// rows x D fp32 GEMV, 2 RHS: o1 = M@v1, o2 = M@v2 (one warp per row)
__global__ __launch_bounds__(256) void gemv2(const float* __restrict__ M,
    const float* __restrict__ v1, const float* __restrict__ v2,
    float* __restrict__ o1, float* __restrict__ o2) {
  const int row = blockIdx.x * 8 + (threadIdx.x >> 5);
  const int lane = threadIdx.x & 31;
  const float4* mr = (const float4*)(M + (size_t)row * DD);
  const float4* a1 = (const float4*)v1;
  const float4* a2 = (const float4*)v2;
  float p1 = 0.f, p2 = 0.f;
#pragma unroll 4
  for (int k = lane; k < DD / 4; k += 32) {
    float4 m = mr[k], b1 = a1[k], b2 = a2[k];
    p1 = fmaf(m.x, b1.x, p1); p1 = fmaf(m.y, b1.y, p1);
    p1 = fmaf(m.z, b1.z, p1); p1 = fmaf(m.w, b1.w, p1);
    p2 = fmaf(m.x, b2.x, p2); p2 = fmaf(m.y, b2.y, p2);
    p2 = fmaf(m.z, b2.z, p2); p2 = fmaf(m.w, b2.w, p2);
  }
#pragma unroll
  for (int off = 16; off; off >>= 1) {
    p1 += __shfl_xor_sync(0xffffffffu, p1, off);
    p2 += __shfl_xor_sync(0xffffffffu, p2, off);
  }
  if (lane == 0) { o1[row] = p1; o2[row] = p2; }
}

__global__ __launch_bounds__(256) void softmax_rows(const float* __restrict__ P,
    __nv_bfloat16* __restrict__ phi, __nv_bfloat16* __restrict__ plo) {
  const int tid = threadIdx.x;
  const size_t rowbase = (size_t)blockIdx.x * NN;
  const float* pr = P + rowbase;
  __shared__ float red[256];

  float vals[16];
  float m = -INFINITY;
#pragma unroll
  for (int t = 0; t < 16; t++) {
    vals[t] = pr[tid + t * 256];
    m = fmaxf(m, vals[t]);
  }
  red[tid] = m;
  __syncthreads();
  for (int s = 128; s; s >>= 1) {
    if (tid < s) red[tid] = fmaxf(red[tid], red[tid + s]);
    __syncthreads();
  }
  m = red[0];
  __syncthreads();
  float sum = 0.f;
#pragma unroll
  for (int t = 0; t < 16; t++) {
    vals[t] = __expf(vals[t] - m);
    sum += vals[t];
  }
  red[tid] = sum;
  __syncthreads();
  for (int s = 128; s; s >>= 1) {
    if (tid < s) red[tid] += red[tid + s];
    __syncthreads();
  }
  const float inv = 1.f / red[0];
#pragma unroll
  for (int t = 0; t < 16; t++) {
    float att = vals[t] * inv;
    __nv_bfloat16 h = __float2bfloat16(att);
    size_t off = rowbase + tid + t * 256;
    phi[off] = h;
    plo[off] = __float2bfloat16(att - __bfloat162float(h));
  }
}

// ================= launch ====================================================
extern "C" void kernel_launch(void* const* d_in, const int* in_sizes, int n_in,
                              void* d_out, int out_size) {
  const float* x   = (const float*)d_in[0];  // (4096, 2048)
  const float* adj = (const float*)d_in[1];  // (4096, 4096)
  const float* W   = (const float*)d_in[2];  // (2048, 2048)
  const float* a   = (const float*)d_in[3];  // (4096, 1)
  float* out = (float*)d_out;                // (4096, 2048)

  __nv_bfloat16 *xhi, *xlo, *wthi, *wtlo, *hthi, *htlo, *phi, *plo;
  float *P, *s1, *s2, *wa1, *wa2;
  cudaGetSymbolAddress((void**)&xhi,  g_xhi);
  cudaGetSymbolAddress((void**)&xlo,  g_xlo);
  cudaGetSymbolAddress((void**)&wthi, g_wthi);
  cudaGetSymbolAddress((void**)&wtlo, g_wtlo);
  cudaGetSymbolAddress((void**)&hthi, g_hthi);
  cudaGetSymbolAddress((void**)&htlo, g_htlo);
  cudaGetSymbolAddress((void**)&P,    g_P);
  cudaGetSymbolAddress((void**)&phi,  g_phi);
  cudaGetSymbolAddress((void**)&plo,  g_plo);
  cudaGetSymbolAddress((void**)&s1,   g_s1);
  cudaGetSymbolAddress((void**)&s2,   g_s2);
  cudaGetSymbolAddress((void**)&wa1,  g_wa1);
  cudaGetSymbolAddress((void**)&wa2,  g_wa2);

  cudaFuncSetAttribute(gemm_fused, cudaFuncAttributeMaxDynamicSharedMemorySize, SMEM_BYTES);
  cudaFuncSetAttribute(gemm_out,   cudaFuncAttributeMaxDynamicSharedMemorySize, SMEM_BYTES);

  // 1) split x -> bf16 hi/lo; reset fixup counter
  split_x<<<(NN * DD) / 256, 256>>>(x, xhi, xlo);
  // 2) W -> W^T split
  trans_split_w<<<dim3(DD / 32, DD / 32), dim3(32, 8)>>>(W, wthi, wtlo);
  // 3) wa = W@a; s = x@wa  (associativity: (xW)a = x(Wa))
  gemv2<<<DD / 8, 256>>>(W, a, a + DD, wa1, wa2);
  gemv2<<<NN / 8, 256>>>(x, wa1, wa2, s1, s2);
  // 4) fused: logits (triangular x@x^T + mask) AND h = x@W (h^T split)
  gemm_fused<<<528 + 512, 256, SMEM_BYTES>>>(
      xhi, xlo, wthi, wtlo, adj, s1, s2, P, hthi, htlo);
  // 4b) exact fp32 recompute of near-zero dots
  fixup_kernel<<<1024, 256>>>(x, adj, s1, s2, P);
  // 5) row softmax -> attention split bf16
  softmax_rows<<<NN, 256>>>(P, phi, plo);
  // 6) out = elu(attention @ h)
  gemm_out<<<512, 256, SMEM_BYTES>>>(phi, plo, hthi, htlo, out);
}

// round 7
// speedup vs baseline: 4.3160x; 1.4031x over previous
#include <cuda_runtime.h>
#include <cuda_fp16.h>
#include <math.h>
#include <stdint.h>

#define NN 4096   // nodes
#define DD 2048   // features
#define DOT_THR 0.002f
#define MAX_FIX (1 << 22)

// ================= scratch (__device__ globals; no allocs allowed) ==========
__device__ __half g_xhi[(size_t)NN * DD];   // 16 MB
__device__ __half g_xlo[(size_t)NN * DD];   // 16 MB
__device__ __half g_wthi[(size_t)DD * DD];  // 8 MB   W^T split
__device__ __half g_wtlo[(size_t)DD * DD];  // 8 MB
__device__ __half g_hthi[(size_t)DD * NN];  // 16 MB  h^T (fp16 single)
__device__ float  g_P[(size_t)NN * NN];     // 64 MB  logits
__device__ __half g_phi[(size_t)NN * NN];   // 32 MB  attention (fp16 single)
__device__ float g_s1[NN], g_s2[NN];
__device__ float g_wa1[DD], g_wa2[DD];
__device__ int g_cnt;                       // fixup worklist
__device__ int g_list[MAX_FIX];             // 16 MB

// ================= PTX helpers ==============================================
__device__ __forceinline__ uint32_t smem_u32(const void* p) {
  uint32_t a;
  asm("{ .reg .u64 t; cvta.to.shared.u64 t, %1; cvt.u32.u64 %0, t; }"
      : "=r"(a) : "l"(p));
  return a;
}
__device__ __forceinline__ void cp16(uint32_t dst, const void* src) {
  asm volatile("cp.async.cg.shared.global [%0], [%1], 16;" :: "r"(dst), "l"(src));
}
#define CP_COMMIT() asm volatile("cp.async.commit_group;" ::: "memory")
#define CP_WAIT1()  asm volatile("cp.async.wait_group 1;" ::: "memory")
#define CP_WAIT0()  asm volatile("cp.async.wait_group 0;" ::: "memory")

__device__ __forceinline__ void ldm4(uint32_t* r, uint32_t addr) {
  asm volatile("ldmatrix.sync.aligned.m8n8.x4.shared.b16 {%0,%1,%2,%3}, [%4];"
               : "=r"(r[0]), "=r"(r[1]), "=r"(r[2]), "=r"(r[3]) : "r"(addr));
}
__device__ __forceinline__ void mma_f16(float* d, const uint32_t* a,
                                        const uint32_t* b) {
  asm volatile(
      "mma.sync.aligned.m16n8k16.row.col.f32.f16.f16.f32 "
      "{%0,%1,%2,%3}, {%4,%5,%6,%7}, {%8,%9}, {%0,%1,%2,%3};"
      : "+f"(d[0]), "+f"(d[1]), "+f"(d[2]), "+f"(d[3])
      : "r"(a[0]), "r"(a[1]), "r"(a[2]), "r"(a[3]), "r"(b[0]), "r"(b[1]));
}

#define RSTRIDE 80                    // 40 fp16 per row: conflict-free ldmatrix
#define TILE_B  (128 * RSTRIDE)       // 10240 B per operand tile
#define STAGE_B (4 * TILE_B)          // Ahi,Alo,Bhi,Blo
#define SMEM_BYTES (2 * STAGE_B)      // 81920
#define STAGE2_B (2 * TILE_B)         // 1-pass loop: A, B
#define SMEM_BYTES_OUT 66048          // epilogue stage (128*129*4)

// ---- 3-pass split-fp16 mainloop, prefetch-reordered ------------------------
#define GEMM_MAINLOOP(Ahi, Alo, Bhi, Blo, K, ldA, ldB, bm, bn)                  \
  {                                                                             \
    auto load_chunk = [&](int k0, int s) {                                      \
      const uint32_t stg = smBase + (uint32_t)s * STAGE_B;                      \
      _Pragma("unroll")                                                         \
      for (int it = 0; it < 2; it++) {                                          \
        int c = tid + it * 256;                                                 \
        int row = c >> 2, chk = c & 3;                                          \
        uint32_t so = row * RSTRIDE + chk * 16;                                 \
        cp16(stg + so,                                                          \
             (const char*)(Ahi + (size_t)(bm + row) * ldA + k0) + chk * 16);    \
        cp16(stg + TILE_B + so,                                                 \
             (const char*)(Alo + (size_t)(bm + row) * ldA + k0) + chk * 16);    \
        cp16(stg + 2 * TILE_B + so,                                             \
             (const char*)(Bhi + (size_t)(bn + row) * ldB + k0) + chk * 16);    \
        cp16(stg + 3 * TILE_B + so,                                             \
             (const char*)(Blo + (size_t)(bn + row) * ldB + k0) + chk * 16);    \
      }                                                                         \
      CP_COMMIT();                                                              \
    };                                                                          \
    const int nch = (K) / 32;                                                   \
    load_chunk(0, 0);                                                           \
    load_chunk(32, 1);                                                          \
    for (int i = 0; i < nch; i++) {                                             \
      if (i + 1 < nch) CP_WAIT1(); else CP_WAIT0();                             \
      __syncthreads();                                                          \
      const uint32_t stg = smBase + (uint32_t)(i & 1) * STAGE_B;                \
      _Pragma("unroll")                                                         \
      for (int ks = 0; ks < 2; ks++) {                                          \
        const uint32_t kso = (uint32_t)(ks * 32);                               \
        uint32_t ah[4][4], bh[2][4], bl[2][4], al[4][4];                        \
        _Pragma("unroll")                                                       \
        for (int mi = 0; mi < 4; mi++)                                          \
          ldm4(ah[mi], stg + aoff + kso + mi * 16 * RSTRIDE);                   \
        _Pragma("unroll")                                                       \
        for (int nb = 0; nb < 2; nb++)                                          \
          ldm4(bh[nb], stg + 2 * TILE_B + boff + kso + nb * 16 * RSTRIDE);      \
        _Pragma("unroll")                                                       \
        for (int nb = 0; nb < 2; nb++)                                          \
          ldm4(bl[nb], stg + 3 * TILE_B + boff + kso + nb * 16 * RSTRIDE);      \
        _Pragma("unroll")                                                       \
        for (int mi = 0; mi < 4; mi++)                                          \
          _Pragma("unroll")                                                     \
          for (int ni = 0; ni < 4; ni++)                                        \
            mma_f16(acc[mi][ni], ah[mi], &bh[ni >> 1][(ni & 1) * 2]);           \
        _Pragma("unroll")                                                       \
        for (int mi = 0; mi < 4; mi++)                                          \
          ldm4(al[mi], stg + TILE_B + aoff + kso + mi * 16 * RSTRIDE);          \
        _Pragma("unroll")                                                       \
        for (int mi = 0; mi < 4; mi++)                                          \
          _Pragma("unroll")                                                     \
          for (int ni = 0; ni < 4; ni++)                                        \
            mma_f16(acc[mi][ni], ah[mi], &bl[ni >> 1][(ni & 1) * 2]);           \
        _Pragma("unroll")                                                       \
        for (int mi = 0; mi < 4; mi++)                                          \
          _Pragma("unroll")                                                     \
          for (int ni = 0; ni < 4; ni++)                                        \
            mma_f16(acc[mi][ni], al[mi], &bh[ni >> 1][(ni & 1) * 2]);           \
      }                                                                         \
      __syncthreads();                                                          \
      if (i + 2 < nch) load_chunk((i + 2) * 32, i & 1);                         \
    }                                                                           \
  }

#define ACC_TO_SMEM()                                                           \
  {                                                                             \
    const int r0 = wm * 64 + (lane >> 2);                                       \
    const int c0 = wn * 32 + (lane & 3) * 2;                                    \
    _Pragma("unroll")                                                           \
    for (int mi = 0; mi < 4; mi++)                                              \
      _Pragma("unroll")                                                         \
      for (int ni = 0; ni < 4; ni++) {                                          \
        int r = r0 + mi * 16, c = c0 + ni * 8;                                  \
        st[r * 129 + c]           = acc[mi][ni][0];                             \
        st[r * 129 + c + 1]       = acc[mi][ni][1];                             \
        st[(r + 8) * 129 + c]     = acc[mi][ni][2];                             \
        st[(r + 8) * 129 + c + 1] = acc[mi][ni][3];                             \
      }                                                                         \
  }

// ================= fused GEMM: logits (528 blocks) + h (512 blocks) =========
__global__ __launch_bounds__(256, 2)
void gemm_fused(const __half* __restrict__ xhi, const __half* __restrict__ xlo,
                const __half* __restrict__ wthi, const __half* __restrict__ wtlo,
                const float* __restrict__ adj, const float* __restrict__ s1,
                const float* __restrict__ s2, float* __restrict__ P,
                __half* __restrict__ hthi) {
  extern __shared__ __align__(16) char smraw[];
  const uint32_t smBase = smem_u32(smraw);
  const int tid = threadIdx.x, wid = tid >> 5, lane = tid & 31;
  const int wm = wid >> 2, wn = wid & 3;

  const int bid = blockIdx.x;
  const bool logits = bid < 528;
  int bm, bn;
  const __half *Bh, *Bl;
  if (logits) {
    int rem = bid, bi = 0;
    while (rem >= 32 - bi) { rem -= 32 - bi; bi++; }
    bm = bi * 128; bn = (bi + rem) * 128;
    Bh = xhi; Bl = xlo;
  } else {
    int t = bid - 528;                     // 512 blocks: 32 m-tiles x 16 n-tiles
    int group = t >> 7;                    // 8-row supergroups
    int rem = t & 127;
    bm = (group * 8 + (rem & 7)) * 128;
    bn = (rem >> 3) * 128;
    Bh = wthi; Bl = wtlo;
  }

  float acc[4][4][4];
#pragma unroll
  for (int i = 0; i < 4; i++)
#pragma unroll
    for (int j = 0; j < 4; j++)
#pragma unroll
      for (int v = 0; v < 4; v++) acc[i][j][v] = 0.f;

  const uint32_t aoff =
      (uint32_t)((wm * 64 + (lane & 15)) * RSTRIDE + (lane >> 4) * 16);
  const uint32_t boff =
      (uint32_t)((wn * 32 + (lane >> 4) * 8 + (lane & 7)) * RSTRIDE +
                 ((lane >> 3) & 1) * 16);

  GEMM_MAINLOOP(xhi, xlo, Bh, Bl, DD, DD, DD, bm, bn);

  float* st = (float*)smraw;
  ACC_TO_SMEM();
  __syncthreads();

  if (logits) {
#pragma unroll 4
    for (int s = 0; s < 64; s++) {
      int idx = s * 256 + tid;
      int rr = idx >> 7, cc = idx & 127;
      float v = st[rr * 129 + cc];
      int gm = bm + rr, gn = bn + cc;
      float av = adj[(size_t)gm * NN + gn];
      float e = s1[gm] + s2[gn];
      e = (e > 0.f) ? e : 0.1f * e;
      P[(size_t)gm * NN + gn] = (av * v > 0.f) ? e : -9.0e15f;
      if (fabsf(v) < DOT_THR) {
        int slot = atomicAdd(&g_cnt, 1);
        if (slot < MAX_FIX) g_list[slot] = (gm << 12) | gn;
      }
    }
    if (bm != bn) {
#pragma unroll 4
      for (int s = 0; s < 64; s++) {
        int idx = s * 256 + tid;
        int rr = idx >> 7, cc = idx & 127;
        float v = st[cc * 129 + rr];
        int gm = bn + rr, gn = bm + cc;
        float av = adj[(size_t)gm * NN + gn];
        float e = s1[gm] + s2[gn];
        e = (e > 0.f) ? e : 0.1f * e;
        P[(size_t)gm * NN + gn] = (av * v > 0.f) ? e : -9.0e15f;
        if (fabsf(v) < DOT_THR) {
          int slot = atomicAdd(&g_cnt, 1);
          if (slot < MAX_FIX) g_list[slot] = (gm << 12) | gn;
        }
      }
    }
  } else {
    // transposed write: h_t[n][m] fp16 single, coalesced along m
#pragma unroll 4
    for (int s = 0; s < 64; s++) {
      int idx = s * 256 + tid;
      int n = idx >> 7, m = idx & 127;
      hthi[(size_t)(bn + n) * NN + bm + m] = __float2half(st[m * 129 + n]);
    }
  }
}

// ================= out GEMM: out = elu(attention @ h), 1-pass fp16 ==========
__global__ __launch_bounds__(256, 2)
void gemm_out(const __half* __restrict__ phi, const __half* __restrict__ hthi,
              float* __restrict__ out) {
  extern __shared__ __align__(16) char smraw[];
  const uint32_t smBase = smem_u32(smraw);
  const int tid = threadIdx.x, wid = tid >> 5, lane = tid & 31;
  const int wm = wid >> 2, wn = wid & 3;

  // 8-row supergroup swizzle over 32 m-tiles x 16 n-tiles
  const int t = blockIdx.x;
  const int group = t >> 7;
  const int rem = t & 127;
  const int bm = (group * 8 + (rem & 7)) * 128;
  const int bn = (rem >> 3) * 128;

  float acc[4][4][4];
#pragma unroll
  for (int i = 0; i < 4; i++)
#pragma unroll
    for (int j = 0; j < 4; j++)
#pragma unroll
      for (int v = 0; v < 4; v++) acc[i][j][v] = 0.f;

  const uint32_t aoff =
      (uint32_t)((wm * 64 + (lane & 15)) * RSTRIDE + (lane >> 4) * 16);
  const uint32_t boff =
      (uint32_t)((wn * 32 + (lane >> 4) * 8 + (lane & 7)) * RSTRIDE +
                 ((lane >> 3) & 1) * 16);

  auto load_chunk = [&](int k0, int s) {
    const uint32_t stg = smBase + (uint32_t)s * STAGE2_B;
#pragma unroll
    for (int it = 0; it < 2; it++) {
      int c = tid + it * 256;
      int row = c >> 2, chk = c & 3;
      uint32_t so = row * RSTRIDE + chk * 16;
      cp16(stg + so,
           (const char*)(phi + (size_t)(bm + row) * NN + k0) + chk * 16);
      cp16(stg + TILE_B + so,
           (const char*)(hthi + (size_t)(bn + row) * NN + k0) + chk * 16);
    }
    CP_COMMIT();
  };

  const int nch = NN / 32;   // 128
  load_chunk(0, 0);
  load_chunk(32, 1);

  for (int i = 0; i < nch; i++) {
    if (i + 1 < nch) CP_WAIT1(); else CP_WAIT0();
    __syncthreads();
    const uint32_t stg = smBase + (uint32_t)(i & 1) * STAGE2_B;
#pragma unroll
    for (int ks = 0; ks < 2; ks++) {
      const uint32_t kso = (uint32_t)(ks * 32);
      uint32_t ah[4][4], bh[2][4];
#pragma unroll
      for (int mi = 0; mi < 4; mi++)
        ldm4(ah[mi], stg + aoff + kso + mi * 16 * RSTRIDE);
#pragma unroll
      for (int nb = 0; nb < 2; nb++)
        ldm4(bh[nb], stg + TILE_B + boff + kso + nb * 16 * RSTRIDE);
#pragma unroll
      for (int mi = 0; mi < 4; mi++)
#pragma unroll
        for (int ni = 0; ni < 4; ni++)
          mma_f16(acc[mi][ni], ah[mi], &bh[ni >> 1][(ni & 1) * 2]);
    }
    __syncthreads();
    if (i + 2 < nch) load_chunk((i + 2) * 32, i & 1);
  }

  float* st = (float*)smraw;
  ACC_TO_SMEM();
  __syncthreads();

#pragma unroll 4
  for (int s = 0; s < 64; s++) {
    int idx = s * 256 + tid;
    int rr = idx >> 7, cc = idx & 127;
    float v = st[rr * 129 + cc];
    float o = (v > 0.f) ? v : expm1f(v);
    out[(size_t)(bm + rr) * DD + bn + cc] = o;
  }
}

// ================= fixup: exact fp32 dot for near-zero entries =============
__global__ __launch_bounds__(256) void fixup_kernel(
    const float* __restrict__ x, const float* __restrict__ adj,
    const float* __restrict__ s1, const float* __restrict__ s2,
    float* __restrict__ P) {
  const int n = min(g_cnt, MAX_FIX);
  const int warps = gridDim.x * (blockDim.x >> 5);
  const int w0 = blockIdx.x * (blockDim.x >> 5) + (threadIdx.x >> 5);
  const int lane = threadIdx.x & 31;
  for (int idx = w0; idx < n; idx += warps) {
    const int code = g_list[idx];
    const int i = code >> 12, j = code & 4095;
    const float4* xi = (const float4*)(x + (size_t)i * DD);
    const float4* xj = (const float4*)(x + (size_t)j * DD);
    float s = 0.f;
#pragma unroll 4
    for (int k = lane; k < DD / 4; k += 32) {
      float4 a = xi[k], b = xj[k];
      s = fmaf(a.x, b.x, s);
      s = fmaf(a.y, b.y, s);
      s = fmaf(a.z, b.z, s);
      s = fmaf(a.w, b.w, s);
    }
#pragma unroll
    for (int off = 16; off; off >>= 1) s += __shfl_xor_sync(0xffffffffu, s, off);
    if (lane == 0) {
      float av = adj[(size_t)i * NN + j];
      float e = s1[i] + s2[j];
      e = (e > 0.f) ? e : 0.1f * e;
      P[(size_t)i * NN + j] = (av * s > 0.f) ? e : -9.0e15f;
    }
  }
}

// ================= support kernels ==========================================
__global__ __launch_bounds__(256) void split_x(const float* __restrict__ x,
    __half* __restrict__ xhi, __half* __restrict__ xlo) {
  size_t i = (size_t)blockIdx.x * 256 + threadIdx.x;
  float v = x[i];
  __half h = __float2half(v);
  xhi[i] = h;
  xlo[i] = __float2half(v - __half2float(h));
  if (i == 0) g_cnt = 0;
}

__global__ __launch_bounds__(256) void trans_split_w(const float* __restrict__ W,
    __half* __restrict__ wthi, __half* __restrict__ wtlo) {
  __shared__ float t[32][33];
  const int bx = blockIdx.x * 32, by = blockIdx.y * 32;  // bx: n, by: k
  const int tx = threadIdx.x, ty = threadIdx.y;          // block (32,8)
#pragma unroll
  for (int rep = 0; rep < 4; rep++)
    t[ty + rep * 8][tx] = W[(size_t)(by + ty + rep * 8) * DD + bx + tx];
  __syncthreads();
#pragma unroll
  for (int rep = 0; rep < 4; rep++) {
    float v = t[tx][ty + rep * 8];
    __half h = __float2half(v);
    size_t off = (size_t)(bx + ty + rep * 8) * DD + by + tx;
    wthi[off] = h;
    wtlo[off] = __float2half(v - __half2float(h));
  }
}

// rows x D fp32 GEMV, 2 RHS: o1 = M@v1, o2 = M@v2 (one warp per row)
__global__ __launch_bounds__(256) void gemv2(const float* __restrict__ M,
    const float* __restrict__ v1, const float* __restrict__ v2,
    float* __restrict__ o1, float* __restrict__ o2) {
  const int row = blockIdx.x * 8 + (threadIdx.x >> 5);
  const int lane = threadIdx.x & 31;
  const float4* mr = (const float4*)(M + (size_t)row * DD);
  const float4* a1 = (const float4*)v1;
  const float4* a2 = (const float4*)v2;
  float p1 = 0.f, p2 = 0.f;
#pragma unroll 4
  for (int k = lane; k < DD / 4; k += 32) {
    float4 m = mr[k], b1 = a1[k], b2 = a2[k];
    p1 = fmaf(m.x, b1.x, p1); p1 = fmaf(m.y, b1.y, p1);
    p1 = fmaf(m.z, b1.z, p1); p1 = fmaf(m.w, b1.w, p1);
    p2 = fmaf(m.x, b2.x, p2); p2 = fmaf(m.y, b2.y, p2);
    p2 = fmaf(m.z, b2.z, p2); p2 = fmaf(m.w, b2.w, p2);
  }
#pragma unroll
  for (int off = 16; off; off >>= 1) {
    p1 += __shfl_xor_sync(0xffffffffu, p1, off);
    p2 += __shfl_xor_sync(0xffffffffu, p2, off);
  }
  if (lane == 0) { o1[row] = p1; o2[row] = p2; }
}

__global__ __launch_bounds__(256) void softmax_rows(const float* __restrict__ P,
    __half* __restrict__ phi) {
  const int tid = threadIdx.x;
  const size_t rowbase = (size_t)blockIdx.x * NN;
  const float* pr = P + rowbase;
  __shared__ float red[256];

  float vals[16];
  float m = -INFINITY;
#pragma unroll
  for (int t = 0; t < 16; t++) {
    vals[t] = pr[tid + t * 256];
    m = fmaxf(m, vals[t]);
  }
  red[tid] = m;
  __syncthreads();
  for (int s = 128; s; s >>= 1) {
    if (tid < s) red[tid] = fmaxf(red[tid], red[tid + s]);
    __syncthreads();
  }
  m = red[0];
  __syncthreads();
  float sum = 0.f;
#pragma unroll
  for (int t = 0; t < 16; t++) {
    vals[t] = __expf(vals[t] - m);
    sum += vals[t];
  }
  red[tid] = sum;
  __syncthreads();
  for (int s = 128; s; s >>= 1) {
    if (tid < s) red[tid] += red[tid + s];
    __syncthreads();
  }
  const float inv = 1.f / red[0];
#pragma unroll
  for (int t = 0; t < 16; t++)
    phi[rowbase + tid + t * 256] = __float2half(vals[t] * inv);
}

// ================= launch ====================================================
extern "C" void kernel_launch(void* const* d_in, const int* in_sizes, int n_in,
                              void* d_out, int out_size) {
  const float* x   = (const float*)d_in[0];  // (4096, 2048)
  const float* adj = (const float*)d_in[1];  // (4096, 4096)
  const float* W   = (const float*)d_in[2];  // (2048, 2048)
  const float* a   = (const float*)d_in[3];  // (4096, 1)
  float* out = (float*)d_out;                // (4096, 2048)

  __half *xhi, *xlo, *wthi, *wtlo, *hthi, *phi;
  float *P, *s1, *s2, *wa1, *wa2;
  cudaGetSymbolAddress((void**)&xhi,  g_xhi);
  cudaGetSymbolAddress((void**)&xlo,  g_xlo);
  cudaGetSymbolAddress((void**)&wthi, g_wthi);
  cudaGetSymbolAddress((void**)&wtlo, g_wtlo);
  cudaGetSymbolAddress((void**)&hthi, g_hthi);
  cudaGetSymbolAddress((void**)&P,    g_P);
  cudaGetSymbolAddress((void**)&phi,  g_phi);
  cudaGetSymbolAddress((void**)&s1,   g_s1);
  cudaGetSymbolAddress((void**)&s2,   g_s2);
  cudaGetSymbolAddress((void**)&wa1,  g_wa1);
  cudaGetSymbolAddress((void**)&wa2,  g_wa2);

  cudaFuncSetAttribute(gemm_fused, cudaFuncAttributeMaxDynamicSharedMemorySize, SMEM_BYTES);
  cudaFuncSetAttribute(gemm_out,   cudaFuncAttributeMaxDynamicSharedMemorySize, SMEM_BYTES_OUT);

  // 1) split x -> fp16 hi/lo; reset fixup counter
  split_x<<<(NN * DD) / 256, 256>>>(x, xhi, xlo);
  // 2) W -> W^T split fp16
  trans_split_w<<<dim3(DD / 32, DD / 32), dim3(32, 8)>>>(W, wthi, wtlo);
  // 3) wa = W@a; s = x@wa  (associativity: (xW)a = x(Wa))
  gemv2<<<DD / 8, 256>>>(W, a, a + DD, wa1, wa2);
  gemv2<<<NN / 8, 256>>>(x, wa1, wa2, s1, s2);
  // 4) fused: logits (triangular x@x^T + mask) AND h = x@W (h^T fp16)
  gemm_fused<<<528 + 512, 256, SMEM_BYTES>>>(
      xhi, xlo, wthi, wtlo, adj, s1, s2, P, hthi);
  // 4b) exact fp32 recompute of near-zero dots
  fixup_kernel<<<1024, 256>>>(x, adj, s1, s2, P);
  // 5) row softmax -> attention fp16
  softmax_rows<<<NN, 256>>>(P, phi);
  // 6) out = elu(attention @ h), 1-pass fp16
  gemm_out<<<512, 256, SMEM_BYTES_OUT>>>(phi, hthi, out);
}

// round 8
// speedup vs baseline: 4.7765x; 1.1067x over previous
#include <cuda_runtime.h>
#include <cuda_fp16.h>
#include <math.h>
#include <stdint.h>

#define NN 4096   // nodes
#define DD 2048   // features
#define DOT_THR 0.15f
#define MAX_FIX (1 << 22)

// ================= scratch (__device__ globals; no allocs allowed) ==========
__device__ __half g_xhi[(size_t)NN * DD];   // 16 MB
__device__ __half g_xlo[(size_t)NN * DD];   // 16 MB
__device__ __half g_wthi[(size_t)DD * DD];  // 8 MB   W^T split
__device__ __half g_wtlo[(size_t)DD * DD];  // 8 MB
__device__ __half g_hthi[(size_t)DD * NN];  // 16 MB  h^T (fp16 single)
__device__ float  g_P[(size_t)NN * NN];     // 64 MB  logits
__device__ __half g_phi[(size_t)NN * NN];   // 32 MB  attention (fp16 single)
__device__ float g_s1[NN], g_s2[NN];
__device__ float g_wa1[DD], g_wa2[DD];
__device__ int g_cnt;                       // fixup worklist
__device__ int g_list[MAX_FIX];             // 16 MB

// ================= PTX helpers ==============================================
__device__ __forceinline__ uint32_t smem_u32(const void* p) {
  uint32_t a;
  asm("{ .reg .u64 t; cvta.to.shared.u64 t, %1; cvt.u32.u64 %0, t; }"
      : "=r"(a) : "l"(p));
  return a;
}
__device__ __forceinline__ void cp16(uint32_t dst, const void* src) {
  asm volatile("cp.async.cg.shared.global [%0], [%1], 16;" :: "r"(dst), "l"(src));
}
#define CP_COMMIT() asm volatile("cp.async.commit_group;" ::: "memory")
#define CP_WAIT1()  asm volatile("cp.async.wait_group 1;" ::: "memory")
#define CP_WAIT0()  asm volatile("cp.async.wait_group 0;" ::: "memory")

__device__ __forceinline__ void ldm4(uint32_t* r, uint32_t addr) {
  asm volatile("ldmatrix.sync.aligned.m8n8.x4.shared.b16 {%0,%1,%2,%3}, [%4];"
               : "=r"(r[0]), "=r"(r[1]), "=r"(r[2]), "=r"(r[3]) : "r"(addr));
}
__device__ __forceinline__ void mma_f16(float* d, const uint32_t* a,
                                        const uint32_t* b) {
  asm volatile(
      "mma.sync.aligned.m16n8k16.row.col.f32.f16.f16.f32 "
      "{%0,%1,%2,%3}, {%4,%5,%6,%7}, {%8,%9}, {%0,%1,%2,%3};"
      : "+f"(d[0]), "+f"(d[1]), "+f"(d[2]), "+f"(d[3])
      : "r"(a[0]), "r"(a[1]), "r"(a[2]), "r"(a[3]), "r"(b[0]), "r"(b[1]));
}

#define RSTRIDE 80                    // 40 fp16 per row: conflict-free ldmatrix
#define TILE_B  (128 * RSTRIDE)       // 10240 B per operand tile
#define STAGE_B (4 * TILE_B)          // Ahi,Alo,Bhi,Blo (3-pass)
#define SMEM_BYTES (2 * STAGE_B)      // 81920
#define STAGE2_B (2 * TILE_B)         // 1-pass loop: A, B
#define SMEM_BYTES_OUT 66048          // epilogue stage (128*129*4)

// ---- 3-pass split-fp16 mainloop, prefetch-reordered ------------------------
#define GEMM_MAINLOOP(Ahi, Alo, Bhi, Blo, K, ldA, ldB, bm, bn)                  \
  {                                                                             \
    auto load_chunk = [&](int k0, int s) {                                      \
      const uint32_t stg = smBase + (uint32_t)s * STAGE_B;                      \
      _Pragma("unroll")                                                         \
      for (int it = 0; it < 2; it++) {                                          \
        int c = tid + it * 256;                                                 \
        int row = c >> 2, chk = c & 3;                                          \
        uint32_t so = row * RSTRIDE + chk * 16;                                 \
        cp16(stg + so,                                                          \
             (const char*)(Ahi + (size_t)(bm + row) * ldA + k0) + chk * 16);    \
        cp16(stg + TILE_B + so,                                                 \
             (const char*)(Alo + (size_t)(bm + row) * ldA + k0) + chk * 16);    \
        cp16(stg + 2 * TILE_B + so,                                             \
             (const char*)(Bhi + (size_t)(bn + row) * ldB + k0) + chk * 16);    \
        cp16(stg + 3 * TILE_B + so,                                             \
             (const char*)(Blo + (size_t)(bn + row) * ldB + k0) + chk * 16);    \
      }                                                                         \
      CP_COMMIT();                                                              \
    };                                                                          \
    const int nch = (K) / 32;                                                   \
    load_chunk(0, 0);                                                           \
    load_chunk(32, 1);                                                          \
    for (int i = 0; i < nch; i++) {                                             \
      if (i + 1 < nch) CP_WAIT1(); else CP_WAIT0();                             \
      __syncthreads();                                                          \
      const uint32_t stg = smBase + (uint32_t)(i & 1) * STAGE_B;                \
      _Pragma("unroll")                                                         \
      for (int ks = 0; ks < 2; ks++) {                                          \
        const uint32_t kso = (uint32_t)(ks * 32);                               \
        uint32_t ah[4][4], bh[2][4], bl[2][4], al[4][4];                        \
        _Pragma("unroll")                                                       \
        for (int mi = 0; mi < 4; mi++)                                          \
          ldm4(ah[mi], stg + aoff + kso + mi * 16 * RSTRIDE);                   \
        _Pragma("unroll")                                                       \
        for (int nb = 0; nb < 2; nb++)                                          \
          ldm4(bh[nb], stg + 2 * TILE_B + boff + kso + nb * 16 * RSTRIDE);      \
        _Pragma("unroll")                                                       \
        for (int nb = 0; nb < 2; nb++)                                          \
          ldm4(bl[nb], stg + 3 * TILE_B + boff + kso + nb * 16 * RSTRIDE);      \
        _Pragma("unroll")                                                       \
        for (int mi = 0; mi < 4; mi++)                                          \
          _Pragma("unroll")                                                     \
          for (int ni = 0; ni < 4; ni++)                                        \
            mma_f16(acc[mi][ni], ah[mi], &bh[ni >> 1][(ni & 1) * 2]);           \
        _Pragma("unroll")                                                       \
        for (int mi = 0; mi < 4; mi++)                                          \
          ldm4(al[mi], stg + TILE_B + aoff + kso + mi * 16 * RSTRIDE);          \
        _Pragma("unroll")                                                       \
        for (int mi = 0; mi < 4; mi++)                                          \
          _Pragma("unroll")                                                     \
          for (int ni = 0; ni < 4; ni++)                                        \
            mma_f16(acc[mi][ni], ah[mi], &bl[ni >> 1][(ni & 1) * 2]);           \
        _Pragma("unroll")                                                       \
        for (int mi = 0; mi < 4; mi++)                                          \
          _Pragma("unroll")                                                     \
          for (int ni = 0; ni < 4; ni++)                                        \
            mma_f16(acc[mi][ni], al[mi], &bh[ni >> 1][(ni & 1) * 2]);           \
      }                                                                         \
      __syncthreads();                                                          \
      if (i + 2 < nch) load_chunk((i + 2) * 32, i & 1);                         \
    }                                                                           \
  }

// ---- 1-pass fp16 mainloop (A rows at bm from Ap, B rows at bn from Bp) -----
#define GEMM_MAINLOOP_1P(Ap, Bp, K, ldA, ldB, bm, bn)                           \
  {                                                                             \
    auto load2 = [&](int k0, int s) {                                           \
      const uint32_t stg = smBase + (uint32_t)s * STAGE2_B;                     \
      _Pragma("unroll")                                                         \
      for (int it = 0; it < 2; it++) {                                          \
        int c = tid + it * 256;                                                 \
        int row = c >> 2, chk = c & 3;                                          \
        uint32_t so = row * RSTRIDE + chk * 16;                                 \
        cp16(stg + so,                                                          \
             (const char*)(Ap + (size_t)(bm + row) * ldA + k0) + chk * 16);     \
        cp16(stg + TILE_B + so,                                                 \
             (const char*)(Bp + (size_t)(bn + row) * ldB + k0) + chk * 16);     \
      }                                                                         \
      CP_COMMIT();                                                              \
    };                                                                          \
    const int nch = (K) / 32;                                                   \
    load2(0, 0);                                                                \
    load2(32, 1);                                                               \
    for (int i = 0; i < nch; i++) {                                             \
      if (i + 1 < nch) CP_WAIT1(); else CP_WAIT0();                             \
      __syncthreads();                                                          \
      const uint32_t stg = smBase + (uint32_t)(i & 1) * STAGE2_B;               \
      _Pragma("unroll")                                                         \
      for (int ks = 0; ks < 2; ks++) {                                          \
        const uint32_t kso = (uint32_t)(ks * 32);                               \
        uint32_t ah[4][4], bh[2][4];                                            \
        _Pragma("unroll")                                                       \
        for (int mi = 0; mi < 4; mi++)                                          \
          ldm4(ah[mi], stg + aoff + kso + mi * 16 * RSTRIDE);                   \
        _Pragma("unroll")                                                       \
        for (int nb = 0; nb < 2; nb++)                                          \
          ldm4(bh[nb], stg + TILE_B + boff + kso + nb * 16 * RSTRIDE);          \
        _Pragma("unroll")                                                       \
        for (int mi = 0; mi < 4; mi++)                                          \
          _Pragma("unroll")                                                     \
          for (int ni = 0; ni < 4; ni++)                                        \
            mma_f16(acc[mi][ni], ah[mi], &bh[ni >> 1][(ni & 1) * 2]);           \
      }                                                                         \
      __syncthreads();                                                          \
      if (i + 2 < nch) load2((i + 2) * 32, i & 1);                              \
    }                                                                           \
  }

#define ACC_TO_SMEM()                                                           \
  {                                                                             \
    const int r0 = wm * 64 + (lane >> 2);                                       \
    const int c0 = wn * 32 + (lane & 3) * 2;                                    \
    _Pragma("unroll")                                                           \
    for (int mi = 0; mi < 4; mi++)                                              \
      _Pragma("unroll")                                                         \
      for (int ni = 0; ni < 4; ni++) {                                          \
        int r = r0 + mi * 16, c = c0 + ni * 8;                                  \
        st[r * 129 + c]           = acc[mi][ni][0];                             \
        st[r * 129 + c + 1]       = acc[mi][ni][1];                             \
        st[(r + 8) * 129 + c]     = acc[mi][ni][2];                             \
        st[(r + 8) * 129 + c + 1] = acc[mi][ni][3];                             \
      }                                                                         \
  }

// ================= fused GEMM: logits 1-pass (528) + h 3-pass (512) =========
__global__ __launch_bounds__(256, 2)
void gemm_fused(const __half* __restrict__ xhi, const __half* __restrict__ xlo,
                const __half* __restrict__ wthi, const __half* __restrict__ wtlo,
                const float* __restrict__ adj, const float* __restrict__ s1,
                const float* __restrict__ s2, float* __restrict__ P,
                __half* __restrict__ hthi) {
  extern __shared__ __align__(16) char smraw[];
  const uint32_t smBase = smem_u32(smraw);
  const int tid = threadIdx.x, wid = tid >> 5, lane = tid & 31;
  const int wm = wid >> 2, wn = wid & 3;

  const int bid = blockIdx.x;
  const bool logits = bid < 528;
  int bm, bn;
  if (logits) {
    int rem = bid, bi = 0;
    while (rem >= 32 - bi) { rem -= 32 - bi; bi++; }
    bm = bi * 128; bn = (bi + rem) * 128;
  } else {
    int t = bid - 528;                     // 512 blocks: 32 m-tiles x 16 n-tiles
    int group = t >> 7;                    // 8-row supergroups
    int rem = t & 127;
    bm = (group * 8 + (rem & 7)) * 128;
    bn = (rem >> 3) * 128;
  }

  float acc[4][4][4];
#pragma unroll
  for (int i = 0; i < 4; i++)
#pragma unroll
    for (int j = 0; j < 4; j++)
#pragma unroll
      for (int v = 0; v < 4; v++) acc[i][j][v] = 0.f;

  const uint32_t aoff =
      (uint32_t)((wm * 64 + (lane & 15)) * RSTRIDE + (lane >> 4) * 16);
  const uint32_t boff =
      (uint32_t)((wn * 32 + (lane >> 4) * 8 + (lane & 7)) * RSTRIDE +
                 ((lane >> 3) & 1) * 16);

  if (logits) {
    GEMM_MAINLOOP_1P(xhi, xhi, DD, DD, DD, bm, bn);
  } else {
    GEMM_MAINLOOP(xhi, xlo, wthi, wtlo, DD, DD, DD, bm, bn);
  }

  float* st = (float*)smraw;
  ACC_TO_SMEM();
  __syncthreads();

  if (logits) {
#pragma unroll 4
    for (int s = 0; s < 64; s++) {
      int idx = s * 256 + tid;
      int rr = idx >> 7, cc = idx & 127;
      float v = st[rr * 129 + cc];
      int gm = bm + rr, gn = bn + cc;
      float av = adj[(size_t)gm * NN + gn];
      float e = s1[gm] + s2[gn];
      e = (e > 0.f) ? e : 0.1f * e;
      P[(size_t)gm * NN + gn] = (av * v > 0.f) ? e : -9.0e15f;
      if (fabsf(v) < DOT_THR) {
        int slot = atomicAdd(&g_cnt, 1);
        if (slot < MAX_FIX) g_list[slot] = (gm << 12) | gn;
      }
    }
    if (bm != bn) {
#pragma unroll 4
      for (int s = 0; s < 64; s++) {
        int idx = s * 256 + tid;
        int rr = idx >> 7, cc = idx & 127;
        float v = st[cc * 129 + rr];
        int gm = bn + rr, gn = bm + cc;
        float av = adj[(size_t)gm * NN + gn];
        float e = s1[gm] + s2[gn];
        e = (e > 0.f) ? e : 0.1f * e;
        P[(size_t)gm * NN + gn] = (av * v > 0.f) ? e : -9.0e15f;
        if (fabsf(v) < DOT_THR) {
          int slot = atomicAdd(&g_cnt, 1);
          if (slot < MAX_FIX) g_list[slot] = (gm << 12) | gn;
        }
      }
    }
  } else {
    // transposed write: h_t[n][m] fp16 single, coalesced along m
#pragma unroll 4
    for (int s = 0; s < 64; s++) {
      int idx = s * 256 + tid;
      int n = idx >> 7, m = idx & 127;
      hthi[(size_t)(bn + n) * NN + bm + m] = __float2half(st[m * 129 + n]);
    }
  }
}

// ================= out GEMM: out = elu(attention @ h), 1-pass fp16 ==========
__global__ __launch_bounds__(256, 2)
void gemm_out(const __half* __restrict__ phi, const __half* __restrict__ hthi,
              float* __restrict__ out) {
  extern __shared__ __align__(16) char smraw[];
  const uint32_t smBase = smem_u32(smraw);
  const int tid = threadIdx.x, wid = tid >> 5, lane = tid & 31;
  const int wm = wid >> 2, wn = wid & 3;

  const int t = blockIdx.x;
  const int group = t >> 7;
  const int rem = t & 127;
  const int bm = (group * 8 + (rem & 7)) * 128;
  const int bn = (rem >> 3) * 128;

  float acc[4][4][4];
#pragma unroll
  for (int i = 0; i < 4; i++)
#pragma unroll
    for (int j = 0; j < 4; j++)
#pragma unroll
      for (int v = 0; v < 4; v++) acc[i][j][v] = 0.f;

  const uint32_t aoff =
      (uint32_t)((wm * 64 + (lane & 15)) * RSTRIDE + (lane >> 4) * 16);
  const uint32_t boff =
      (uint32_t)((wn * 32 + (lane >> 4) * 8 + (lane & 7)) * RSTRIDE +
                 ((lane >> 3) & 1) * 16);

  GEMM_MAINLOOP_1P(phi, hthi, NN, NN, NN, bm, bn);

  float* st = (float*)smraw;
  ACC_TO_SMEM();
  __syncthreads();

#pragma unroll 4
  for (int s = 0; s < 64; s++) {
    int idx = s * 256 + tid;
    int rr = idx >> 7, cc = idx & 127;
    float v = st[rr * 129 + cc];
    float o = (v > 0.f) ? v : expm1f(v);
    out[(size_t)(bm + rr) * DD + bn + cc] = o;
  }
}

// ================= fixup: exact fp32 dot for near-zero entries =============
__global__ __launch_bounds__(256) void fixup_kernel(
    const float* __restrict__ x, const float* __restrict__ adj,
    const float* __restrict__ s1, const float* __restrict__ s2,
    float* __restrict__ P) {
  const int n = min(g_cnt, MAX_FIX);
  const int warps = gridDim.x * (blockDim.x >> 5);
  const int w0 = blockIdx.x * (blockDim.x >> 5) + (threadIdx.x >> 5);
  const int lane = threadIdx.x & 31;
  for (int idx = w0; idx < n; idx += warps) {
    const int code = g_list[idx];
    const int i = code >> 12, j = code & 4095;
    const float4* xi = (const float4*)(x + (size_t)i * DD);
    const float4* xj = (const float4*)(x + (size_t)j * DD);
    float s = 0.f;
#pragma unroll 4
    for (int k = lane; k < DD / 4; k += 32) {
      float4 a = xi[k], b = xj[k];
      s = fmaf(a.x, b.x, s);
      s = fmaf(a.y, b.y, s);
      s = fmaf(a.z, b.z, s);
      s = fmaf(a.w, b.w, s);
    }
#pragma unroll
    for (int off = 16; off; off >>= 1) s += __shfl_xor_sync(0xffffffffu, s, off);
    if (lane == 0) {
      float av = adj[(size_t)i * NN + j];
      float e = s1[i] + s2[j];
      e = (e > 0.f) ? e : 0.1f * e;
      P[(size_t)i * NN + j] = (av * s > 0.f) ? e : -9.0e15f;
    }
  }
}

// ================= support kernels ==========================================
__global__ __launch_bounds__(256) void split_x(const float* __restrict__ x,
    __half* __restrict__ xhi, __half* __restrict__ xlo) {
  size_t i = (size_t)blockIdx.x * 256 + threadIdx.x;
  float v = x[i];
  __half h = __float2half(v);
  xhi[i] = h;
  xlo[i] = __float2half(v - __half2float(h));
  if (i == 0) g_cnt = 0;
}

__global__ __launch_bounds__(256) void trans_split_w(const float* __restrict__ W,
    __half* __restrict__ wthi, __half* __restrict__ wtlo) {
  __shared__ float t[32][33];
  const int bx = blockIdx.x * 32, by = blockIdx.y * 32;  // bx: n, by: k
  const int tx = threadIdx.x, ty = threadIdx.y;          // block (32,8)
#pragma unroll
  for (int rep = 0; rep < 4; rep++)
    t[ty + rep * 8][tx] = W[(size_t)(by + ty + rep * 8) * DD + bx + tx];
  __syncthreads();
#pragma unroll
  for (int rep = 0; rep < 4; rep++) {
    float v = t[tx][ty + rep * 8];
    __half h = __float2half(v);
    size_t off = (size_t)(bx + ty + rep * 8) * DD + by + tx;
    wthi[off] = h;
    wtlo[off] = __float2half(v - __half2float(h));
  }
}

// rows x D fp32 GEMV, 2 RHS: o1 = M@v1, o2 = M@v2 (one warp per row)
__global__ __launch_bounds__(256) void gemv2(const float* __restrict__ M,
    const float* __restrict__ v1, const float* __restrict__ v2,
    float* __restrict__ o1, float* __restrict__ o2) {
  const int row = blockIdx.x * 8 + (threadIdx.x >> 5);
  const int lane = threadIdx.x & 31;
  const float4* mr = (const float4*)(M + (size_t)row * DD);
  const float4* a1 = (const float4*)v1;
  const float4* a2 = (const float4*)v2;
  float p1 = 0.f, p2 = 0.f;
#pragma unroll 4
  for (int k = lane; k < DD / 4; k += 32) {
    float4 m = mr[k], b1 = a1[k], b2 = a2[k];
    p1 = fmaf(m.x, b1.x, p1); p1 = fmaf(m.y, b1.y, p1);
    p1 = fmaf(m.z, b1.z, p1); p1 = fmaf(m.w, b1.w, p1);
    p2 = fmaf(m.x, b2.x, p2); p2 = fmaf(m.y, b2.y, p2);
    p2 = fmaf(m.z, b2.z, p2); p2 = fmaf(m.w, b2.w, p2);
  }
#pragma unroll
  for (int off = 16; off; off >>= 1) {
    p1 += __shfl_xor_sync(0xffffffffu, p1, off);
    p2 += __shfl_xor_sync(0xffffffffu, p2, off);
  }
  if (lane == 0) { o1[row] = p1; o2[row] = p2; }
}

__global__ __launch_bounds__(256) void softmax_rows(const float* __restrict__ P,
    __half* __restrict__ phi) {
  const int tid = threadIdx.x;
  const size_t rowbase = (size_t)blockIdx.x * NN;
  const float* pr = P + rowbase;
  __shared__ float red[256];

  float vals[16];
  float m = -INFINITY;
#pragma unroll
  for (int t = 0; t < 16; t++) {
    vals[t] = pr[tid + t * 256];
    m = fmaxf(m, vals[t]);
  }
  red[tid] = m;
  __syncthreads();
  for (int s = 128; s; s >>= 1) {
    if (tid < s) red[tid] = fmaxf(red[tid], red[tid + s]);
    __syncthreads();
  }
  m = red[0];
  __syncthreads();
  float sum = 0.f;
#pragma unroll
  for (int t = 0; t < 16; t++) {
    vals[t] = __expf(vals[t] - m);
    sum += vals[t];
  }
  red[tid] = sum;
  __syncthreads();
  for (int s = 128; s; s >>= 1) {
    if (tid < s) red[tid] += red[tid + s];
    __syncthreads();
  }
  const float inv = 1.f / red[0];
#pragma unroll
  for (int t = 0; t < 16; t++)
    phi[rowbase + tid + t * 256] = __float2half(vals[t] * inv);
}

// ================= launch ====================================================
extern "C" void kernel_launch(void* const* d_in, const int* in_sizes, int n_in,
                              void* d_out, int out_size) {
  const float* x   = (const float*)d_in[0];  // (4096, 2048)
  const float* adj = (const float*)d_in[1];  // (4096, 4096)
  const float* W   = (const float*)d_in[2];  // (2048, 2048)
  const float* a   = (const float*)d_in[3];  // (4096, 1)
  float* out = (float*)d_out;                // (4096, 2048)

  __half *xhi, *xlo, *wthi, *wtlo, *hthi, *phi;
  float *P, *s1, *s2, *wa1, *wa2;
  cudaGetSymbolAddress((void**)&xhi,  g_xhi);
  cudaGetSymbolAddress((void**)&xlo,  g_xlo);
  cudaGetSymbolAddress((void**)&wthi, g_wthi);
  cudaGetSymbolAddress((void**)&wtlo, g_wtlo);
  cudaGetSymbolAddress((void**)&hthi, g_hthi);
  cudaGetSymbolAddress((void**)&P,    g_P);
  cudaGetSymbolAddress((void**)&phi,  g_phi);
  cudaGetSymbolAddress((void**)&s1,   g_s1);
  cudaGetSymbolAddress((void**)&s2,   g_s2);
  cudaGetSymbolAddress((void**)&wa1,  g_wa1);
  cudaGetSymbolAddress((void**)&wa2,  g_wa2);

  cudaFuncSetAttribute(gemm_fused, cudaFuncAttributeMaxDynamicSharedMemorySize, SMEM_BYTES);
  cudaFuncSetAttribute(gemm_out,   cudaFuncAttributeMaxDynamicSharedMemorySize, SMEM_BYTES_OUT);

  // 1) split x -> fp16 hi/lo; reset fixup counter
  split_x<<<(NN * DD) / 256, 256>>>(x, xhi, xlo);
  // 2) W -> W^T split fp16
  trans_split_w<<<dim3(DD / 32, DD / 32), dim3(32, 8)>>>(W, wthi, wtlo);
  // 3) wa = W@a; s = x@wa  (associativity: (xW)a = x(Wa))
  gemv2<<<DD / 8, 256>>>(W, a, a + DD, wa1, wa2);
  gemv2<<<NN / 8, 256>>>(x, wa1, wa2, s1, s2);
  // 4) fused: logits 1-pass (triangular x@x^T + mask) AND h = x@W 3-pass
  gemm_fused<<<528 + 512, 256, SMEM_BYTES>>>(
      xhi, xlo, wthi, wtlo, adj, s1, s2, P, hthi);
  // 4b) exact fp32 recompute of near-zero dots (~45K entries)
  fixup_kernel<<<1024, 256>>>(x, adj, s1, s2, P);
  // 5) row softmax -> attention fp16
  softmax_rows<<<NN, 256>>>(P, phi);
  // 6) out = elu(attention @ h), 1-pass fp16
  gemm_out<<<512, 256, SMEM_BYTES_OUT>>>(phi, hthi, out);
}

// round 9
// speedup vs baseline: 6.2401x; 1.3064x over previous
#include <cuda_runtime.h>
#include <cuda_fp16.h>
#include <math.h>
#include <stdint.h>

#define NN 4096   // nodes
#define DD 2048   // features
#define DOT_THR 0.15f
#define MAX_FIX (1 << 22)

// ================= scratch (__device__ globals; no allocs allowed) ==========
__device__ __half g_xhi[(size_t)NN * DD];   // 16 MB
__device__ __half g_wthi[(size_t)DD * DD];  // 8 MB   W^T fp16
__device__ __half g_hthi[(size_t)DD * NN];  // 16 MB  h^T fp16
__device__ float  g_P[(size_t)NN * NN];     // 64 MB  logits
__device__ __half g_phi[(size_t)NN * NN];   // 32 MB  attention fp16
__device__ float g_s1[NN], g_s2[NN];
__device__ float g_wa1[DD], g_wa2[DD];
__device__ int g_cnt;                       // fixup worklist
__device__ int g_list[MAX_FIX];             // 16 MB

// ================= PTX helpers ==============================================
__device__ __forceinline__ uint32_t smem_u32(const void* p) {
  uint32_t a;
  asm("{ .reg .u64 t; cvta.to.shared.u64 t, %1; cvt.u32.u64 %0, t; }"
      : "=r"(a) : "l"(p));
  return a;
}
__device__ __forceinline__ void cp16(uint32_t dst, const void* src) {
  asm volatile("cp.async.cg.shared.global [%0], [%1], 16;" :: "r"(dst), "l"(src));
}
#define CP_COMMIT() asm volatile("cp.async.commit_group;" ::: "memory")
#define CP_WAIT1()  asm volatile("cp.async.wait_group 1;" ::: "memory")
#define CP_WAIT0()  asm volatile("cp.async.wait_group 0;" ::: "memory")

__device__ __forceinline__ void ldm4(uint32_t* r, uint32_t addr) {
  asm volatile("ldmatrix.sync.aligned.m8n8.x4.shared.b16 {%0,%1,%2,%3}, [%4];"
               : "=r"(r[0]), "=r"(r[1]), "=r"(r[2]), "=r"(r[3]) : "r"(addr));
}
__device__ __forceinline__ void mma_f16(float* d, const uint32_t* a,
                                        const uint32_t* b) {
  asm volatile(
      "mma.sync.aligned.m16n8k16.row.col.f32.f16.f16.f32 "
      "{%0,%1,%2,%3}, {%4,%5,%6,%7}, {%8,%9}, {%0,%1,%2,%3};"
      : "+f"(d[0]), "+f"(d[1]), "+f"(d[2]), "+f"(d[3])
      : "r"(a[0]), "r"(a[1]), "r"(a[2]), "r"(a[3]), "r"(b[0]), "r"(b[1]));
}

#define RSTRIDE 80                    // 40 fp16 per row: conflict-free ldmatrix
#define TILE_B  (128 * RSTRIDE)       // 10240 B per 128x32 operand tile
#define STAGE_B (4 * TILE_B)          // A0,A1,B0,B1 (BK=64 as 2 sub-chunks)
#define SMEM_BYTES (2 * STAGE_B)      // 81920

// ---- 1-pass fp16 mainloop, BK=64 (2 sub-chunks per stage) ------------------
#define GEMM_MAINLOOP_1P64(Ap, Bp, K, ldA, ldB, bm, bn)                         \
  {                                                                             \
    auto load64 = [&](int k0, int s) {                                          \
      const uint32_t stg = smBase + (uint32_t)s * STAGE_B;                      \
      _Pragma("unroll")                                                         \
      for (int it = 0; it < 2; it++) {                                          \
        int c = tid + it * 256;            /* 0..511 */                         \
        int row = c >> 2, chk = c & 3;     /* 4 x 16B per 64B sub-row */        \
        uint32_t so = row * RSTRIDE + chk * 16;                                 \
        const char* arow = (const char*)(Ap + (size_t)(bm + row) * ldA + k0);   \
        const char* brow = (const char*)(Bp + (size_t)(bn + row) * ldB + k0);   \
        cp16(stg + so,               arow + chk * 16);                          \
        cp16(stg + TILE_B + so,      arow + 64 + chk * 16);                     \
        cp16(stg + 2 * TILE_B + so,  brow + chk * 16);                          \
        cp16(stg + 3 * TILE_B + so,  brow + 64 + chk * 16);                     \
      }                                                                         \
      CP_COMMIT();                                                              \
    };                                                                          \
    const int nch = (K) / 64;                                                   \
    load64(0, 0);                                                               \
    load64(64, 1);                                                              \
    for (int i = 0; i < nch; i++) {                                             \
      if (i + 1 < nch) CP_WAIT1(); else CP_WAIT0();                             \
      __syncthreads();                                                          \
      const uint32_t stg = smBase + (uint32_t)(i & 1) * STAGE_B;                \
      _Pragma("unroll")                                                         \
      for (int sub = 0; sub < 2; sub++) {                                       \
        _Pragma("unroll")                                                       \
        for (int ks = 0; ks < 2; ks++) {                                        \
          const uint32_t kso = (uint32_t)(ks * 32);                             \
          uint32_t ah[4][4], bh[2][4];                                          \
          _Pragma("unroll")                                                     \
          for (int mi = 0; mi < 4; mi++)                                        \
            ldm4(ah[mi], stg + sub * TILE_B + aoff + kso + mi * 16 * RSTRIDE);  \
          _Pragma("unroll")                                                     \
          for (int nb = 0; nb < 2; nb++)                                        \
            ldm4(bh[nb],                                                        \
                 stg + (2 + sub) * TILE_B + boff + kso + nb * 16 * RSTRIDE);    \
          _Pragma("unroll")                                                     \
          for (int mi = 0; mi < 4; mi++)                                        \
            _Pragma("unroll")                                                   \
            for (int ni = 0; ni < 4; ni++)                                      \
              mma_f16(acc[mi][ni], ah[mi], &bh[ni >> 1][(ni & 1) * 2]);         \
        }                                                                       \
      }                                                                         \
      __syncthreads();                                                          \
      if (i + 2 < nch) load64((i + 2) * 64, i & 1);                             \
    }                                                                           \
  }

#define ACC_TO_SMEM()                                                           \
  {                                                                             \
    const int r0 = wm * 64 + (lane >> 2);                                       \
    const int c0 = wn * 32 + (lane & 3) * 2;                                    \
    _Pragma("unroll")                                                           \
    for (int mi = 0; mi < 4; mi++)                                              \
      _Pragma("unroll")                                                         \
      for (int ni = 0; ni < 4; ni++) {                                          \
        int r = r0 + mi * 16, c = c0 + ni * 8;                                  \
        st[r * 129 + c]           = acc[mi][ni][0];                             \
        st[r * 129 + c + 1]       = acc[mi][ni][1];                             \
        st[(r + 8) * 129 + c]     = acc[mi][ni][2];                             \
        st[(r + 8) * 129 + c + 1] = acc[mi][ni][3];                             \
      }                                                                         \
  }

// ================= fused GEMM: logits (528) + h (512), both 1-pass BK64 =====
__global__ __launch_bounds__(256, 2)
void gemm_fused(const __half* __restrict__ xhi, const __half* __restrict__ wthi,
                const float* __restrict__ adj, const float* __restrict__ s1,
                const float* __restrict__ s2, float* __restrict__ P,
                __half* __restrict__ hthi) {
  extern __shared__ __align__(16) char smraw[];
  const uint32_t smBase = smem_u32(smraw);
  const int tid = threadIdx.x, wid = tid >> 5, lane = tid & 31;
  const int wm = wid >> 2, wn = wid & 3;

  const int bid = blockIdx.x;
  const bool logits = bid < 528;
  int bm, bn;
  if (logits) {
    int rem = bid, bi = 0;
    while (rem >= 32 - bi) { rem -= 32 - bi; bi++; }
    bm = bi * 128; bn = (bi + rem) * 128;
  } else {
    int t = bid - 528;                     // 512 blocks: 32 m-tiles x 16 n-tiles
    int group = t >> 7;                    // 8-row supergroups
    int rem = t & 127;
    bm = (group * 8 + (rem & 7)) * 128;
    bn = (rem >> 3) * 128;
  }

  float acc[4][4][4];
#pragma unroll
  for (int i = 0; i < 4; i++)
#pragma unroll
    for (int j = 0; j < 4; j++)
#pragma unroll
      for (int v = 0; v < 4; v++) acc[i][j][v] = 0.f;

  const uint32_t aoff =
      (uint32_t)((wm * 64 + (lane & 15)) * RSTRIDE + (lane >> 4) * 16);
  const uint32_t boff =
      (uint32_t)((wn * 32 + (lane >> 4) * 8 + (lane & 7)) * RSTRIDE +
                 ((lane >> 3) & 1) * 16);

  if (logits) {
    GEMM_MAINLOOP_1P64(xhi, xhi, DD, DD, DD, bm, bn);
  } else {
    GEMM_MAINLOOP_1P64(xhi, wthi, DD, DD, DD, bm, bn);
  }

  float* st = (float*)smraw;
  ACC_TO_SMEM();
  __syncthreads();

  if (logits) {
#pragma unroll 4
    for (int s = 0; s < 64; s++) {
      int idx = s * 256 + tid;
      int rr = idx >> 7, cc = idx & 127;
      float v = st[rr * 129 + cc];
      int gm = bm + rr, gn = bn + cc;
      float av = adj[(size_t)gm * NN + gn];
      float e = s1[gm] + s2[gn];
      e = (e > 0.f) ? e : 0.1f * e;
      P[(size_t)gm * NN + gn] = (av * v > 0.f) ? e : -9.0e15f;
      if (fabsf(v) < DOT_THR) {
        int slot = atomicAdd(&g_cnt, 1);
        if (slot < MAX_FIX) g_list[slot] = (gm << 12) | gn;
      }
    }
    if (bm != bn) {
#pragma unroll 4
      for (int s = 0; s < 64; s++) {
        int idx = s * 256 + tid;
        int rr = idx >> 7, cc = idx & 127;
        float v = st[cc * 129 + rr];
        int gm = bn + rr, gn = bm + cc;
        float av = adj[(size_t)gm * NN + gn];
        float e = s1[gm] + s2[gn];
        e = (e > 0.f) ? e : 0.1f * e;
        P[(size_t)gm * NN + gn] = (av * v > 0.f) ? e : -9.0e15f;
        if (fabsf(v) < DOT_THR) {
          int slot = atomicAdd(&g_cnt, 1);
          if (slot < MAX_FIX) g_list[slot] = (gm << 12) | gn;
        }
      }
    }
  } else {
    // transposed write: h_t[n][m] fp16, coalesced along m
#pragma unroll 4
    for (int s = 0; s < 64; s++) {
      int idx = s * 256 + tid;
      int n = idx >> 7, m = idx & 127;
      hthi[(size_t)(bn + n) * NN + bm + m] = __float2half(st[m * 129 + n]);
    }
  }
}

// ================= out GEMM: out = elu(attention @ h), 1-pass BK64 ==========
__global__ __launch_bounds__(256, 2)
void gemm_out(const __half* __restrict__ phi, const __half* __restrict__ hthi,
              float* __restrict__ out) {
  extern __shared__ __align__(16) char smraw[];
  const uint32_t smBase = smem_u32(smraw);
  const int tid = threadIdx.x, wid = tid >> 5, lane = tid & 31;
  const int wm = wid >> 2, wn = wid & 3;

  const int t = blockIdx.x;
  const int group = t >> 7;
  const int rem = t & 127;
  const int bm = (group * 8 + (rem & 7)) * 128;
  const int bn = (rem >> 3) * 128;

  float acc[4][4][4];
#pragma unroll
  for (int i = 0; i < 4; i++)
#pragma unroll
    for (int j = 0; j < 4; j++)
#pragma unroll
      for (int v = 0; v < 4; v++) acc[i][j][v] = 0.f;

  const uint32_t aoff =
      (uint32_t)((wm * 64 + (lane & 15)) * RSTRIDE + (lane >> 4) * 16);
  const uint32_t boff =
      (uint32_t)((wn * 32 + (lane >> 4) * 8 + (lane & 7)) * RSTRIDE +
                 ((lane >> 3) & 1) * 16);

  GEMM_MAINLOOP_1P64(phi, hthi, NN, NN, NN, bm, bn);

  float* st = (float*)smraw;
  ACC_TO_SMEM();
  __syncthreads();

#pragma unroll 4
  for (int s = 0; s < 64; s++) {
    int idx = s * 256 + tid;
    int rr = idx >> 7, cc = idx & 127;
    float v = st[rr * 129 + cc];
    float o = (v > 0.f) ? v : expm1f(v);
    out[(size_t)(bm + rr) * DD + bn + cc] = o;
  }
}

// ================= fixup: exact fp32 dot for near-zero entries =============
__global__ __launch_bounds__(256) void fixup_kernel(
    const float* __restrict__ x, const float* __restrict__ adj,
    const float* __restrict__ s1, const float* __restrict__ s2,
    float* __restrict__ P) {
  const int n = min(g_cnt, MAX_FIX);
  const int warps = gridDim.x * (blockDim.x >> 5);
  const int w0 = blockIdx.x * (blockDim.x >> 5) + (threadIdx.x >> 5);
  const int lane = threadIdx.x & 31;
  for (int idx = w0; idx < n; idx += warps) {
    const int code = g_list[idx];
    const int i = code >> 12, j = code & 4095;
    const float4* xi = (const float4*)(x + (size_t)i * DD);
    const float4* xj = (const float4*)(x + (size_t)j * DD);
    float s = 0.f;
#pragma unroll 4
    for (int k = lane; k < DD / 4; k += 32) {
      float4 a = xi[k], b = xj[k];
      s = fmaf(a.x, b.x, s);
      s = fmaf(a.y, b.y, s);
      s = fmaf(a.z, b.z, s);
      s = fmaf(a.w, b.w, s);
    }
#pragma unroll
    for (int off = 16; off; off >>= 1) s += __shfl_xor_sync(0xffffffffu, s, off);
    if (lane == 0) {
      float av = adj[(size_t)i * NN + j];
      float e = s1[i] + s2[j];
      e = (e > 0.f) ? e : 0.1f * e;
      P[(size_t)i * NN + j] = (av * s > 0.f) ? e : -9.0e15f;
    }
  }
}

// ================= support kernels ==========================================
__global__ __launch_bounds__(256) void split_x(const float* __restrict__ x,
    __half* __restrict__ xhi) {
  size_t i = (size_t)blockIdx.x * 256 + threadIdx.x;
  xhi[i] = __float2half(x[i]);
  if (i == 0) g_cnt = 0;
}

__global__ __launch_bounds__(256) void trans_w(const float* __restrict__ W,
    __half* __restrict__ wthi) {
  __shared__ float t[32][33];
  const int bx = blockIdx.x * 32, by = blockIdx.y * 32;  // bx: n, by: k
  const int tx = threadIdx.x, ty = threadIdx.y;          // block (32,8)
#pragma unroll
  for (int rep = 0; rep < 4; rep++)
    t[ty + rep * 8][tx] = W[(size_t)(by + ty + rep * 8) * DD + bx + tx];
  __syncthreads();
#pragma unroll
  for (int rep = 0; rep < 4; rep++)
    wthi[(size_t)(bx + ty + rep * 8) * DD + by + tx] =
        __float2half(t[tx][ty + rep * 8]);
}

// rows x D fp32 GEMV, 2 RHS: o1 = M@v1, o2 = M@v2 (one warp per row)
__global__ __launch_bounds__(256) void gemv2(const float* __restrict__ M,
    const float* __restrict__ v1, const float* __restrict__ v2,
    float* __restrict__ o1, float* __restrict__ o2) {
  const int row = blockIdx.x * 8 + (threadIdx.x >> 5);
  const int lane = threadIdx.x & 31;
  const float4* mr = (const float4*)(M + (size_t)row * DD);
  const float4* a1 = (const float4*)v1;
  const float4* a2 = (const float4*)v2;
  float p1 = 0.f, p2 = 0.f;
#pragma unroll 4
  for (int k = lane; k < DD / 4; k += 32) {
    float4 m = mr[k], b1 = a1[k], b2 = a2[k];
    p1 = fmaf(m.x, b1.x, p1); p1 = fmaf(m.y, b1.y, p1);
    p1 = fmaf(m.z, b1.z, p1); p1 = fmaf(m.w, b1.w, p1);
    p2 = fmaf(m.x, b2.x, p2); p2 = fmaf(m.y, b2.y, p2);
    p2 = fmaf(m.z, b2.z, p2); p2 = fmaf(m.w, b2.w, p2);
  }
#pragma unroll
  for (int off = 16; off; off >>= 1) {
    p1 += __shfl_xor_sync(0xffffffffu, p1, off);
    p2 += __shfl_xor_sync(0xffffffffu, p2, off);
  }
  if (lane == 0) { o1[row] = p1; o2[row] = p2; }
}

__global__ __launch_bounds__(256) void softmax_rows(const float* __restrict__ P,
    __half* __restrict__ phi) {
  const int tid = threadIdx.x;
  const size_t rowbase = (size_t)blockIdx.x * NN;
  const float* pr = P + rowbase;
  __shared__ float red[256];

  float vals[16];
  float m = -INFINITY;
#pragma unroll
  for (int t = 0; t < 16; t++) {
    vals[t] = pr[tid + t * 256];
    m = fmaxf(m, vals[t]);
  }
  red[tid] = m;
  __syncthreads();
  for (int s = 128; s; s >>= 1) {
    if (tid < s) red[tid] = fmaxf(red[tid], red[tid + s]);
    __syncthreads();
  }
  m = red[0];
  __syncthreads();
  float sum = 0.f;
#pragma unroll
  for (int t = 0; t < 16; t++) {
    vals[t] = __expf(vals[t] - m);
    sum += vals[t];
  }
  red[tid] = sum;
  __syncthreads();
  for (int s = 128; s; s >>= 1) {
    if (tid < s) red[tid] += red[tid + s];
    __syncthreads();
  }
  const float inv = 1.f / red[0];
#pragma unroll
  for (int t = 0; t < 16; t++)
    phi[rowbase + tid + t * 256] = __float2half(vals[t] * inv);
}

// ================= launch ====================================================
extern "C" void kernel_launch(void* const* d_in, const int* in_sizes, int n_in,
                              void* d_out, int out_size) {
  const float* x   = (const float*)d_in[0];  // (4096, 2048)
  const float* adj = (const float*)d_in[1];  // (4096, 4096)
  const float* W   = (const float*)d_in[2];  // (2048, 2048)
  const float* a   = (const float*)d_in[3];  // (4096, 1)
  float* out = (float*)d_out;                // (4096, 2048)

  __half *xhi, *wthi, *hthi, *phi;
  float *P, *s1, *s2, *wa1, *wa2;
  cudaGetSymbolAddress((void**)&xhi,  g_xhi);
  cudaGetSymbolAddress((void**)&wthi, g_wthi);
  cudaGetSymbolAddress((void**)&hthi, g_hthi);
  cudaGetSymbolAddress((void**)&P,    g_P);
  cudaGetSymbolAddress((void**)&phi,  g_phi);
  cudaGetSymbolAddress((void**)&s1,   g_s1);
  cudaGetSymbolAddress((void**)&s2,   g_s2);
  cudaGetSymbolAddress((void**)&wa1,  g_wa1);
  cudaGetSymbolAddress((void**)&wa2,  g_wa2);

  cudaFuncSetAttribute(gemm_fused, cudaFuncAttributeMaxDynamicSharedMemorySize, SMEM_BYTES);
  cudaFuncSetAttribute(gemm_out,   cudaFuncAttributeMaxDynamicSharedMemorySize, SMEM_BYTES);

  // 1) x -> fp16; reset fixup counter
  split_x<<<(NN * DD) / 256, 256>>>(x, xhi);
  // 2) W -> W^T fp16
  trans_w<<<dim3(DD / 32, DD / 32), dim3(32, 8)>>>(W, wthi);
  // 3) wa = W@a; s = x@wa  (associativity: (xW)a = x(Wa), fp32 exact-ish)
  gemv2<<<DD / 8, 256>>>(W, a, a + DD, wa1, wa2);
  gemv2<<<NN / 8, 256>>>(x, wa1, wa2, s1, s2);
  // 4) fused: logits (triangular x@x^T + mask) AND h = x@W, both 1-pass BK64
  gemm_fused<<<528 + 512, 256, SMEM_BYTES>>>(
      xhi, wthi, adj, s1, s2, P, hthi);
  // 4b) exact fp32 recompute of near-zero dots
  fixup_kernel<<<1024, 256>>>(x, adj, s1, s2, P);
  // 5) row softmax -> attention fp16
  softmax_rows<<<NN, 256>>>(P, phi);
  // 6) out = elu(attention @ h), 1-pass BK64
  gemm_out<<<512, 256, SMEM_BYTES>>>(phi, hthi, out);
}

// round 10
// speedup vs baseline: 6.3317x; 1.0147x over previous
#include <cuda_runtime.h>
#include <cuda_fp16.h>
#include <math.h>
#include <stdint.h>

#define NN 4096   // nodes
#define DD 2048   // features
#define DOT_THR 0.15f
#define MAX_FIX (1 << 22)

// ================= scratch (__device__ globals; no allocs allowed) ==========
__device__ __half g_xhi[(size_t)NN * DD];     // 16 MB
__device__ __half g_wthi[(size_t)DD * DD];    // 8 MB   W^T fp16
__device__ __half g_hthi[(size_t)DD * NN];    // 16 MB  h^T fp16
__device__ uint32_t g_mask[(size_t)NN * NN / 32];  // 2 MB  attention mask bits
__device__ __half g_phi[(size_t)NN * NN];     // 32 MB  attention fp16
__device__ float g_s1[NN], g_s2[NN];
__device__ float g_wa1[DD], g_wa2[DD];
__device__ int g_cnt;                         // fixup worklist
__device__ int g_list[MAX_FIX];               // 16 MB

// ================= PTX helpers ==============================================
__device__ __forceinline__ uint32_t smem_u32(const void* p) {
  uint32_t a;
  asm("{ .reg .u64 t; cvta.to.shared.u64 t, %1; cvt.u32.u64 %0, t; }"
      : "=r"(a) : "l"(p));
  return a;
}
__device__ __forceinline__ void cp16(uint32_t dst, const void* src) {
  asm volatile("cp.async.cg.shared.global [%0], [%1], 16;" :: "r"(dst), "l"(src));
}
#define CP_COMMIT() asm volatile("cp.async.commit_group;" ::: "memory")
#define CP_WAIT1()  asm volatile("cp.async.wait_group 1;" ::: "memory")
#define CP_WAIT0()  asm volatile("cp.async.wait_group 0;" ::: "memory")

__device__ __forceinline__ void ldm4(uint32_t* r, uint32_t addr) {
  asm volatile("ldmatrix.sync.aligned.m8n8.x4.shared.b16 {%0,%1,%2,%3}, [%4];"
               : "=r"(r[0]), "=r"(r[1]), "=r"(r[2]), "=r"(r[3]) : "r"(addr));
}
__device__ __forceinline__ void mma_f16(float* d, const uint32_t* a,
                                        const uint32_t* b) {
  asm volatile(
      "mma.sync.aligned.m16n8k16.row.col.f32.f16.f16.f32 "
      "{%0,%1,%2,%3}, {%4,%5,%6,%7}, {%8,%9}, {%0,%1,%2,%3};"
      : "+f"(d[0]), "+f"(d[1]), "+f"(d[2]), "+f"(d[3])
      : "r"(a[0]), "r"(a[1]), "r"(a[2]), "r"(a[3]), "r"(b[0]), "r"(b[1]));
}

#define RSTRIDE 80                    // 40 fp16 per row: conflict-free ldmatrix
#define TILE_B  (128 * RSTRIDE)       // 10240 B per 128x32 operand tile
#define STAGE_B (4 * TILE_B)          // A0,A1,B0,B1 (BK=64 as 2 sub-chunks)
#define SMEM_BYTES (2 * STAGE_B)      // 81920

// ---- 1-pass fp16 mainloop, BK=64 (2 sub-chunks per stage) ------------------
#define GEMM_MAINLOOP_1P64(Ap, Bp, K, ldA, ldB, bm, bn)                         \
  {                                                                             \
    auto load64 = [&](int k0, int s) {                                          \
      const uint32_t stg = smBase + (uint32_t)s * STAGE_B;                      \
      _Pragma("unroll")                                                         \
      for (int it = 0; it < 2; it++) {                                          \
        int c = tid + it * 256;            /* 0..511 */                         \
        int row = c >> 2, chk = c & 3;     /* 4 x 16B per 64B sub-row */        \
        uint32_t so = row * RSTRIDE + chk * 16;                                 \
        const char* arow = (const char*)(Ap + (size_t)(bm + row) * ldA + k0);   \
        const char* brow = (const char*)(Bp + (size_t)(bn + row) * ldB + k0);   \
        cp16(stg + so,               arow + chk * 16);                          \
        cp16(stg + TILE_B + so,      arow + 64 + chk * 16);                     \
        cp16(stg + 2 * TILE_B + so,  brow + chk * 16);                          \
        cp16(stg + 3 * TILE_B + so,  brow + 64 + chk * 16);                     \
      }                                                                         \
      CP_COMMIT();                                                              \
    };                                                                          \
    const int nch = (K) / 64;                                                   \
    load64(0, 0);                                                               \
    load64(64, 1);                                                              \
    for (int i = 0; i < nch; i++) {                                             \
      if (i + 1 < nch) CP_WAIT1(); else CP_WAIT0();                             \
      __syncthreads();                                                          \
      const uint32_t stg = smBase + (uint32_t)(i & 1) * STAGE_B;                \
      _Pragma("unroll")                                                         \
      for (int sub = 0; sub < 2; sub++) {                                       \
        _Pragma("unroll")                                                       \
        for (int ks = 0; ks < 2; ks++) {                                        \
          const uint32_t kso = (uint32_t)(ks * 32);                             \
          uint32_t ah[4][4], bh[2][4];                                          \
          _Pragma("unroll")                                                     \
          for (int mi = 0; mi < 4; mi++)                                        \
            ldm4(ah[mi], stg + sub * TILE_B + aoff + kso + mi * 16 * RSTRIDE);  \
          _Pragma("unroll")                                                     \
          for (int nb = 0; nb < 2; nb++)                                        \
            ldm4(bh[nb],                                                        \
                 stg + (2 + sub) * TILE_B + boff + kso + nb * 16 * RSTRIDE);    \
          _Pragma("unroll")                                                     \
          for (int mi = 0; mi < 4; mi++)                                        \
            _Pragma("unroll")                                                   \
            for (int ni = 0; ni < 4; ni++)                                      \
              mma_f16(acc[mi][ni], ah[mi], &bh[ni >> 1][(ni & 1) * 2]);         \
        }                                                                       \
      }                                                                         \
      __syncthreads();                                                          \
      if (i + 2 < nch) load64((i + 2) * 64, i & 1);                             \
    }                                                                           \
  }

#define ACC_TO_SMEM()                                                           \
  {                                                                             \
    const int r0 = wm * 64 + (lane >> 2);                                       \
    const int c0 = wn * 32 + (lane & 3) * 2;                                    \
    _Pragma("unroll")                                                           \
    for (int mi = 0; mi < 4; mi++)                                              \
      _Pragma("unroll")                                                         \
      for (int ni = 0; ni < 4; ni++) {                                          \
        int r = r0 + mi * 16, c = c0 + ni * 8;                                  \
        st[r * 129 + c]           = acc[mi][ni][0];                             \
        st[r * 129 + c + 1]       = acc[mi][ni][1];                             \
        st[(r + 8) * 129 + c]     = acc[mi][ni][2];                             \
        st[(r + 8) * 129 + c + 1] = acc[mi][ni][3];                             \
      }                                                                         \
  }

// ================= fused GEMM: logits mask (528) + h (512), 1-pass BK64 =====
__global__ __launch_bounds__(256, 2)
void gemm_fused(const __half* __restrict__ xhi, const __half* __restrict__ wthi,
                const float* __restrict__ adj, uint32_t* __restrict__ mask,
                __half* __restrict__ hthi) {
  extern __shared__ __align__(16) char smraw[];
  const uint32_t smBase = smem_u32(smraw);
  const int tid = threadIdx.x, wid = tid >> 5, lane = tid & 31;
  const int wm = wid >> 2, wn = wid & 3;

  const int bid = blockIdx.x;
  const bool logits = bid < 528;
  int bm, bn;
  if (logits) {
    int rem = bid, bi = 0;
    while (rem >= 32 - bi) { rem -= 32 - bi; bi++; }
    bm = bi * 128; bn = (bi + rem) * 128;
  } else {
    int t = bid - 528;                     // 512 blocks: 32 m-tiles x 16 n-tiles
    int group = t >> 7;                    // 8-row supergroups
    int rem = t & 127;
    bm = (group * 8 + (rem & 7)) * 128;
    bn = (rem >> 3) * 128;
  }

  float acc[4][4][4];
#pragma unroll
  for (int i = 0; i < 4; i++)
#pragma unroll
    for (int j = 0; j < 4; j++)
#pragma unroll
      for (int v = 0; v < 4; v++) acc[i][j][v] = 0.f;

  const uint32_t aoff =
      (uint32_t)((wm * 64 + (lane & 15)) * RSTRIDE + (lane >> 4) * 16);
  const uint32_t boff =
      (uint32_t)((wn * 32 + (lane >> 4) * 8 + (lane & 7)) * RSTRIDE +
                 ((lane >> 3) & 1) * 16);

  if (logits) {
    GEMM_MAINLOOP_1P64(xhi, xhi, DD, DD, DD, bm, bn);
  } else {
    GEMM_MAINLOOP_1P64(xhi, wthi, DD, DD, DD, bm, bn);
  }

  float* st = (float*)smraw;
  ACC_TO_SMEM();
  __syncthreads();

  if (logits) {
    // build mask words: 128 rows x 4 words per tile (512 words, 2/thread)
#pragma unroll
    for (int s = 0; s < 2; s++) {
      int idx = s * 256 + tid;
      int rr = idx >> 2, wc = idx & 3;
      int gm = bm + rr;
      const float* arow = adj + (size_t)gm * NN + bn + wc * 32;
      uint32_t word = 0;
#pragma unroll 8
      for (int b = 0; b < 32; b++) {
        float v = st[rr * 129 + wc * 32 + b];
        if (arow[b] * v > 0.f) word |= (1u << b);
        if (fabsf(v) < DOT_THR) {
          int slot = atomicAdd(&g_cnt, 1);
          if (slot < MAX_FIX) g_list[slot] = (gm << 12) | (bn + wc * 32 + b);
        }
      }
      mask[(size_t)gm * 128 + (bn >> 5) + wc] = word;
    }
    if (bm != bn) {   // mirrored half: dot symmetric, transposed smem read
#pragma unroll
      for (int s = 0; s < 2; s++) {
        int idx = s * 256 + tid;
        int rr = idx >> 2, wc = idx & 3;
        int gm = bn + rr;
        const float* arow = adj + (size_t)gm * NN + bm + wc * 32;
        uint32_t word = 0;
#pragma unroll 8
        for (int b = 0; b < 32; b++) {
          float v = st[(wc * 32 + b) * 129 + rr];
          if (arow[b] * v > 0.f) word |= (1u << b);
          if (fabsf(v) < DOT_THR) {
            int slot = atomicAdd(&g_cnt, 1);
            if (slot < MAX_FIX) g_list[slot] = (gm << 12) | (bm + wc * 32 + b);
          }
        }
        mask[(size_t)gm * 128 + (bm >> 5) + wc] = word;
      }
    }
  } else {
    // transposed write: h_t[n][m] fp16, coalesced along m
#pragma unroll 4
    for (int s = 0; s < 64; s++) {
      int idx = s * 256 + tid;
      int n = idx >> 7, m = idx & 127;
      hthi[(size_t)(bn + n) * NN + bm + m] = __float2half(st[m * 129 + n]);
    }
  }
}

// ================= out GEMM: out = elu(attention @ h), 1-pass BK64 ==========
__global__ __launch_bounds__(256, 2)
void gemm_out(const __half* __restrict__ phi, const __half* __restrict__ hthi,
              float* __restrict__ out) {
  extern __shared__ __align__(16) char smraw[];
  const uint32_t smBase = smem_u32(smraw);
  const int tid = threadIdx.x, wid = tid >> 5, lane = tid & 31;
  const int wm = wid >> 2, wn = wid & 3;

  const int t = blockIdx.x;
  const int group = t >> 7;
  const int rem = t & 127;
  const int bm = (group * 8 + (rem & 7)) * 128;
  const int bn = (rem >> 3) * 128;

  float acc[4][4][4];
#pragma unroll
  for (int i = 0; i < 4; i++)
#pragma unroll
    for (int j = 0; j < 4; j++)
#pragma unroll
      for (int v = 0; v < 4; v++) acc[i][j][v] = 0.f;

  const uint32_t aoff =
      (uint32_t)((wm * 64 + (lane & 15)) * RSTRIDE + (lane >> 4) * 16);
  const uint32_t boff =
      (uint32_t)((wn * 32 + (lane >> 4) * 8 + (lane & 7)) * RSTRIDE +
                 ((lane >> 3) & 1) * 16);

  GEMM_MAINLOOP_1P64(phi, hthi, NN, NN, NN, bm, bn);

  float* st = (float*)smraw;
  ACC_TO_SMEM();
  __syncthreads();

#pragma unroll 4
  for (int s = 0; s < 64; s++) {
    int idx = s * 256 + tid;
    int rr = idx >> 7, cc = idx & 127;
    float v = st[rr * 129 + cc];
    float o = (v > 0.f) ? v : expm1f(v);
    out[(size_t)(bm + rr) * DD + bn + cc] = o;
  }
}

// ================= fixup: exact fp32 dot -> set/clear mask bit ==============
__global__ __launch_bounds__(256) void fixup_kernel(
    const float* __restrict__ x, const float* __restrict__ adj,
    uint32_t* __restrict__ mask) {
  const int n = min(g_cnt, MAX_FIX);
  const int warps = gridDim.x * (blockDim.x >> 5);
  const int w0 = blockIdx.x * (blockDim.x >> 5) + (threadIdx.x >> 5);
  const int lane = threadIdx.x & 31;
  for (int idx = w0; idx < n; idx += warps) {
    const int code = g_list[idx];
    const int i = code >> 12, j = code & 4095;
    const float4* xi = (const float4*)(x + (size_t)i * DD);
    const float4* xj = (const float4*)(x + (size_t)j * DD);
    float s = 0.f;
#pragma unroll 4
    for (int k = lane; k < DD / 4; k += 32) {
      float4 a = xi[k], b = xj[k];
      s = fmaf(a.x, b.x, s);
      s = fmaf(a.y, b.y, s);
      s = fmaf(a.z, b.z, s);
      s = fmaf(a.w, b.w, s);
    }
#pragma unroll
    for (int off = 16; off; off >>= 1) s += __shfl_xor_sync(0xffffffffu, s, off);
    if (lane == 0) {
      float av = adj[(size_t)i * NN + j];
      uint32_t* w = &mask[(size_t)i * 128 + (j >> 5)];
      uint32_t bit = 1u << (j & 31);
      if (av * s > 0.f) atomicOr(w, bit);
      else              atomicAnd(w, ~bit);
    }
  }
}

// ================= support kernels ==========================================
// per-row: x -> fp16, and s1 = x@wa1, s2 = x@wa2 (fused, single x pass)
__global__ __launch_bounds__(256) void split_s(const float* __restrict__ x,
    const float* __restrict__ wa1, const float* __restrict__ wa2,
    __half* __restrict__ xhi, float* __restrict__ s1, float* __restrict__ s2) {
  const int row = blockIdx.x;
  const int tid = threadIdx.x;
  const float4* xr = (const float4*)(x + (size_t)row * DD);
  const float4* a1 = (const float4*)wa1;
  const float4* a2 = (const float4*)wa2;
  float p1 = 0.f, p2 = 0.f;
#pragma unroll
  for (int t = 0; t < 2; t++) {
    int k = tid + t * 256;            // float4 index, 0..511
    float4 v = xr[k], b1 = a1[k], b2 = a2[k];
    p1 = fmaf(v.x, b1.x, p1); p1 = fmaf(v.y, b1.y, p1);
    p1 = fmaf(v.z, b1.z, p1); p1 = fmaf(v.w, b1.w, p1);
    p2 = fmaf(v.x, b2.x, p2); p2 = fmaf(v.y, b2.y, p2);
    p2 = fmaf(v.z, b2.z, p2); p2 = fmaf(v.w, b2.w, p2);
    __half2 h0 = __floats2half2_rn(v.x, v.y);
    __half2 h1 = __floats2half2_rn(v.z, v.w);
    *(__half2*)(xhi + (size_t)row * DD + k * 4)     = h0;
    *(__half2*)(xhi + (size_t)row * DD + k * 4 + 2) = h1;
  }
#pragma unroll
  for (int off = 16; off; off >>= 1) {
    p1 += __shfl_xor_sync(0xffffffffu, p1, off);
    p2 += __shfl_xor_sync(0xffffffffu, p2, off);
  }
  __shared__ float r1[8], r2[8];
  const int warp = tid >> 5, lane = tid & 31;
  if (lane == 0) { r1[warp] = p1; r2[warp] = p2; }
  __syncthreads();
  if (tid == 0) {
    float t1 = 0.f, t2 = 0.f;
#pragma unroll
    for (int w = 0; w < 8; w++) { t1 += r1[w]; t2 += r2[w]; }
    s1[row] = t1;
    s2[row] = t2;
    if (row == 0) g_cnt = 0;
  }
}

__global__ __launch_bounds__(256) void trans_w(const float* __restrict__ W,
    __half* __restrict__ wthi) {
  __shared__ float t[32][33];
  const int bx = blockIdx.x * 32, by = blockIdx.y * 32;  // bx: n, by: k
  const int tx = threadIdx.x, ty = threadIdx.y;          // block (32,8)
#pragma unroll
  for (int rep = 0; rep < 4; rep++)
    t[ty + rep * 8][tx] = W[(size_t)(by + ty + rep * 8) * DD + bx + tx];
  __syncthreads();
#pragma unroll
  for (int rep = 0; rep < 4; rep++)
    wthi[(size_t)(bx + ty + rep * 8) * DD + by + tx] =
        __float2half(t[tx][ty + rep * 8]);
}

// rows x D fp32 GEMV, 2 RHS: o1 = M@v1, o2 = M@v2 (one warp per row)
__global__ __launch_bounds__(256) void gemv2(const float* __restrict__ M,
    const float* __restrict__ v1, const float* __restrict__ v2,
    float* __restrict__ o1, float* __restrict__ o2) {
  const int row = blockIdx.x * 8 + (threadIdx.x >> 5);
  const int lane = threadIdx.x & 31;
  const float4* mr = (const float4*)(M + (size_t)row * DD);
  const float4* a1 = (const float4*)v1;
  const float4* a2 = (const float4*)v2;
  float p1 = 0.f, p2 = 0.f;
#pragma unroll 4
  for (int k = lane; k < DD / 4; k += 32) {
    float4 m = mr[k], b1 = a1[k], b2 = a2[k];
    p1 = fmaf(m.x, b1.x, p1); p1 = fmaf(m.y, b1.y, p1);
    p1 = fmaf(m.z, b1.z, p1); p1 = fmaf(m.w, b1.w, p1);
    p2 = fmaf(m.x, b2.x, p2); p2 = fmaf(m.y, b2.y, p2);
    p2 = fmaf(m.z, b2.z, p2); p2 = fmaf(m.w, b2.w, p2);
  }
#pragma unroll
  for (int off = 16; off; off >>= 1) {
    p1 += __shfl_xor_sync(0xffffffffu, p1, off);
    p2 += __shfl_xor_sync(0xffffffffu, p2, off);
  }
  if (lane == 0) { o1[row] = p1; o2[row] = p2; }
}

// softmax from mask bits: e = leaky(s1[i]+s2[j]) recomputed on the fly
__global__ __launch_bounds__(256) void softmax_rows(
    const uint32_t* __restrict__ mask, const float* __restrict__ s1,
    const float* __restrict__ s2, __half* __restrict__ phi) {
  const int tid = threadIdx.x;
  const int row = blockIdx.x;
  __shared__ uint32_t mw[128];
  __shared__ float red[256];
  if (tid < 128) mw[tid] = mask[(size_t)row * 128 + tid];
  __syncthreads();
  const float s1i = s1[row];

  float vals[16];
  bool mk[16];
  float m = -INFINITY;
#pragma unroll
  for (int t = 0; t < 16; t++) {
    int j = tid + t * 256;
    bool b = (mw[j >> 5] >> (j & 31)) & 1u;
    float e = s1i + s2[j];
    e = (e > 0.f) ? e : 0.1f * e;
    mk[t] = b; vals[t] = e;
    if (b) m = fmaxf(m, e);
  }
  red[tid] = m;
  __syncthreads();
  for (int s = 128; s; s >>= 1) {
    if (tid < s) red[tid] = fmaxf(red[tid], red[tid + s]);
    __syncthreads();
  }
  m = red[0];
  __syncthreads();
  float sum = 0.f;
#pragma unroll
  for (int t = 0; t < 16; t++) {
    float ev = mk[t] ? __expf(vals[t] - m) : 0.f;
    vals[t] = ev;
    sum += ev;
  }
  red[tid] = sum;
  __syncthreads();
  for (int s = 128; s; s >>= 1) {
    if (tid < s) red[tid] += red[tid + s];
    __syncthreads();
  }
  const float tot = red[0];
  const float inv = (tot > 0.f) ? 1.f / tot : 0.f;
  const float uni = 1.f / (float)NN;
#pragma unroll
  for (int t = 0; t < 16; t++) {
    float att = (tot > 0.f) ? vals[t] * inv : uni;
    phi[(size_t)row * NN + tid + t * 256] = __float2half(att);
  }
}

// ================= launch ====================================================
extern "C" void kernel_launch(void* const* d_in, const int* in_sizes, int n_in,
                              void* d_out, int out_size) {
  const float* x   = (const float*)d_in[0];  // (4096, 2048)
  const float* adj = (const float*)d_in[1];  // (4096, 4096)
  const float* W   = (const float*)d_in[2];  // (2048, 2048)
  const float* a   = (const float*)d_in[3];  // (4096, 1)
  float* out = (float*)d_out;                // (4096, 2048)

  __half *xhi, *wthi, *hthi, *phi;
  uint32_t* mask;
  float *s1, *s2, *wa1, *wa2;
  cudaGetSymbolAddress((void**)&xhi,  g_xhi);
  cudaGetSymbolAddress((void**)&wthi, g_wthi);
  cudaGetSymbolAddress((void**)&hthi, g_hthi);
  cudaGetSymbolAddress((void**)&mask, g_mask);
  cudaGetSymbolAddress((void**)&phi,  g_phi);
  cudaGetSymbolAddress((void**)&s1,   g_s1);
  cudaGetSymbolAddress((void**)&s2,   g_s2);
  cudaGetSymbolAddress((void**)&wa1,  g_wa1);
  cudaGetSymbolAddress((void**)&wa2,  g_wa2);

  cudaFuncSetAttribute(gemm_fused, cudaFuncAttributeMaxDynamicSharedMemorySize, SMEM_BYTES);
  cudaFuncSetAttribute(gemm_out,   cudaFuncAttributeMaxDynamicSharedMemorySize, SMEM_BYTES);

  // 1) W -> W^T fp16
  trans_w<<<dim3(DD / 32, DD / 32), dim3(32, 8)>>>(W, wthi);
  // 2) wa = W@a
  gemv2<<<DD / 8, 256>>>(W, a, a + DD, wa1, wa2);
  // 3) x -> fp16 AND s1 = x@wa1, s2 = x@wa2 (fused single pass over x)
  split_s<<<NN, 256>>>(x, wa1, wa2, xhi, s1, s2);
  // 4) fused: logits -> mask bits (triangular x@x^T) AND h = x@W
  gemm_fused<<<528 + 512, 256, SMEM_BYTES>>>(xhi, wthi, adj, mask, hthi);
  // 4b) exact fp32 recompute of near-zero dots -> fix mask bits
  fixup_kernel<<<1024, 256>>>(x, adj, mask);
  // 5) softmax from mask + s1/s2 -> attention fp16
  softmax_rows<<<NN, 256>>>(mask, s1, s2, phi);
  // 6) out = elu(attention @ h), 1-pass BK64
  gemm_out<<<512, 256, SMEM_BYTES>>>(phi, hthi, out);
}

// round 11
// speedup vs baseline: 6.4751x; 1.0226x over previous
#include <cuda_runtime.h>
#include <cuda_fp16.h>
#include <math.h>
#include <stdint.h>

#define NN 4096   // nodes
#define DD 2048   // features
#define DOT_THR 0.15f
#define MAX_FIX (1 << 22)

// ================= scratch (__device__ globals; no allocs allowed) ==========
__device__ __half g_xhi[(size_t)NN * DD];     // 16 MB
__device__ __half g_wthi[(size_t)DD * DD];    // 8 MB   W^T fp16
__device__ __half g_hthi[(size_t)DD * NN];    // 16 MB  h^T fp16
__device__ uint32_t g_mask[(size_t)NN * NN / 32];  // 2 MB  attention mask bits
__device__ __half g_phi[(size_t)NN * NN];     // 32 MB  attention fp16
__device__ float g_s1[NN], g_s2[NN];
__device__ float g_wa1[DD], g_wa2[DD];
__device__ int g_cnt;                         // fixup worklist
__device__ int g_list[MAX_FIX];               // 16 MB

// ================= PTX helpers ==============================================
__device__ __forceinline__ uint32_t smem_u32(const void* p) {
  uint32_t a;
  asm("{ .reg .u64 t; cvta.to.shared.u64 t, %1; cvt.u32.u64 %0, t; }"
      : "=r"(a) : "l"(p));
  return a;
}
__device__ __forceinline__ void cp16(uint32_t dst, const void* src) {
  asm volatile("cp.async.cg.shared.global [%0], [%1], 16;" :: "r"(dst), "l"(src));
}
#define CP_COMMIT() asm volatile("cp.async.commit_group;" ::: "memory")
#define CP_WAIT2()  asm volatile("cp.async.wait_group 2;" ::: "memory")

__device__ __forceinline__ void ldm4(uint32_t* r, uint32_t addr) {
  asm volatile("ldmatrix.sync.aligned.m8n8.x4.shared.b16 {%0,%1,%2,%3}, [%4];"
               : "=r"(r[0]), "=r"(r[1]), "=r"(r[2]), "=r"(r[3]) : "r"(addr));
}
__device__ __forceinline__ void mma_f16(float* d, const uint32_t* a,
                                        const uint32_t* b) {
  asm volatile(
      "mma.sync.aligned.m16n8k16.row.col.f32.f16.f16.f32 "
      "{%0,%1,%2,%3}, {%4,%5,%6,%7}, {%8,%9}, {%0,%1,%2,%3};"
      : "+f"(d[0]), "+f"(d[1]), "+f"(d[2]), "+f"(d[3])
      : "r"(a[0]), "r"(a[1]), "r"(a[2]), "r"(a[3]), "r"(b[0]), "r"(b[1]));
}

#define RSTRIDE 80                    // 40 fp16 per row: conflict-free ldmatrix
#define TILE_B  (128 * RSTRIDE)       // 10240 B per 128x32 operand tile
#define STAGE_B (2 * TILE_B)          // A, B per stage (BK=32)
#define NSTAGE  4
#define SMEM_BYTES (NSTAGE * STAGE_B) // 81920

// ---- 1-pass fp16 mainloop, BK=32, 4-stage, single sync per iteration -------
// At the wait of iteration i, commit_groups issued = 3 + i (prologue 3 + one
// per prior iteration, empty-tail groups included), so wait_group(2) ensures
// stage i is complete. Prefetch into slot (i+3)&3 == (i-1)&3, whose compute
// finished before this iteration's barrier.
#define GEMM_MAINLOOP_1P(Ap, Bp, K, ldA, ldB, bm, bn)                           \
  {                                                                             \
    auto load32 = [&](int ci, int s) {                                          \
      const uint32_t stg = smBase + (uint32_t)s * STAGE_B;                      \
      const int k0 = ci * 32;                                                   \
      _Pragma("unroll")                                                         \
      for (int it = 0; it < 2; it++) {                                          \
        int c = tid + it * 256;            /* 0..511 */                         \
        int row = c >> 2, chk = c & 3;     /* 4 x 16B per 64B row */            \
        uint32_t so = row * RSTRIDE + chk * 16;                                 \
        cp16(stg + so,                                                          \
             (const char*)(Ap + (size_t)(bm + row) * ldA + k0) + chk * 16);     \
        cp16(stg + TILE_B + so,                                                 \
             (const char*)(Bp + (size_t)(bn + row) * ldB + k0) + chk * 16);     \
      }                                                                         \
      CP_COMMIT();                                                              \
    };                                                                          \
    const int nch = (K) / 32;                                                   \
    load32(0, 0);                                                               \
    load32(1, 1);                                                               \
    load32(2, 2);                                                               \
    for (int i = 0; i < nch; i++) {                                             \
      CP_WAIT2();                                                               \
      __syncthreads();                                                          \
      if (i + 3 < nch) load32(i + 3, (i + 3) & 3);                              \
      else             CP_COMMIT();   /* keep group arithmetic exact */         \
      const uint32_t stg = smBase + (uint32_t)(i & 3) * STAGE_B;                \
      _Pragma("unroll")                                                         \
      for (int ks = 0; ks < 2; ks++) {                                          \
        const uint32_t kso = (uint32_t)(ks * 32);                               \
        uint32_t ah[4][4], bh[2][4];                                            \
        _Pragma("unroll")                                                       \
        for (int mi = 0; mi < 4; mi++)                                          \
          ldm4(ah[mi], stg + aoff + kso + mi * 16 * RSTRIDE);                   \
        _Pragma("unroll")                                                       \
        for (int nb = 0; nb < 2; nb++)                                          \
          ldm4(bh[nb], stg + TILE_B + boff + kso + nb * 16 * RSTRIDE);          \
        _Pragma("unroll")                                                       \
        for (int mi = 0; mi < 4; mi++)                                          \
          _Pragma("unroll")                                                     \
          for (int ni = 0; ni < 4; ni++)                                        \
            mma_f16(acc[mi][ni], ah[mi], &bh[ni >> 1][(ni & 1) * 2]);           \
      }                                                                         \
    }                                                                           \
    __syncthreads();   /* protect smem reuse by epilogue staging */             \
  }

#define ACC_TO_SMEM()                                                           \
  {                                                                             \
    const int r0 = wm * 64 + (lane >> 2);                                       \
    const int c0 = wn * 32 + (lane & 3) * 2;                                    \
    _Pragma("unroll")                                                           \
    for (int mi = 0; mi < 4; mi++)                                              \
      _Pragma("unroll")                                                         \
      for (int ni = 0; ni < 4; ni++) {                                          \
        int r = r0 + mi * 16, c = c0 + ni * 8;                                  \
        st[r * 129 + c]           = acc[mi][ni][0];                             \
        st[r * 129 + c + 1]       = acc[mi][ni][1];                             \
        st[(r + 8) * 129 + c]     = acc[mi][ni][2];                             \
        st[(r + 8) * 129 + c + 1] = acc[mi][ni][3];                             \
      }                                                                         \
  }

// ================= fused GEMM: logits mask (528) + h (512) ==================
__global__ __launch_bounds__(256, 2)
void gemm_fused(const __half* __restrict__ xhi, const __half* __restrict__ wthi,
                const float* __restrict__ adj, uint32_t* __restrict__ mask,
                __half* __restrict__ hthi) {
  extern __shared__ __align__(16) char smraw[];
  const uint32_t smBase = smem_u32(smraw);
  const int tid = threadIdx.x, wid = tid >> 5, lane = tid & 31;
  const int wm = wid >> 2, wn = wid & 3;

  const int bid = blockIdx.x;
  const bool logits = bid < 528;
  int bm, bn;
  if (logits) {
    int rem = bid, bi = 0;
    while (rem >= 32 - bi) { rem -= 32 - bi; bi++; }
    bm = bi * 128; bn = (bi + rem) * 128;
  } else {
    int t = bid - 528;                     // 512 blocks: 32 m-tiles x 16 n-tiles
    int group = t >> 7;                    // 8-row supergroups
    int rem = t & 127;
    bm = (group * 8 + (rem & 7)) * 128;
    bn = (rem >> 3) * 128;
  }

  float acc[4][4][4];
#pragma unroll
  for (int i = 0; i < 4; i++)
#pragma unroll
    for (int j = 0; j < 4; j++)
#pragma unroll
      for (int v = 0; v < 4; v++) acc[i][j][v] = 0.f;

  const uint32_t aoff =
      (uint32_t)((wm * 64 + (lane & 15)) * RSTRIDE + (lane >> 4) * 16);
  const uint32_t boff =
      (uint32_t)((wn * 32 + (lane >> 4) * 8 + (lane & 7)) * RSTRIDE +
                 ((lane >> 3) & 1) * 16);

  if (logits) {
    GEMM_MAINLOOP_1P(xhi, xhi, DD, DD, DD, bm, bn);
  } else {
    GEMM_MAINLOOP_1P(xhi, wthi, DD, DD, DD, bm, bn);
  }

  float* st = (float*)smraw;
  ACC_TO_SMEM();
  __syncthreads();

  if (logits) {
    // build mask words: 128 rows x 4 words per tile (512 words, 2/thread)
#pragma unroll
    for (int s = 0; s < 2; s++) {
      int idx = s * 256 + tid;
      int rr = idx >> 2, wc = idx & 3;
      int gm = bm + rr;
      const float* arow = adj + (size_t)gm * NN + bn + wc * 32;
      uint32_t word = 0;
#pragma unroll 8
      for (int b = 0; b < 32; b++) {
        float v = st[rr * 129 + wc * 32 + b];
        if (arow[b] * v > 0.f) word |= (1u << b);
        if (fabsf(v) < DOT_THR) {
          int slot = atomicAdd(&g_cnt, 1);
          if (slot < MAX_FIX) g_list[slot] = (gm << 12) | (bn + wc * 32 + b);
        }
      }
      mask[(size_t)gm * 128 + (bn >> 5) + wc] = word;
    }
    if (bm != bn) {   // mirrored half: dot symmetric, transposed smem read
#pragma unroll
      for (int s = 0; s < 2; s++) {
        int idx = s * 256 + tid;
        int rr = idx >> 2, wc = idx & 3;
        int gm = bn + rr;
        const float* arow = adj + (size_t)gm * NN + bm + wc * 32;
        uint32_t word = 0;
#pragma unroll 8
        for (int b = 0; b < 32; b++) {
          float v = st[(wc * 32 + b) * 129 + rr];
          if (arow[b] * v > 0.f) word |= (1u << b);
          if (fabsf(v) < DOT_THR) {
            int slot = atomicAdd(&g_cnt, 1);
            if (slot < MAX_FIX) g_list[slot] = (gm << 12) | (bm + wc * 32 + b);
          }
        }
        mask[(size_t)gm * 128 + (bm >> 5) + wc] = word;
      }
    }
  } else {
    // transposed write: h_t[n][m] fp16, coalesced along m
#pragma unroll 4
    for (int s = 0; s < 64; s++) {
      int idx = s * 256 + tid;
      int n = idx >> 7, m = idx & 127;
      hthi[(size_t)(bn + n) * NN + bm + m] = __float2half(st[m * 129 + n]);
    }
  }
}

// ================= out GEMM: out = elu(attention @ h) =======================
__global__ __launch_bounds__(256, 2)
void gemm_out(const __half* __restrict__ phi, const __half* __restrict__ hthi,
              float* __restrict__ out) {
  extern __shared__ __align__(16) char smraw[];
  const uint32_t smBase = smem_u32(smraw);
  const int tid = threadIdx.x, wid = tid >> 5, lane = tid & 31;
  const int wm = wid >> 2, wn = wid & 3;

  const int t = blockIdx.x;
  const int group = t >> 7;
  const int rem = t & 127;
  const int bm = (group * 8 + (rem & 7)) * 128;
  const int bn = (rem >> 3) * 128;

  float acc[4][4][4];
#pragma unroll
  for (int i = 0; i < 4; i++)
#pragma unroll
    for (int j = 0; j < 4; j++)
#pragma unroll
      for (int v = 0; v < 4; v++) acc[i][j][v] = 0.f;

  const uint32_t aoff =
      (uint32_t)((wm * 64 + (lane & 15)) * RSTRIDE + (lane >> 4) * 16);
  const uint32_t boff =
      (uint32_t)((wn * 32 + (lane >> 4) * 8 + (lane & 7)) * RSTRIDE +
                 ((lane >> 3) & 1) * 16);

  GEMM_MAINLOOP_1P(phi, hthi, NN, NN, NN, bm, bn);

  float* st = (float*)smraw;
  ACC_TO_SMEM();
  __syncthreads();

#pragma unroll 4
  for (int s = 0; s < 64; s++) {
    int idx = s * 256 + tid;
    int rr = idx >> 7, cc = idx & 127;
    float v = st[rr * 129 + cc];
    float o = (v > 0.f) ? v : expm1f(v);
    out[(size_t)(bm + rr) * DD + bn + cc] = o;
  }
}

// ================= fixup: exact fp32 dot -> set/clear mask bit ==============
__global__ __launch_bounds__(256) void fixup_kernel(
    const float* __restrict__ x, const float* __restrict__ adj,
    uint32_t* __restrict__ mask) {
  const int n = min(g_cnt, MAX_FIX);
  const int warps = gridDim.x * (blockDim.x >> 5);
  const int w0 = blockIdx.x * (blockDim.x >> 5) + (threadIdx.x >> 5);
  const int lane = threadIdx.x & 31;
  for (int idx = w0; idx < n; idx += warps) {
    const int code = g_list[idx];
    const int i = code >> 12, j = code & 4095;
    const float4* xi = (const float4*)(x + (size_t)i * DD);
    const float4* xj = (const float4*)(x + (size_t)j * DD);
    float s = 0.f;
#pragma unroll 4
    for (int k = lane; k < DD / 4; k += 32) {
      float4 a = xi[k], b = xj[k];
      s = fmaf(a.x, b.x, s);
      s = fmaf(a.y, b.y, s);
      s = fmaf(a.z, b.z, s);
      s = fmaf(a.w, b.w, s);
    }
#pragma unroll
    for (int off = 16; off; off >>= 1) s += __shfl_xor_sync(0xffffffffu, s, off);
    if (lane == 0) {
      float av = adj[(size_t)i * NN + j];
      uint32_t* w = &mask[(size_t)i * 128 + (j >> 5)];
      uint32_t bit = 1u << (j & 31);
      if (av * s > 0.f) atomicOr(w, bit);
      else              atomicAnd(w, ~bit);
    }
  }
}

// ================= support kernels ==========================================
// per-row: x -> fp16, and s1 = x@wa1, s2 = x@wa2 (fused, single x pass)
__global__ __launch_bounds__(256) void split_s(const float* __restrict__ x,
    const float* __restrict__ wa1, const float* __restrict__ wa2,
    __half* __restrict__ xhi, float* __restrict__ s1, float* __restrict__ s2) {
  const int row = blockIdx.x;
  const int tid = threadIdx.x;
  const float4* xr = (const float4*)(x + (size_t)row * DD);
  const float4* a1 = (const float4*)wa1;
  const float4* a2 = (const float4*)wa2;
  float p1 = 0.f, p2 = 0.f;
#pragma unroll
  for (int t = 0; t < 2; t++) {
    int k = tid + t * 256;            // float4 index, 0..511
    float4 v = xr[k], b1 = a1[k], b2 = a2[k];
    p1 = fmaf(v.x, b1.x, p1); p1 = fmaf(v.y, b1.y, p1);
    p1 = fmaf(v.z, b1.z, p1); p1 = fmaf(v.w, b1.w, p1);
    p2 = fmaf(v.x, b2.x, p2); p2 = fmaf(v.y, b2.y, p2);
    p2 = fmaf(v.z, b2.z, p2); p2 = fmaf(v.w, b2.w, p2);
    __half2 h0 = __floats2half2_rn(v.x, v.y);
    __half2 h1 = __floats2half2_rn(v.z, v.w);
    *(__half2*)(xhi + (size_t)row * DD + k * 4)     = h0;
    *(__half2*)(xhi + (size_t)row * DD + k * 4 + 2) = h1;
  }
#pragma unroll
  for (int off = 16; off; off >>= 1) {
    p1 += __shfl_xor_sync(0xffffffffu, p1, off);
    p2 += __shfl_xor_sync(0xffffffffu, p2, off);
  }
  __shared__ float r1[8], r2[8];
  const int warp = tid >> 5, lane = tid & 31;
  if (lane == 0) { r1[warp] = p1; r2[warp] = p2; }
  __syncthreads();
  if (tid == 0) {
    float t1 = 0.f, t2 = 0.f;
#pragma unroll
    for (int w = 0; w < 8; w++) { t1 += r1[w]; t2 += r2[w]; }
    s1[row] = t1;
    s2[row] = t2;
    if (row == 0) g_cnt = 0;
  }
}

__global__ __launch_bounds__(256) void trans_w(const float* __restrict__ W,
    __half* __restrict__ wthi) {
  __shared__ float t[32][33];
  const int bx = blockIdx.x * 32, by = blockIdx.y * 32;  // bx: n, by: k
  const int tx = threadIdx.x, ty = threadIdx.y;          // block (32,8)
#pragma unroll
  for (int rep = 0; rep < 4; rep++)
    t[ty + rep * 8][tx] = W[(size_t)(by + ty + rep * 8) * DD + bx + tx];
  __syncthreads();
#pragma unroll
  for (int rep = 0; rep < 4; rep++)
    wthi[(size_t)(bx + ty + rep * 8) * DD + by + tx] =
        __float2half(t[tx][ty + rep * 8]);
}

// rows x D fp32 GEMV, 2 RHS: o1 = M@v1, o2 = M@v2 (one warp per row)
__global__ __launch_bounds__(256) void gemv2(const float* __restrict__ M,
    const float* __restrict__ v1, const float* __restrict__ v2,
    float* __restrict__ o1, float* __restrict__ o2) {
  const int row = blockIdx.x * 8 + (threadIdx.x >> 5);
  const int lane = threadIdx.x & 31;
  const float4* mr = (const float4*)(M + (size_t)row * DD);
  const float4* a1 = (const float4*)v1;
  const float4* a2 = (const float4*)v2;
  float p1 = 0.f, p2 = 0.f;
#pragma unroll 4
  for (int k = lane; k < DD / 4; k += 32) {
    float4 m = mr[k], b1 = a1[k], b2 = a2[k];
    p1 = fmaf(m.x, b1.x, p1); p1 = fmaf(m.y, b1.y, p1);
    p1 = fmaf(m.z, b1.z, p1); p1 = fmaf(m.w, b1.w, p1);
    p2 = fmaf(m.x, b2.x, p2); p2 = fmaf(m.y, b2.y, p2);
    p2 = fmaf(m.z, b2.z, p2); p2 = fmaf(m.w, b2.w, p2);
  }
#pragma unroll
  for (int off = 16; off; off >>= 1) {
    p1 += __shfl_xor_sync(0xffffffffu, p1, off);
    p2 += __shfl_xor_sync(0xffffffffu, p2, off);
  }
  if (lane == 0) { o1[row] = p1; o2[row] = p2; }
}

// softmax from mask bits: e = leaky(s1[i]+s2[j]) recomputed on the fly
__global__ __launch_bounds__(256) void softmax_rows(
    const uint32_t* __restrict__ mask, const float* __restrict__ s1,
    const float* __restrict__ s2, __half* __restrict__ phi) {
  const int tid = threadIdx.x;
  const int row = blockIdx.x;
  __shared__ uint32_t mw[128];
  __shared__ float red[256];
  if (tid < 128) mw[tid] = mask[(size_t)row * 128 + tid];
  __syncthreads();
  const float s1i = s1[row];

  float vals[16];
  bool mk[16];
  float m = -INFINITY;
#pragma unroll
  for (int t = 0; t < 16; t++) {
    int j = tid + t * 256;
    bool b = (mw[j >> 5] >> (j & 31)) & 1u;
    float e = s1i + s2[j];
    e = (e > 0.f) ? e : 0.1f * e;
    mk[t] = b; vals[t] = e;
    if (b) m = fmaxf(m, e);
  }
  red[tid] = m;
  __syncthreads();
  for (int s = 128; s; s >>= 1) {
    if (tid < s) red[tid] = fmaxf(red[tid], red[tid + s]);
    __syncthreads();
  }
  m = red[0];
  __syncthreads();
  float sum = 0.f;
#pragma unroll
  for (int t = 0; t < 16; t++) {
    float ev = mk[t] ? __expf(vals[t] - m) : 0.f;
    vals[t] = ev;
    sum += ev;
  }
  red[tid] = sum;
  __syncthreads();
  for (int s = 128; s; s >>= 1) {
    if (tid < s) red[tid] += red[tid + s];
    __syncthreads();
  }
  const float tot = red[0];
  const float inv = (tot > 0.f) ? 1.f / tot : 0.f;
  const float uni = 1.f / (float)NN;
#pragma unroll
  for (int t = 0; t < 16; t++) {
    float att = (tot > 0.f) ? vals[t] * inv : uni;
    phi[(size_t)row * NN + tid + t * 256] = __float2half(att);
  }
}

// ================= launch ====================================================
extern "C" void kernel_launch(void* const* d_in, const int* in_sizes, int n_in,
                              void* d_out, int out_size) {
  const float* x   = (const float*)d_in[0];  // (4096, 2048)
  const float* adj = (const float*)d_in[1];  // (4096, 4096)
  const float* W   = (const float*)d_in[2];  // (2048, 2048)
  const float* a   = (const float*)d_in[3];  // (4096, 1)
  float* out = (float*)d_out;                // (4096, 2048)

  __half *xhi, *wthi, *hthi, *phi;
  uint32_t* mask;
  float *s1, *s2, *wa1, *wa2;
  cudaGetSymbolAddress((void**)&xhi,  g_xhi);
  cudaGetSymbolAddress((void**)&wthi, g_wthi);
  cudaGetSymbolAddress((void**)&hthi, g_hthi);
  cudaGetSymbolAddress((void**)&mask, g_mask);
  cudaGetSymbolAddress((void**)&phi,  g_phi);
  cudaGetSymbolAddress((void**)&s1,   g_s1);
  cudaGetSymbolAddress((void**)&s2,   g_s2);
  cudaGetSymbolAddress((void**)&wa1,  g_wa1);
  cudaGetSymbolAddress((void**)&wa2,  g_wa2);

  cudaFuncSetAttribute(gemm_fused, cudaFuncAttributeMaxDynamicSharedMemorySize, SMEM_BYTES);
  cudaFuncSetAttribute(gemm_out,   cudaFuncAttributeMaxDynamicSharedMemorySize, SMEM_BYTES);

  // 1) W -> W^T fp16
  trans_w<<<dim3(DD / 32, DD / 32), dim3(32, 8)>>>(W, wthi);
  // 2) wa = W@a
  gemv2<<<DD / 8, 256>>>(W, a, a + DD, wa1, wa2);
  // 3) x -> fp16 AND s1 = x@wa1, s2 = x@wa2 (fused single pass over x)
  split_s<<<NN, 256>>>(x, wa1, wa2, xhi, s1, s2);
  // 4) fused: logits -> mask bits (triangular x@x^T) AND h = x@W
  gemm_fused<<<528 + 512, 256, SMEM_BYTES>>>(xhi, wthi, adj, mask, hthi);
  // 4b) exact fp32 recompute of near-zero dots -> fix mask bits
  fixup_kernel<<<1024, 256>>>(x, adj, mask);
  // 5) softmax from mask + s1/s2 -> attention fp16
  softmax_rows<<<NN, 256>>>(mask, s1, s2, phi);
  // 6) out = elu(attention @ h), 1-pass BK32 4-stage
  gemm_out<<<512, 256, SMEM_BYTES>>>(phi, hthi, out);
}

// round 12
// speedup vs baseline: 7.4454x; 1.1498x over previous
#include <cuda_runtime.h>
#include <cuda_fp16.h>
#include <math.h>
#include <stdint.h>

#define NN 4096   // nodes
#define DD 2048   // features
#define DOT_THR 0.15f
#define MAX_FIX (1 << 22)

// ================= scratch (__device__ globals; no allocs allowed) ==========
__device__ __half g_xhi[(size_t)NN * DD];     // 16 MB
__device__ __half g_wthi[(size_t)DD * DD];    // 8 MB   W^T fp16
__device__ __half g_hthi[(size_t)DD * NN];    // 16 MB  h^T fp16
__device__ uint32_t g_mask[(size_t)NN * NN / 32];  // 2 MB  attention mask bits
__device__ __half g_phi[(size_t)NN * NN];     // 32 MB  attention fp16
__device__ float g_s1[NN], g_s2[NN];
__device__ float g_wa1[DD], g_wa2[DD];
__device__ int g_cnt;                         // fixup worklist
__device__ int g_list[MAX_FIX];               // 16 MB

// ================= PTX helpers ==============================================
__device__ __forceinline__ uint32_t smem_u32(const void* p) {
  uint32_t a;
  asm("{ .reg .u64 t; cvta.to.shared.u64 t, %1; cvt.u32.u64 %0, t; }"
      : "=r"(a) : "l"(p));
  return a;
}
__device__ __forceinline__ void cp16(uint32_t dst, const void* src) {
  asm volatile("cp.async.cg.shared.global [%0], [%1], 16;" :: "r"(dst), "l"(src));
}
#define CP_COMMIT() asm volatile("cp.async.commit_group;" ::: "memory")
#define CP_WAIT2()  asm volatile("cp.async.wait_group 2;" ::: "memory")

__device__ __forceinline__ void ldm4(uint32_t* r, uint32_t addr) {
  asm volatile("ldmatrix.sync.aligned.m8n8.x4.shared.b16 {%0,%1,%2,%3}, [%4];"
               : "=r"(r[0]), "=r"(r[1]), "=r"(r[2]), "=r"(r[3]) : "r"(addr));
}
__device__ __forceinline__ void mma_f16(float* d, const uint32_t* a,
                                        const uint32_t* b) {
  asm volatile(
      "mma.sync.aligned.m16n8k16.row.col.f32.f16.f16.f32 "
      "{%0,%1,%2,%3}, {%4,%5,%6,%7}, {%8,%9}, {%0,%1,%2,%3};"
      : "+f"(d[0]), "+f"(d[1]), "+f"(d[2]), "+f"(d[3])
      : "r"(a[0]), "r"(a[1]), "r"(a[2]), "r"(a[3]), "r"(b[0]), "r"(b[1]));
}

// Dense 64B rows with XOR chunk swizzle: phys(row, L) = row*64 + (L ^ ((row>>1)&3))*16
// - STS: warp's 8 rows x 64B = 4 dense 128B wavefronts
// - LDSM: quad-bank (4(row&1) + L^((row>>1)&3)) mod 8 distinct over 8-row groups
// - swizzle term invariant under row += 8/16/32 -> folds into per-lane constants
#define TILE_B  (128 * 64)            // 8192 B per 128x32 operand tile
#define STAGE_B (2 * TILE_B)          // A, B per stage (BK=32)
#define NSTAGE  4
#define SMEM_BYTES 66048              // max(4*STAGE_B=65536, epilogue 128*129*4)

// ---- 1-pass fp16 mainloop, BK=32, 4-stage, single sync per iteration -------
#define GEMM_MAINLOOP_1P(Ap, Bp, K, ldA, ldB, bm, bn)                           \
  {                                                                             \
    auto load32 = [&](int ci, int s) {                                          \
      const uint32_t stg = smBase + (uint32_t)s * STAGE_B;                      \
      const int k0 = ci * 32;                                                   \
      _Pragma("unroll")                                                         \
      for (int it = 0; it < 2; it++) {                                          \
        int c = tid + it * 256;            /* 0..511 */                         \
        int row = c >> 2, chk = c & 3;                                          \
        uint32_t so = row * 64 + ((chk ^ ((row >> 1) & 3)) * 16);               \
        cp16(stg + so,                                                          \
             (const char*)(Ap + (size_t)(bm + row) * ldA + k0) + chk * 16);     \
        cp16(stg + TILE_B + so,                                                 \
             (const char*)(Bp + (size_t)(bn + row) * ldB + k0) + chk * 16);     \
      }                                                                         \
      CP_COMMIT();                                                              \
    };                                                                          \
    const int nch = (K) / 32;                                                   \
    load32(0, 0);                                                               \
    load32(1, 1);                                                               \
    load32(2, 2);                                                               \
    for (int i = 0; i < nch; i++) {                                             \
      CP_WAIT2();                                                               \
      __syncthreads();                                                          \
      if (i + 3 < nch) load32(i + 3, (i + 3) & 3);                              \
      else             CP_COMMIT();   /* keep group arithmetic exact */         \
      const uint32_t stg = smBase + (uint32_t)(i & 3) * STAGE_B;                \
      _Pragma("unroll")                                                         \
      for (int ks = 0; ks < 2; ks++) {                                          \
        uint32_t ah[4][4], bh[2][4];                                            \
        _Pragma("unroll")                                                       \
        for (int mi = 0; mi < 4; mi++)                                          \
          ldm4(ah[mi], stg + aoffk[ks] + mi * 1024);                            \
        _Pragma("unroll")                                                       \
        for (int nb = 0; nb < 2; nb++)                                          \
          ldm4(bh[nb], stg + TILE_B + boffk[ks] + nb * 1024);                   \
        _Pragma("unroll")                                                       \
        for (int mi = 0; mi < 4; mi++)                                          \
          _Pragma("unroll")                                                     \
          for (int ni = 0; ni < 4; ni++)                                        \
            mma_f16(acc[mi][ni], ah[mi], &bh[ni >> 1][(ni & 1) * 2]);           \
      }                                                                         \
    }                                                                           \
    __syncthreads();   /* protect smem reuse by epilogue staging */             \
  }

// per-lane swizzled fragment bases for ks = 0,1
#define FRAG_OFFSETS()                                                          \
  uint32_t aoffk[2], boffk[2];                                                  \
  {                                                                             \
    int arow = wm * 64 + (lane & 15);                                           \
    uint32_t swxA = (uint32_t)((arow >> 1) & 3);                                \
    int brow = wn * 32 + ((lane >> 4) & 1) * 8 + (lane & 7);                    \
    uint32_t swxB = (uint32_t)((brow >> 1) & 3);                                \
    _Pragma("unroll")                                                           \
    for (int ks = 0; ks < 2; ks++) {                                            \
      aoffk[ks] = (uint32_t)(arow * 64 +                                        \
                  ((((lane >> 4) & 1) + 2 * ks) ^ swxA) * 16);                  \
      boffk[ks] = (uint32_t)(brow * 64 +                                        \
                  ((((lane >> 3) & 1) + 2 * ks) ^ swxB) * 16);                  \
    }                                                                           \
  }

#define ACC_TO_SMEM()                                                           \
  {                                                                             \
    const int r0 = wm * 64 + (lane >> 2);                                       \
    const int c0 = wn * 32 + (lane & 3) * 2;                                    \
    _Pragma("unroll")                                                           \
    for (int mi = 0; mi < 4; mi++)                                              \
      _Pragma("unroll")                                                         \
      for (int ni = 0; ni < 4; ni++) {                                          \
        int r = r0 + mi * 16, c = c0 + ni * 8;                                  \
        st[r * 129 + c]           = acc[mi][ni][0];                             \
        st[r * 129 + c + 1]       = acc[mi][ni][1];                             \
        st[(r + 8) * 129 + c]     = acc[mi][ni][2];                             \
        st[(r + 8) * 129 + c + 1] = acc[mi][ni][3];                             \
      }                                                                         \
  }

// ================= fused GEMM: logits mask (528) + h (512) ==================
__global__ __launch_bounds__(256, 2)
void gemm_fused(const __half* __restrict__ xhi, const __half* __restrict__ wthi,
                const float* __restrict__ adj, uint32_t* __restrict__ mask,
                __half* __restrict__ hthi) {
  extern __shared__ __align__(16) char smraw[];
  const uint32_t smBase = smem_u32(smraw);
  const int tid = threadIdx.x, wid = tid >> 5, lane = tid & 31;
  const int wm = wid >> 2, wn = wid & 3;

  const int bid = blockIdx.x;
  const bool logits = bid < 528;
  int bm, bn;
  if (logits) {
    int rem = bid, bi = 0;
    while (rem >= 32 - bi) { rem -= 32 - bi; bi++; }
    bm = bi * 128; bn = (bi + rem) * 128;
  } else {
    int t = bid - 528;                     // 512 blocks: 32 m-tiles x 16 n-tiles
    int group = t >> 7;                    // 8-row supergroups
    int rem = t & 127;
    bm = (group * 8 + (rem & 7)) * 128;
    bn = (rem >> 3) * 128;
  }

  float acc[4][4][4];
#pragma unroll
  for (int i = 0; i < 4; i++)
#pragma unroll
    for (int j = 0; j < 4; j++)
#pragma unroll
      for (int v = 0; v < 4; v++) acc[i][j][v] = 0.f;

  FRAG_OFFSETS();

  if (logits) {
    GEMM_MAINLOOP_1P(xhi, xhi, DD, DD, DD, bm, bn);
  } else {
    GEMM_MAINLOOP_1P(xhi, wthi, DD, DD, DD, bm, bn);
  }

  float* st = (float*)smraw;
  ACC_TO_SMEM();
  __syncthreads();

  if (logits) {
    // build mask words: 128 rows x 4 words per tile (512 words, 2/thread)
#pragma unroll
    for (int s = 0; s < 2; s++) {
      int idx = s * 256 + tid;
      int rr = idx >> 2, wc = idx & 3;
      int gm = bm + rr;
      const float* arow = adj + (size_t)gm * NN + bn + wc * 32;
      uint32_t word = 0;
#pragma unroll 8
      for (int b = 0; b < 32; b++) {
        float v = st[rr * 129 + wc * 32 + b];
        if (arow[b] * v > 0.f) word |= (1u << b);
        if (fabsf(v) < DOT_THR) {
          int slot = atomicAdd(&g_cnt, 1);
          if (slot < MAX_FIX) g_list[slot] = (gm << 12) | (bn + wc * 32 + b);
        }
      }
      mask[(size_t)gm * 128 + (bn >> 5) + wc] = word;
    }
    if (bm != bn) {   // mirrored half: dot symmetric, transposed smem read
#pragma unroll
      for (int s = 0; s < 2; s++) {
        int idx = s * 256 + tid;
        int rr = idx >> 2, wc = idx & 3;
        int gm = bn + rr;
        const float* arow = adj + (size_t)gm * NN + bm + wc * 32;
        uint32_t word = 0;
#pragma unroll 8
        for (int b = 0; b < 32; b++) {
          float v = st[(wc * 32 + b) * 129 + rr];
          if (arow[b] * v > 0.f) word |= (1u << b);
          if (fabsf(v) < DOT_THR) {
            int slot = atomicAdd(&g_cnt, 1);
            if (slot < MAX_FIX) g_list[slot] = (gm << 12) | (bm + wc * 32 + b);
          }
        }
        mask[(size_t)gm * 128 + (bm >> 5) + wc] = word;
      }
    }
  } else {
    // transposed write: h_t[n][m] fp16, coalesced along m
#pragma unroll 4
    for (int s = 0; s < 64; s++) {
      int idx = s * 256 + tid;
      int n = idx >> 7, m = idx & 127;
      hthi[(size_t)(bn + n) * NN + bm + m] = __float2half(st[m * 129 + n]);
    }
  }
}

// ================= out GEMM: out = elu(attention @ h) =======================
__global__ __launch_bounds__(256, 2)
void gemm_out(const __half* __restrict__ phi, const __half* __restrict__ hthi,
              float* __restrict__ out) {
  extern __shared__ __align__(16) char smraw[];
  const uint32_t smBase = smem_u32(smraw);
  const int tid = threadIdx.x, wid = tid >> 5, lane = tid & 31;
  const int wm = wid >> 2, wn = wid & 3;

  const int t = blockIdx.x;
  const int group = t >> 7;
  const int rem = t & 127;
  const int bm = (group * 8 + (rem & 7)) * 128;
  const int bn = (rem >> 3) * 128;

  float acc[4][4][4];
#pragma unroll
  for (int i = 0; i < 4; i++)
#pragma unroll
    for (int j = 0; j < 4; j++)
#pragma unroll
      for (int v = 0; v < 4; v++) acc[i][j][v] = 0.f;

  FRAG_OFFSETS();

  GEMM_MAINLOOP_1P(phi, hthi, NN, NN, NN, bm, bn);

  float* st = (float*)smraw;
  ACC_TO_SMEM();
  __syncthreads();

#pragma unroll 4
  for (int s = 0; s < 64; s++) {
    int idx = s * 256 + tid;
    int rr = idx >> 7, cc = idx & 127;
    float v = st[rr * 129 + cc];
    float o = (v > 0.f) ? v : expm1f(v);
    out[(size_t)(bm + rr) * DD + bn + cc] = o;
  }
}

// ================= fixup: exact fp32 dot -> set/clear mask bit ==============
__global__ __launch_bounds__(256) void fixup_kernel(
    const float* __restrict__ x, const float* __restrict__ adj,
    uint32_t* __restrict__ mask) {
  const int n = min(g_cnt, MAX_FIX);
  const int warps = gridDim.x * (blockDim.x >> 5);
  const int w0 = blockIdx.x * (blockDim.x >> 5) + (threadIdx.x >> 5);
  const int lane = threadIdx.x & 31;
  for (int idx = w0; idx < n; idx += warps) {
    const int code = g_list[idx];
    const int i = code >> 12, j = code & 4095;
    const float4* xi = (const float4*)(x + (size_t)i * DD);
    const float4* xj = (const float4*)(x + (size_t)j * DD);
    float s = 0.f;
#pragma unroll 4
    for (int k = lane; k < DD / 4; k += 32) {
      float4 a = xi[k], b = xj[k];
      s = fmaf(a.x, b.x, s);
      s = fmaf(a.y, b.y, s);
      s = fmaf(a.z, b.z, s);
      s = fmaf(a.w, b.w, s);
    }
#pragma unroll
    for (int off = 16; off; off >>= 1) s += __shfl_xor_sync(0xffffffffu, s, off);
    if (lane == 0) {
      float av = adj[(size_t)i * NN + j];
      uint32_t* w = &mask[(size_t)i * 128 + (j >> 5)];
      uint32_t bit = 1u << (j & 31);
      if (av * s > 0.f) atomicOr(w, bit);
      else              atomicAnd(w, ~bit);
    }
  }
}

// ================= support kernels ==========================================
// per-row: x -> fp16, and s1 = x@wa1, s2 = x@wa2 (fused, single x pass)
__global__ __launch_bounds__(256) void split_s(const float* __restrict__ x,
    const float* __restrict__ wa1, const float* __restrict__ wa2,
    __half* __restrict__ xhi, float* __restrict__ s1, float* __restrict__ s2) {
  const int row = blockIdx.x;
  const int tid = threadIdx.x;
  const float4* xr = (const float4*)(x + (size_t)row * DD);
  const float4* a1 = (const float4*)wa1;
  const float4* a2 = (const float4*)wa2;
  float p1 = 0.f, p2 = 0.f;
#pragma unroll
  for (int t = 0; t < 2; t++) {
    int k = tid + t * 256;            // float4 index, 0..511
    float4 v = xr[k], b1 = a1[k], b2 = a2[k];
    p1 = fmaf(v.x, b1.x, p1); p1 = fmaf(v.y, b1.y, p1);
    p1 = fmaf(v.z, b1.z, p1); p1 = fmaf(v.w, b1.w, p1);
    p2 = fmaf(v.x, b2.x, p2); p2 = fmaf(v.y, b2.y, p2);
    p2 = fmaf(v.z, b2.z, p2); p2 = fmaf(v.w, b2.w, p2);
    __half2 h0 = __floats2half2_rn(v.x, v.y);
    __half2 h1 = __floats2half2_rn(v.z, v.w);
    *(__half2*)(xhi + (size_t)row * DD + k * 4)     = h0;
    *(__half2*)(xhi + (size_t)row * DD + k * 4 + 2) = h1;
  }
#pragma unroll
  for (int off = 16; off; off >>= 1) {
    p1 += __shfl_xor_sync(0xffffffffu, p1, off);
    p2 += __shfl_xor_sync(0xffffffffu, p2, off);
  }
  __shared__ float r1[8], r2[8];
  const int warp = tid >> 5, lane = tid & 31;
  if (lane == 0) { r1[warp] = p1; r2[warp] = p2; }
  __syncthreads();
  if (tid == 0) {
    float t1 = 0.f, t2 = 0.f;
#pragma unroll
    for (int w = 0; w < 8; w++) { t1 += r1[w]; t2 += r2[w]; }
    s1[row] = t1;
    s2[row] = t2;
    if (row == 0) g_cnt = 0;
  }
}

__global__ __launch_bounds__(256) void trans_w(const float* __restrict__ W,
    __half* __restrict__ wthi) {
  __shared__ float t[32][33];
  const int bx = blockIdx.x * 32, by = blockIdx.y * 32;  // bx: n, by: k
  const int tx = threadIdx.x, ty = threadIdx.y;          // block (32,8)
#pragma unroll
  for (int rep = 0; rep < 4; rep++)
    t[ty + rep * 8][tx] = W[(size_t)(by + ty + rep * 8) * DD + bx + tx];
  __syncthreads();
#pragma unroll
  for (int rep = 0; rep < 4; rep++)
    wthi[(size_t)(bx + ty + rep * 8) * DD + by + tx] =
        __float2half(t[tx][ty + rep * 8]);
}

// rows x D fp32 GEMV, 2 RHS: o1 = M@v1, o2 = M@v2 (one warp per row)
__global__ __launch_bounds__(256) void gemv2(const float* __restrict__ M,
    const float* __restrict__ v1, const float* __restrict__ v2,
    float* __restrict__ o1, float* __restrict__ o2) {
  const int row = blockIdx.x * 8 + (threadIdx.x >> 5);
  const int lane = threadIdx.x & 31;
  const float4* mr = (const float4*)(M + (size_t)row * DD);
  const float4* a1 = (const float4*)v1;
  const float4* a2 = (const float4*)v2;
  float p1 = 0.f, p2 = 0.f;
#pragma unroll 4
  for (int k = lane; k < DD / 4; k += 32) {
    float4 m = mr[k], b1 = a1[k], b2 = a2[k];
    p1 = fmaf(m.x, b1.x, p1); p1 = fmaf(m.y, b1.y, p1);
    p1 = fmaf(m.z, b1.z, p1); p1 = fmaf(m.w, b1.w, p1);
    p2 = fmaf(m.x, b2.x, p2); p2 = fmaf(m.y, b2.y, p2);
    p2 = fmaf(m.z, b2.z, p2); p2 = fmaf(m.w, b2.w, p2);
  }
#pragma unroll
  for (int off = 16; off; off >>= 1) {
    p1 += __shfl_xor_sync(0xffffffffu, p1, off);
    p2 += __shfl_xor_sync(0xffffffffu, p2, off);
  }
  if (lane == 0) { o1[row] = p1; o2[row] = p2; }
}

// softmax from mask bits: e = leaky(s1[i]+s2[j]) recomputed on the fly
__global__ __launch_bounds__(256) void softmax_rows(
    const uint32_t* __restrict__ mask, const float* __restrict__ s1,
    const float* __restrict__ s2, __half* __restrict__ phi) {
  const int tid = threadIdx.x;
  const int row = blockIdx.x;
  __shared__ uint32_t mw[128];
  __shared__ float red[256];
  if (tid < 128) mw[tid] = mask[(size_t)row * 128 + tid];
  __syncthreads();
  const float s1i = s1[row];

  float vals[16];
  bool mk[16];
  float m = -INFINITY;
#pragma unroll
  for (int t = 0; t < 16; t++) {
    int j = tid + t * 256;
    bool b = (mw[j >> 5] >> (j & 31)) & 1u;
    float e = s1i + s2[j];
    e = (e > 0.f) ? e : 0.1f * e;
    mk[t] = b; vals[t] = e;
    if (b) m = fmaxf(m, e);
  }
  red[tid] = m;
  __syncthreads();
  for (int s = 128; s; s >>= 1) {
    if (tid < s) red[tid] = fmaxf(red[tid], red[tid + s]);
    __syncthreads();
  }
  m = red[0];
  __syncthreads();
  float sum = 0.f;
#pragma unroll
  for (int t = 0; t < 16; t++) {
    float ev = mk[t] ? __expf(vals[t] - m) : 0.f;
    vals[t] = ev;
    sum += ev;
  }
  red[tid] = sum;
  __syncthreads();
  for (int s = 128; s; s >>= 1) {
    if (tid < s) red[tid] += red[tid + s];
    __syncthreads();
  }
  const float tot = red[0];
  const float inv = (tot > 0.f) ? 1.f / tot : 0.f;
  const float uni = 1.f / (float)NN;
#pragma unroll
  for (int t = 0; t < 16; t++) {
    float att = (tot > 0.f) ? vals[t] * inv : uni;
    phi[(size_t)row * NN + tid + t * 256] = __float2half(att);
  }
}

// ================= launch ====================================================
extern "C" void kernel_launch(void* const* d_in, const int* in_sizes, int n_in,
                              void* d_out, int out_size) {
  const float* x   = (const float*)d_in[0];  // (4096, 2048)
  const float* adj = (const float*)d_in[1];  // (4096, 4096)
  const float* W   = (const float*)d_in[2];  // (2048, 2048)
  const float* a   = (const float*)d_in[3];  // (4096, 1)
  float* out = (float*)d_out;                // (4096, 2048)

  __half *xhi, *wthi, *hthi, *phi;
  uint32_t* mask;
  float *s1, *s2, *wa1, *wa2;
  cudaGetSymbolAddress((void**)&xhi,  g_xhi);
  cudaGetSymbolAddress((void**)&wthi, g_wthi);
  cudaGetSymbolAddress((void**)&hthi, g_hthi);
  cudaGetSymbolAddress((void**)&mask, g_mask);
  cudaGetSymbolAddress((void**)&phi,  g_phi);
  cudaGetSymbolAddress((void**)&s1,   g_s1);
  cudaGetSymbolAddress((void**)&s2,   g_s2);
  cudaGetSymbolAddress((void**)&wa1,  g_wa1);
  cudaGetSymbolAddress((void**)&wa2,  g_wa2);

  cudaFuncSetAttribute(gemm_fused, cudaFuncAttributeMaxDynamicSharedMemorySize, SMEM_BYTES);
  cudaFuncSetAttribute(gemm_out,   cudaFuncAttributeMaxDynamicSharedMemorySize, SMEM_BYTES);

  // 1) W -> W^T fp16
  trans_w<<<dim3(DD / 32, DD / 32), dim3(32, 8)>>>(W, wthi);
  // 2) wa = W@a
  gemv2<<<DD / 8, 256>>>(W, a, a + DD, wa1, wa2);
  // 3) x -> fp16 AND s1 = x@wa1, s2 = x@wa2 (fused single pass over x)
  split_s<<<NN, 256>>>(x, wa1, wa2, xhi, s1, s2);
  // 4) fused: logits -> mask bits (triangular x@x^T) AND h = x@W
  gemm_fused<<<528 + 512, 256, SMEM_BYTES>>>(xhi, wthi, adj, mask, hthi);
  // 4b) exact fp32 recompute of near-zero dots -> fix mask bits
  fixup_kernel<<<1024, 256>>>(x, adj, mask);
  // 5) softmax from mask + s1/s2 -> attention fp16
  softmax_rows<<<NN, 256>>>(mask, s1, s2, phi);
  // 6) out = elu(attention @ h), 1-pass BK32 4-stage, swizzled smem
  gemm_out<<<512, 256, SMEM_BYTES>>>(phi, hthi, out);
}

// round 13
// speedup vs baseline: 7.8365x; 1.0525x over previous
#include <cuda_runtime.h>
#include <cuda_fp16.h>
#include <math.h>
#include <stdint.h>

#define NN 4096   // nodes
#define DD 2048   // features
#define DOT_THR 0.15f
#define MAX_FIX (1 << 22)
#define NT 128    // threads per GEMM block (4 warps, 2x2 grid of 64x64 tiles)

// ================= scratch (__device__ globals; no allocs allowed) ==========
__device__ __half g_xhi[(size_t)NN * DD];     // 16 MB
__device__ __half g_wthi[(size_t)DD * DD];    // 8 MB   W^T fp16
__device__ __half g_hthi[(size_t)DD * NN];    // 16 MB  h^T fp16
__device__ uint32_t g_mask[(size_t)NN * NN / 32];  // 2 MB  attention mask bits
__device__ __half g_phi[(size_t)NN * NN];     // 32 MB  attention fp16
__device__ float g_s1[NN], g_s2[NN];
__device__ float g_wa1[DD], g_wa2[DD];
__device__ int g_cnt;                         // fixup worklist
__device__ int g_list[MAX_FIX];               // 16 MB

// ================= PTX helpers ==============================================
__device__ __forceinline__ uint32_t smem_u32(const void* p) {
  uint32_t a;
  asm("{ .reg .u64 t; cvta.to.shared.u64 t, %1; cvt.u32.u64 %0, t; }"
      : "=r"(a) : "l"(p));
  return a;
}
__device__ __forceinline__ void cp16(uint32_t dst, const void* src) {
  asm volatile("cp.async.cg.shared.global [%0], [%1], 16;" :: "r"(dst), "l"(src));
}
#define CP_COMMIT() asm volatile("cp.async.commit_group;" ::: "memory")
#define CP_WAIT2()  asm volatile("cp.async.wait_group 2;" ::: "memory")

__device__ __forceinline__ void ldm4(uint32_t* r, uint32_t addr) {
  asm volatile("ldmatrix.sync.aligned.m8n8.x4.shared.b16 {%0,%1,%2,%3}, [%4];"
               : "=r"(r[0]), "=r"(r[1]), "=r"(r[2]), "=r"(r[3]) : "r"(addr));
}
__device__ __forceinline__ void mma_f16(float* d, const uint32_t* a,
                                        const uint32_t* b) {
  asm volatile(
      "mma.sync.aligned.m16n8k16.row.col.f32.f16.f16.f32 "
      "{%0,%1,%2,%3}, {%4,%5,%6,%7}, {%8,%9}, {%0,%1,%2,%3};"
      : "+f"(d[0]), "+f"(d[1]), "+f"(d[2]), "+f"(d[3])
      : "r"(a[0]), "r"(a[1]), "r"(a[2]), "r"(a[3]), "r"(b[0]), "r"(b[1]));
}

// Dense 64B rows with XOR chunk swizzle: phys(row, L) = row*64 + (L ^ ((row>>1)&3))*16
#define TILE_B  (128 * 64)            // 8192 B per 128x32 operand tile
#define STAGE_B (2 * TILE_B)          // A, B per stage (BK=32)
#define SMEM_BYTES 66048              // max(4*STAGE_B=65536, epilogue 128*129*4)

// ---- 1-pass fp16 mainloop, BK=32, 4-stage, single sync per iteration -------
// 4 warps, warp tile 64x64: acc[4][8][4]. Minimal-duplication LDSM:
// per iter = 4 warps x 2 ks x (4 A + 4 B) = 64 ldm4 (32KB vs 49KB at 2x4).
#define GEMM_MAINLOOP_1P(Ap, Bp, K, ldA, ldB, bm, bn)                           \
  {                                                                             \
    auto load32 = [&](int ci, int s) {                                          \
      const uint32_t stg = smBase + (uint32_t)s * STAGE_B;                      \
      const int k0 = ci * 32;                                                   \
      _Pragma("unroll")                                                         \
      for (int it = 0; it < 4; it++) {                                          \
        int c = tid + it * NT;             /* 0..511 */                         \
        int row = c >> 2, chk = c & 3;                                          \
        uint32_t so = row * 64 + ((chk ^ ((row >> 1) & 3)) * 16);               \
        cp16(stg + so,                                                          \
             (const char*)(Ap + (size_t)(bm + row) * ldA + k0) + chk * 16);     \
        cp16(stg + TILE_B + so,                                                 \
             (const char*)(Bp + (size_t)(bn + row) * ldB + k0) + chk * 16);     \
      }                                                                         \
      CP_COMMIT();                                                              \
    };                                                                          \
    const int nch = (K) / 32;                                                   \
    load32(0, 0);                                                               \
    load32(1, 1);                                                               \
    load32(2, 2);                                                               \
    for (int i = 0; i < nch; i++) {                                             \
      CP_WAIT2();                                                               \
      __syncthreads();                                                          \
      if (i + 3 < nch) load32(i + 3, (i + 3) & 3);                              \
      else             CP_COMMIT();   /* keep group arithmetic exact */         \
      const uint32_t stg = smBase + (uint32_t)(i & 3) * STAGE_B;                \
      _Pragma("unroll")                                                         \
      for (int ks = 0; ks < 2; ks++) {                                          \
        uint32_t ah[4][4], bh[4][4];                                            \
        _Pragma("unroll")                                                       \
        for (int mi = 0; mi < 4; mi++)                                          \
          ldm4(ah[mi], stg + aoffk[ks] + mi * 1024);                            \
        _Pragma("unroll")                                                       \
        for (int nb = 0; nb < 4; nb++)                                          \
          ldm4(bh[nb], stg + TILE_B + boffk[ks] + nb * 1024);                   \
        _Pragma("unroll")                                                       \
        for (int mi = 0; mi < 4; mi++)                                          \
          _Pragma("unroll")                                                     \
          for (int ni = 0; ni < 8; ni++)                                        \
            mma_f16(acc[mi][ni], ah[mi], &bh[ni >> 1][(ni & 1) * 2]);           \
      }                                                                         \
    }                                                                           \
    __syncthreads();   /* protect smem reuse by epilogue staging */             \
  }

// per-lane swizzled fragment bases for ks = 0,1 (warp grid 2x2, tile 64x64)
#define FRAG_OFFSETS()                                                          \
  uint32_t aoffk[2], boffk[2];                                                  \
  {                                                                             \
    int arow = wm * 64 + (lane & 15);                                           \
    uint32_t swxA = (uint32_t)((arow >> 1) & 3);                                \
    int brow = wn * 64 + ((lane >> 4) & 1) * 8 + (lane & 7);                    \
    uint32_t swxB = (uint32_t)((brow >> 1) & 3);                                \
    _Pragma("unroll")                                                           \
    for (int ks = 0; ks < 2; ks++) {                                            \
      aoffk[ks] = (uint32_t)(arow * 64 +                                        \
                  ((((lane >> 4) & 1) + 2 * ks) ^ swxA) * 16);                  \
      boffk[ks] = (uint32_t)(brow * 64 +                                        \
                  ((((lane >> 3) & 1) + 2 * ks) ^ swxB) * 16);                  \
    }                                                                           \
  }

#define ACC_TO_SMEM()                                                           \
  {                                                                             \
    const int r0 = wm * 64 + (lane >> 2);                                       \
    const int c0 = wn * 64 + (lane & 3) * 2;                                    \
    _Pragma("unroll")                                                           \
    for (int mi = 0; mi < 4; mi++)                                              \
      _Pragma("unroll")                                                         \
      for (int ni = 0; ni < 8; ni++) {                                          \
        int r = r0 + mi * 16, c = c0 + ni * 8;                                  \
        st[r * 129 + c]           = acc[mi][ni][0];                             \
        st[r * 129 + c + 1]       = acc[mi][ni][1];                             \
        st[(r + 8) * 129 + c]     = acc[mi][ni][2];                             \
        st[(r + 8) * 129 + c + 1] = acc[mi][ni][3];                             \
      }                                                                         \
  }

// ================= fused GEMM: logits mask (528) + h (512) ==================
__global__ __launch_bounds__(NT, 2)
void gemm_fused(const __half* __restrict__ xhi, const __half* __restrict__ wthi,
                const float* __restrict__ adj, uint32_t* __restrict__ mask,
                __half* __restrict__ hthi) {
  extern __shared__ __align__(16) char smraw[];
  const uint32_t smBase = smem_u32(smraw);
  const int tid = threadIdx.x, wid = tid >> 5, lane = tid & 31;
  const int wm = wid >> 1, wn = wid & 1;

  const int bid = blockIdx.x;
  const bool logits = bid < 528;
  int bm, bn;
  if (logits) {
    int rem = bid, bi = 0;
    while (rem >= 32 - bi) { rem -= 32 - bi; bi++; }
    bm = bi * 128; bn = (bi + rem) * 128;
  } else {
    int t = bid - 528;                     // 512 blocks: 32 m-tiles x 16 n-tiles
    int group = t >> 7;                    // 8-row supergroups
    int rem = t & 127;
    bm = (group * 8 + (rem & 7)) * 128;
    bn = (rem >> 3) * 128;
  }

  float acc[4][8][4];
#pragma unroll
  for (int i = 0; i < 4; i++)
#pragma unroll
    for (int j = 0; j < 8; j++)
#pragma unroll
      for (int v = 0; v < 4; v++) acc[i][j][v] = 0.f;

  FRAG_OFFSETS();

  if (logits) {
    GEMM_MAINLOOP_1P(xhi, xhi, DD, DD, DD, bm, bn);
  } else {
    GEMM_MAINLOOP_1P(xhi, wthi, DD, DD, DD, bm, bn);
  }

  float* st = (float*)smraw;
  ACC_TO_SMEM();
  __syncthreads();

  if (logits) {
    // build mask words: 128 rows x 4 words per tile (512 words, 4/thread)
#pragma unroll
    for (int s = 0; s < 4; s++) {
      int idx = s * NT + tid;
      int rr = idx >> 2, wc = idx & 3;
      int gm = bm + rr;
      const float* arow = adj + (size_t)gm * NN + bn + wc * 32;
      uint32_t word = 0;
#pragma unroll 8
      for (int b = 0; b < 32; b++) {
        float v = st[rr * 129 + wc * 32 + b];
        if (arow[b] * v > 0.f) word |= (1u << b);
        if (fabsf(v) < DOT_THR) {
          int slot = atomicAdd(&g_cnt, 1);
          if (slot < MAX_FIX) g_list[slot] = (gm << 12) | (bn + wc * 32 + b);
        }
      }
      mask[(size_t)gm * 128 + (bn >> 5) + wc] = word;
    }
    if (bm != bn) {   // mirrored half: dot symmetric, transposed smem read
#pragma unroll
      for (int s = 0; s < 4; s++) {
        int idx = s * NT + tid;
        int rr = idx >> 2, wc = idx & 3;
        int gm = bn + rr;
        const float* arow = adj + (size_t)gm * NN + bm + wc * 32;
        uint32_t word = 0;
#pragma unroll 8
        for (int b = 0; b < 32; b++) {
          float v = st[(wc * 32 + b) * 129 + rr];
          if (arow[b] * v > 0.f) word |= (1u << b);
          if (fabsf(v) < DOT_THR) {
            int slot = atomicAdd(&g_cnt, 1);
            if (slot < MAX_FIX) g_list[slot] = (gm << 12) | (bm + wc * 32 + b);
          }
        }
        mask[(size_t)gm * 128 + (bm >> 5) + wc] = word;
      }
    }
  } else {
    // transposed write: h_t[n][m] fp16, coalesced along m
#pragma unroll 4
    for (int s = 0; s < 128; s++) {
      int idx = s * NT + tid;
      int n = idx >> 7, m = idx & 127;
      hthi[(size_t)(bn + n) * NN + bm + m] = __float2half(st[m * 129 + n]);
    }
  }
}

// ================= out GEMM: out = elu(attention @ h) =======================
__global__ __launch_bounds__(NT, 2)
void gemm_out(const __half* __restrict__ phi, const __half* __restrict__ hthi,
              float* __restrict__ out) {
  extern __shared__ __align__(16) char smraw[];
  const uint32_t smBase = smem_u32(smraw);
  const int tid = threadIdx.x, wid = tid >> 5, lane = tid & 31;
  const int wm = wid >> 1, wn = wid & 1;

  const int t = blockIdx.x;
  const int group = t >> 7;
  const int rem = t & 127;
  const int bm = (group * 8 + (rem & 7)) * 128;
  const int bn = (rem >> 3) * 128;

  float acc[4][8][4];
#pragma unroll
  for (int i = 0; i < 4; i++)
#pragma unroll
    for (int j = 0; j < 8; j++)
#pragma unroll
      for (int v = 0; v < 4; v++) acc[i][j][v] = 0.f;

  FRAG_OFFSETS();

  GEMM_MAINLOOP_1P(phi, hthi, NN, NN, NN, bm, bn);

  float* st = (float*)smraw;
  ACC_TO_SMEM();
  __syncthreads();

#pragma unroll 4
  for (int s = 0; s < 128; s++) {
    int idx = s * NT + tid;
    int rr = idx >> 7, cc = idx & 127;
    float v = st[rr * 129 + cc];
    float o = (v > 0.f) ? v : expm1f(v);
    out[(size_t)(bm + rr) * DD + bn + cc] = o;
  }
}

// ================= fixup: exact fp32 dot -> set/clear mask bit ==============
__global__ __launch_bounds__(256) void fixup_kernel(
    const float* __restrict__ x, const float* __restrict__ adj,
    uint32_t* __restrict__ mask) {
  const int n = min(g_cnt, MAX_FIX);
  const int warps = gridDim.x * (blockDim.x >> 5);
  const int w0 = blockIdx.x * (blockDim.x >> 5) + (threadIdx.x >> 5);
  const int lane = threadIdx.x & 31;
  for (int idx = w0; idx < n; idx += warps) {
    const int code = g_list[idx];
    const int i = code >> 12, j = code & 4095;
    const float4* xi = (const float4*)(x + (size_t)i * DD);
    const float4* xj = (const float4*)(x + (size_t)j * DD);
    float s = 0.f;
#pragma unroll 4
    for (int k = lane; k < DD / 4; k += 32) {
      float4 a = xi[k], b = xj[k];
      s = fmaf(a.x, b.x, s);
      s = fmaf(a.y, b.y, s);
      s = fmaf(a.z, b.z, s);
      s = fmaf(a.w, b.w, s);
    }
#pragma unroll
    for (int off = 16; off; off >>= 1) s += __shfl_xor_sync(0xffffffffu, s, off);
    if (lane == 0) {
      float av = adj[(size_t)i * NN + j];
      uint32_t* w = &mask[(size_t)i * 128 + (j >> 5)];
      uint32_t bit = 1u << (j & 31);
      if (av * s > 0.f) atomicOr(w, bit);
      else              atomicAnd(w, ~bit);
    }
  }
}

// ================= support kernels ==========================================
// per-row: x -> fp16, and s1 = x@wa1, s2 = x@wa2 (fused, single x pass)
__global__ __launch_bounds__(256) void split_s(const float* __restrict__ x,
    const float* __restrict__ wa1, const float* __restrict__ wa2,
    __half* __restrict__ xhi, float* __restrict__ s1, float* __restrict__ s2) {
  const int row = blockIdx.x;
  const int tid = threadIdx.x;
  const float4* xr = (const float4*)(x + (size_t)row * DD);
  const float4* a1 = (const float4*)wa1;
  const float4* a2 = (const float4*)wa2;
  float p1 = 0.f, p2 = 0.f;
#pragma unroll
  for (int t = 0; t < 2; t++) {
    int k = tid + t * 256;            // float4 index, 0..511
    float4 v = xr[k], b1 = a1[k], b2 = a2[k];
    p1 = fmaf(v.x, b1.x, p1); p1 = fmaf(v.y, b1.y, p1);
    p1 = fmaf(v.z, b1.z, p1); p1 = fmaf(v.w, b1.w, p1);
    p2 = fmaf(v.x, b2.x, p2); p2 = fmaf(v.y, b2.y, p2);
    p2 = fmaf(v.z, b2.z, p2); p2 = fmaf(v.w, b2.w, p2);
    __half2 h0 = __floats2half2_rn(v.x, v.y);
    __half2 h1 = __floats2half2_rn(v.z, v.w);
    *(__half2*)(xhi + (size_t)row * DD + k * 4)     = h0;
    *(__half2*)(xhi + (size_t)row * DD + k * 4 + 2) = h1;
  }
#pragma unroll
  for (int off = 16; off; off >>= 1) {
    p1 += __shfl_xor_sync(0xffffffffu, p1, off);
    p2 += __shfl_xor_sync(0xffffffffu, p2, off);
  }
  __shared__ float r1[8], r2[8];
  const int warp = tid >> 5, lane = tid & 31;
  if (lane == 0) { r1[warp] = p1; r2[warp] = p2; }
  __syncthreads();
  if (tid == 0) {
    float t1 = 0.f, t2 = 0.f;
#pragma unroll
    for (int w = 0; w < 8; w++) { t1 += r1[w]; t2 += r2[w]; }
    s1[row] = t1;
    s2[row] = t2;
    if (row == 0) g_cnt = 0;
  }
}

__global__ __launch_bounds__(256) void trans_w(const float* __restrict__ W,
    __half* __restrict__ wthi) {
  __shared__ float t[32][33];
  const int bx = blockIdx.x * 32, by = blockIdx.y * 32;  // bx: n, by: k
  const int tx = threadIdx.x, ty = threadIdx.y;          // block (32,8)
#pragma unroll
  for (int rep = 0; rep < 4; rep++)
    t[ty + rep * 8][tx] = W[(size_t)(by + ty + rep * 8) * DD + bx + tx];
  __syncthreads();
#pragma unroll
  for (int rep = 0; rep < 4; rep++)
    wthi[(size_t)(bx + ty + rep * 8) * DD + by + tx] =
        __float2half(t[tx][ty + rep * 8]);
}

// rows x D fp32 GEMV, 2 RHS: o1 = M@v1, o2 = M@v2 (one warp per row)
__global__ __launch_bounds__(256) void gemv2(const float* __restrict__ M,
    const float* __restrict__ v1, const float* __restrict__ v2,
    float* __restrict__ o1, float* __restrict__ o2) {
  const int row = blockIdx.x * 8 + (threadIdx.x >> 5);
  const int lane = threadIdx.x & 31;
  const float4* mr = (const float4*)(M + (size_t)row * DD);
  const float4* a1 = (const float4*)v1;
  const float4* a2 = (const float4*)v2;
  float p1 = 0.f, p2 = 0.f;
#pragma unroll 4
  for (int k = lane; k < DD / 4; k += 32) {
    float4 m = mr[k], b1 = a1[k], b2 = a2[k];
    p1 = fmaf(m.x, b1.x, p1); p1 = fmaf(m.y, b1.y, p1);
    p1 = fmaf(m.z, b1.z, p1); p1 = fmaf(m.w, b1.w, p1);
    p2 = fmaf(m.x, b2.x, p2); p2 = fmaf(m.y, b2.y, p2);
    p2 = fmaf(m.z, b2.z, p2); p2 = fmaf(m.w, b2.w, p2);
  }
#pragma unroll
  for (int off = 16; off; off >>= 1) {
    p1 += __shfl_xor_sync(0xffffffffu, p1, off);
    p2 += __shfl_xor_sync(0xffffffffu, p2, off);
  }
  if (lane == 0) { o1[row] = p1; o2[row] = p2; }
}

// softmax from mask bits: e = leaky(s1[i]+s2[j]) recomputed on the fly
__global__ __launch_bounds__(256) void softmax_rows(
    const uint32_t* __restrict__ mask, const float* __restrict__ s1,
    const float* __restrict__ s2, __half* __restrict__ phi) {
  const int tid = threadIdx.x;
  const int row = blockIdx.x;
  __shared__ uint32_t mw[128];
  __shared__ float red[256];
  if (tid < 128) mw[tid] = mask[(size_t)row * 128 + tid];
  __syncthreads();
  const float s1i = s1[row];

  float vals[16];
  bool mk[16];
  float m = -INFINITY;
#pragma unroll
  for (int t = 0; t < 16; t++) {
    int j = tid + t * 256;
    bool b = (mw[j >> 5] >> (j & 31)) & 1u;
    float e = s1i + s2[j];
    e = (e > 0.f) ? e : 0.1f * e;
    mk[t] = b; vals[t] = e;
    if (b) m = fmaxf(m, e);
  }
  red[tid] = m;
  __syncthreads();
  for (int s = 128; s; s >>= 1) {
    if (tid < s) red[tid] = fmaxf(red[tid], red[tid + s]);
    __syncthreads();
  }
  m = red[0];
  __syncthreads();
  float sum = 0.f;
#pragma unroll
  for (int t = 0; t < 16; t++) {
    float ev = mk[t] ? __expf(vals[t] - m) : 0.f;
    vals[t] = ev;
    sum += ev;
  }
  red[tid] = sum;
  __syncthreads();
  for (int s = 128; s; s >>= 1) {
    if (tid < s) red[tid] += red[tid + s];
    __syncthreads();
  }
  const float tot = red[0];
  const float inv = (tot > 0.f) ? 1.f / tot : 0.f;
  const float uni = 1.f / (float)NN;
#pragma unroll
  for (int t = 0; t < 16; t++) {
    float att = (tot > 0.f) ? vals[t] * inv : uni;
    phi[(size_t)row * NN + tid + t * 256] = __float2half(att);
  }
}

// ================= launch ====================================================
extern "C" void kernel_launch(void* const* d_in, const int* in_sizes, int n_in,
                              void* d_out, int out_size) {
  const float* x   = (const float*)d_in[0];  // (4096, 2048)
  const float* adj = (const float*)d_in[1];  // (4096, 4096)
  const float* W   = (const float*)d_in[2];  // (2048, 2048)
  const float* a   = (const float*)d_in[3];  // (4096, 1)
  float* out = (float*)d_out;                // (4096, 2048)

  __half *xhi, *wthi, *hthi, *phi;
  uint32_t* mask;
  float *s1, *s2, *wa1, *wa2;
  cudaGetSymbolAddress((void**)&xhi,  g_xhi);
  cudaGetSymbolAddress((void**)&wthi, g_wthi);
  cudaGetSymbolAddress((void**)&hthi, g_hthi);
  cudaGetSymbolAddress((void**)&mask, g_mask);
  cudaGetSymbolAddress((void**)&phi,  g_phi);
  cudaGetSymbolAddress((void**)&s1,   g_s1);
  cudaGetSymbolAddress((void**)&s2,   g_s2);
  cudaGetSymbolAddress((void**)&wa1,  g_wa1);
  cudaGetSymbolAddress((void**)&wa2,  g_wa2);

  cudaFuncSetAttribute(gemm_fused, cudaFuncAttributeMaxDynamicSharedMemorySize, SMEM_BYTES);
  cudaFuncSetAttribute(gemm_out,   cudaFuncAttributeMaxDynamicSharedMemorySize, SMEM_BYTES);

  // 1) W -> W^T fp16
  trans_w<<<dim3(DD / 32, DD / 32), dim3(32, 8)>>>(W, wthi);
  // 2) wa = W@a
  gemv2<<<DD / 8, 256>>>(W, a, a + DD, wa1, wa2);
  // 3) x -> fp16 AND s1 = x@wa1, s2 = x@wa2 (fused single pass over x)
  split_s<<<NN, 256>>>(x, wa1, wa2, xhi, s1, s2);
  // 4) fused: logits -> mask bits (triangular x@x^T) AND h = x@W
  gemm_fused<<<528 + 512, NT, SMEM_BYTES>>>(xhi, wthi, adj, mask, hthi);
  // 4b) exact fp32 recompute of near-zero dots -> fix mask bits
  fixup_kernel<<<1024, 256>>>(x, adj, mask);
  // 5) softmax from mask + s1/s2 -> attention fp16
  softmax_rows<<<NN, 256>>>(mask, s1, s2, phi);
  // 6) out = elu(attention @ h), 1-pass BK32 4-stage, swizzled smem
  gemm_out<<<512, NT, SMEM_BYTES>>>(phi, hthi, out);
}

// round 14
// speedup vs baseline: 7.9497x; 1.0144x over previous
#include <cuda_runtime.h>
#include <cuda_fp16.h>
#include <math.h>
#include <stdint.h>

#define NN 4096   // nodes
#define DD 2048   // features
#define DOT_THR 0.10f
#define MAX_FIX (1 << 22)
#define NT 128    // threads per GEMM block (4 warps, 2x2 grid of 64x64 tiles)

// ================= scratch (__device__ globals; no allocs allowed) ==========
__device__ __half g_xhi[(size_t)NN * DD];     // 16 MB
__device__ __half g_wthi[(size_t)DD * DD];    // 8 MB   W^T fp16
__device__ __half g_hthi[(size_t)DD * NN];    // 16 MB  h^T fp16
__device__ uint32_t g_mask[(size_t)NN * NN / 32];  // 2 MB  attention mask bits
__device__ __half g_phi[(size_t)NN * NN];     // 32 MB  attention fp16
__device__ float g_s1[NN], g_s2[NN];
__device__ float g_wa1[DD], g_wa2[DD];
__device__ int g_cnt;                         // fixup worklist
__device__ int g_list[MAX_FIX];               // 16 MB

// ================= PTX helpers ==============================================
__device__ __forceinline__ uint32_t smem_u32(const void* p) {
  uint32_t a;
  asm("{ .reg .u64 t; cvta.to.shared.u64 t, %1; cvt.u32.u64 %0, t; }"
      : "=r"(a) : "l"(p));
  return a;
}
__device__ __forceinline__ void cp16(uint32_t dst, const void* src) {
  asm volatile("cp.async.cg.shared.global [%0], [%1], 16;" :: "r"(dst), "l"(src));
}
#define CP_COMMIT() asm volatile("cp.async.commit_group;" ::: "memory")
#define CP_WAIT2()  asm volatile("cp.async.wait_group 2;" ::: "memory")

__device__ __forceinline__ void ldm4(uint32_t* r, uint32_t addr) {
  asm volatile("ldmatrix.sync.aligned.m8n8.x4.shared.b16 {%0,%1,%2,%3}, [%4];"
               : "=r"(r[0]), "=r"(r[1]), "=r"(r[2]), "=r"(r[3]) : "r"(addr));
}
__device__ __forceinline__ void mma_f16(float* d, const uint32_t* a,
                                        const uint32_t* b) {
  asm volatile(
      "mma.sync.aligned.m16n8k16.row.col.f32.f16.f16.f32 "
      "{%0,%1,%2,%3}, {%4,%5,%6,%7}, {%8,%9}, {%0,%1,%2,%3};"
      : "+f"(d[0]), "+f"(d[1]), "+f"(d[2]), "+f"(d[3])
      : "r"(a[0]), "r"(a[1]), "r"(a[2]), "r"(a[3]), "r"(b[0]), "r"(b[1]));
}

// warp-aggregated worklist append: 1 atomic per warp instead of per thread
__device__ __forceinline__ void push_fix(bool flag, int code) {
  uint32_t bal = __ballot_sync(0xffffffffu, flag);
  if (bal == 0u) return;
  const int lane = threadIdx.x & 31;
  const int leader = __ffs(bal) - 1;
  int base = 0;
  if (lane == leader) base = atomicAdd(&g_cnt, __popc(bal));
  base = __shfl_sync(0xffffffffu, base, leader);
  if (flag) {
    int off = __popc(bal & ((1u << lane) - 1u));
    if (base + off < MAX_FIX) g_list[base + off] = code;
  }
}

// Dense 64B rows with XOR chunk swizzle: phys(row, L) = row*64 + (L ^ ((row>>1)&3))*16
#define TILE_B  (128 * 64)            // 8192 B per 128x32 operand tile
#define STAGE_B (2 * TILE_B)          // A, B per stage (BK=32)
#define SMEM_BYTES 66048              // max(4*STAGE_B=65536, epilogue 128*129*4)

// ---- 1-pass fp16 mainloop, BK=32, 4-stage, single sync per iteration -------
#define GEMM_MAINLOOP_1P(Ap, Bp, K, ldA, ldB, bm, bn)                           \
  {                                                                             \
    auto load32 = [&](int ci, int s) {                                          \
      const uint32_t stg = smBase + (uint32_t)s * STAGE_B;                      \
      const int k0 = ci * 32;                                                   \
      _Pragma("unroll")                                                         \
      for (int it = 0; it < 4; it++) {                                          \
        int c = tid + it * NT;             /* 0..511 */                         \
        int row = c >> 2, chk = c & 3;                                          \
        uint32_t so = row * 64 + ((chk ^ ((row >> 1) & 3)) * 16);               \
        cp16(stg + so,                                                          \
             (const char*)(Ap + (size_t)(bm + row) * ldA + k0) + chk * 16);     \
        cp16(stg + TILE_B + so,                                                 \
             (const char*)(Bp + (size_t)(bn + row) * ldB + k0) + chk * 16);     \
      }                                                                         \
      CP_COMMIT();                                                              \
    };                                                                          \
    const int nch = (K) / 32;                                                   \
    load32(0, 0);                                                               \
    load32(1, 1);                                                               \
    load32(2, 2);                                                               \
    for (int i = 0; i < nch; i++) {                                             \
      CP_WAIT2();                                                               \
      __syncthreads();                                                          \
      if (i + 3 < nch) load32(i + 3, (i + 3) & 3);                              \
      else             CP_COMMIT();   /* keep group arithmetic exact */         \
      const uint32_t stg = smBase + (uint32_t)(i & 3) * STAGE_B;                \
      _Pragma("unroll")                                                         \
      for (int ks = 0; ks < 2; ks++) {                                          \
        uint32_t ah[4][4], bh[4][4];                                            \
        _Pragma("unroll")                                                       \
        for (int mi = 0; mi < 4; mi++)                                          \
          ldm4(ah[mi], stg + aoffk[ks] + mi * 1024);                            \
        _Pragma("unroll")                                                       \
        for (int nb = 0; nb < 4; nb++)                                          \
          ldm4(bh[nb], stg + TILE_B + boffk[ks] + nb * 1024);                   \
        _Pragma("unroll")                                                       \
        for (int mi = 0; mi < 4; mi++)                                          \
          _Pragma("unroll")                                                     \
          for (int ni = 0; ni < 8; ni++)                                        \
            mma_f16(acc[mi][ni], ah[mi], &bh[ni >> 1][(ni & 1) * 2]);           \
      }                                                                         \
    }                                                                           \
    __syncthreads();   /* protect smem reuse by epilogue staging */             \
  }

// per-lane swizzled fragment bases for ks = 0,1 (warp grid 2x2, tile 64x64)
#define FRAG_OFFSETS()                                                          \
  uint32_t aoffk[2], boffk[2];                                                  \
  {                                                                             \
    int arow = wm * 64 + (lane & 15);                                           \
    uint32_t swxA = (uint32_t)((arow >> 1) & 3);                                \
    int brow = wn * 64 + ((lane >> 4) & 1) * 8 + (lane & 7);                    \
    uint32_t swxB = (uint32_t)((brow >> 1) & 3);                                \
    _Pragma("unroll")                                                           \
    for (int ks = 0; ks < 2; ks++) {                                            \
      aoffk[ks] = (uint32_t)(arow * 64 +                                        \
                  ((((lane >> 4) & 1) + 2 * ks) ^ swxA) * 16);                  \
      boffk[ks] = (uint32_t)(brow * 64 +                                        \
                  ((((lane >> 3) & 1) + 2 * ks) ^ swxB) * 16);                  \
    }                                                                           \
  }

#define ACC_TO_SMEM()                                                           \
  {                                                                             \
    const int r0 = wm * 64 + (lane >> 2);                                       \
    const int c0 = wn * 64 + (lane & 3) * 2;                                    \
    _Pragma("unroll")                                                           \
    for (int mi = 0; mi < 4; mi++)                                              \
      _Pragma("unroll")                                                         \
      for (int ni = 0; ni < 8; ni++) {                                          \
        int r = r0 + mi * 16, c = c0 + ni * 8;                                  \
        st[r * 129 + c]           = acc[mi][ni][0];                             \
        st[r * 129 + c + 1]       = acc[mi][ni][1];                             \
        st[(r + 8) * 129 + c]     = acc[mi][ni][2];                             \
        st[(r + 8) * 129 + c + 1] = acc[mi][ni][3];                             \
      }                                                                         \
  }

// ================= fused GEMM: logits mask (528) + h (512) ==================
__global__ __launch_bounds__(NT, 2)
void gemm_fused(const __half* __restrict__ xhi, const __half* __restrict__ wthi,
                const float* __restrict__ adj, uint32_t* __restrict__ mask,
                __half* __restrict__ hthi) {
  extern __shared__ __align__(16) char smraw[];
  const uint32_t smBase = smem_u32(smraw);
  const int tid = threadIdx.x, wid = tid >> 5, lane = tid & 31;
  const int wm = wid >> 1, wn = wid & 1;

  const int bid = blockIdx.x;
  const bool logits = bid < 528;
  int bm, bn;
  if (logits) {
    int rem = bid, bi = 0;
    while (rem >= 32 - bi) { rem -= 32 - bi; bi++; }
    bm = bi * 128; bn = (bi + rem) * 128;
  } else {
    int t = bid - 528;                     // 512 blocks: 32 m-tiles x 16 n-tiles
    int group = t >> 7;                    // 8-row supergroups
    int rem = t & 127;
    bm = (group * 8 + (rem & 7)) * 128;
    bn = (rem >> 3) * 128;
  }

  float acc[4][8][4];
#pragma unroll
  for (int i = 0; i < 4; i++)
#pragma unroll
    for (int j = 0; j < 8; j++)
#pragma unroll
      for (int v = 0; v < 4; v++) acc[i][j][v] = 0.f;

  FRAG_OFFSETS();

  if (logits) {
    GEMM_MAINLOOP_1P(xhi, xhi, DD, DD, DD, bm, bn);
  } else {
    GEMM_MAINLOOP_1P(xhi, wthi, DD, DD, DD, bm, bn);
  }

  float* st = (float*)smraw;
  ACC_TO_SMEM();
  __syncthreads();

  if (logits) {
    // build mask words: 128 rows x 4 words per tile (512 words, 4/thread)
#pragma unroll
    for (int s = 0; s < 4; s++) {
      int idx = s * NT + tid;
      int rr = idx >> 2, wc = idx & 3;
      int gm = bm + rr;
      const float* arow = adj + (size_t)gm * NN + bn + wc * 32;
      uint32_t word = 0;
#pragma unroll 8
      for (int b = 0; b < 32; b++) {
        float v = st[rr * 129 + wc * 32 + b];
        if (arow[b] * v > 0.f) word |= (1u << b);
        push_fix(fabsf(v) < DOT_THR, (gm << 12) | (bn + wc * 32 + b));
      }
      mask[(size_t)gm * 128 + (bn >> 5) + wc] = word;
    }
    if (bm != bn) {   // mirrored half: dot symmetric, transposed smem read
#pragma unroll
      for (int s = 0; s < 4; s++) {
        int idx = s * NT + tid;
        int rr = idx >> 2, wc = idx & 3;
        int gm = bn + rr;
        const float* arow = adj + (size_t)gm * NN + bm + wc * 32;
        uint32_t word = 0;
#pragma unroll 8
        for (int b = 0; b < 32; b++) {
          float v = st[(wc * 32 + b) * 129 + rr];
          if (arow[b] * v > 0.f) word |= (1u << b);
          push_fix(fabsf(v) < DOT_THR, (gm << 12) | (bm + wc * 32 + b));
        }
        mask[(size_t)gm * 128 + (bm >> 5) + wc] = word;
      }
    }
  } else {
    // transposed write: h_t[n][m] fp16, coalesced along m
#pragma unroll 4
    for (int s = 0; s < 128; s++) {
      int idx = s * NT + tid;
      int n = idx >> 7, m = idx & 127;
      hthi[(size_t)(bn + n) * NN + bm + m] = __float2half(st[m * 129 + n]);
    }
  }
}

// ================= out GEMM: out = elu(attention @ h) =======================
__global__ __launch_bounds__(NT, 2)
void gemm_out(const __half* __restrict__ phi, const __half* __restrict__ hthi,
              float* __restrict__ out) {
  extern __shared__ __align__(16) char smraw[];
  const uint32_t smBase = smem_u32(smraw);
  const int tid = threadIdx.x, wid = tid >> 5, lane = tid & 31;
  const int wm = wid >> 1, wn = wid & 1;

  const int t = blockIdx.x;
  const int group = t >> 7;
  const int rem = t & 127;
  const int bm = (group * 8 + (rem & 7)) * 128;
  const int bn = (rem >> 3) * 128;

  float acc[4][8][4];
#pragma unroll
  for (int i = 0; i < 4; i++)
#pragma unroll
    for (int j = 0; j < 8; j++)
#pragma unroll
      for (int v = 0; v < 4; v++) acc[i][j][v] = 0.f;

  FRAG_OFFSETS();

  GEMM_MAINLOOP_1P(phi, hthi, NN, NN, NN, bm, bn);

  float* st = (float*)smraw;
  ACC_TO_SMEM();
  __syncthreads();

#pragma unroll 4
  for (int s = 0; s < 128; s++) {
    int idx = s * NT + tid;
    int rr = idx >> 7, cc = idx & 127;
    float v = st[rr * 129 + cc];
    float o = (v > 0.f) ? v : expm1f(v);
    out[(size_t)(bm + rr) * DD + bn + cc] = o;
  }
}

// ================= fixup: exact fp32 dot -> set/clear mask bit ==============
__global__ __launch_bounds__(256) void fixup_kernel(
    const float* __restrict__ x, const float* __restrict__ adj,
    uint32_t* __restrict__ mask) {
  const int n = min(g_cnt, MAX_FIX);
  const int warps = gridDim.x * (blockDim.x >> 5);
  const int w0 = blockIdx.x * (blockDim.x >> 5) + (threadIdx.x >> 5);
  const int lane = threadIdx.x & 31;
  for (int idx = w0; idx < n; idx += warps) {
    const int code = g_list[idx];
    const int i = code >> 12, j = code & 4095;
    const float4* xi = (const float4*)(x + (size_t)i * DD);
    const float4* xj = (const float4*)(x + (size_t)j * DD);
    float s = 0.f;
#pragma unroll 4
    for (int k = lane; k < DD / 4; k += 32) {
      float4 a = xi[k], b = xj[k];
      s = fmaf(a.x, b.x, s);
      s = fmaf(a.y, b.y, s);
      s = fmaf(a.z, b.z, s);
      s = fmaf(a.w, b.w, s);
    }
#pragma unroll
    for (int off = 16; off; off >>= 1) s += __shfl_xor_sync(0xffffffffu, s, off);
    if (lane == 0) {
      float av = adj[(size_t)i * NN + j];
      uint32_t* w = &mask[(size_t)i * 128 + (j >> 5)];
      uint32_t bit = 1u << (j & 31);
      if (av * s > 0.f) atomicOr(w, bit);
      else              atomicAnd(w, ~bit);
    }
  }
}

// ================= support kernels ==========================================
// per-row: x -> fp16, and s1 = x@wa1, s2 = x@wa2 (fused, single x pass)
__global__ __launch_bounds__(256) void split_s(const float* __restrict__ x,
    const float* __restrict__ wa1, const float* __restrict__ wa2,
    __half* __restrict__ xhi, float* __restrict__ s1, float* __restrict__ s2) {
  const int row = blockIdx.x;
  const int tid = threadIdx.x;
  const float4* xr = (const float4*)(x + (size_t)row * DD);
  const float4* a1 = (const float4*)wa1;
  const float4* a2 = (const float4*)wa2;
  float p1 = 0.f, p2 = 0.f;
#pragma unroll
  for (int t = 0; t < 2; t++) {
    int k = tid + t * 256;            // float4 index, 0..511
    float4 v = xr[k], b1 = a1[k], b2 = a2[k];
    p1 = fmaf(v.x, b1.x, p1); p1 = fmaf(v.y, b1.y, p1);
    p1 = fmaf(v.z, b1.z, p1); p1 = fmaf(v.w, b1.w, p1);
    p2 = fmaf(v.x, b2.x, p2); p2 = fmaf(v.y, b2.y, p2);
    p2 = fmaf(v.z, b2.z, p2); p2 = fmaf(v.w, b2.w, p2);
    __half2 h0 = __floats2half2_rn(v.x, v.y);
    __half2 h1 = __floats2half2_rn(v.z, v.w);
    *(__half2*)(xhi + (size_t)row * DD + k * 4)     = h0;
    *(__half2*)(xhi + (size_t)row * DD + k * 4 + 2) = h1;
  }
#pragma unroll
  for (int off = 16; off; off >>= 1) {
    p1 += __shfl_xor_sync(0xffffffffu, p1, off);
    p2 += __shfl_xor_sync(0xffffffffu, p2, off);
  }
  __shared__ float r1[8], r2[8];
  const int warp = tid >> 5, lane = tid & 31;
  if (lane == 0) { r1[warp] = p1; r2[warp] = p2; }
  __syncthreads();
  if (tid == 0) {
    float t1 = 0.f, t2 = 0.f;
#pragma unroll
    for (int w = 0; w < 8; w++) { t1 += r1[w]; t2 += r2[w]; }
    s1[row] = t1;
    s2[row] = t2;
    if (row == 0) g_cnt = 0;
  }
}

__global__ __launch_bounds__(256) void trans_w(const float* __restrict__ W,
    __half* __restrict__ wthi) {
  __shared__ float t[32][33];
  const int bx = blockIdx.x * 32, by = blockIdx.y * 32;  // bx: n, by: k
  const int tx = threadIdx.x, ty = threadIdx.y;          // block (32,8)
#pragma unroll
  for (int rep = 0; rep < 4; rep++)
    t[ty + rep * 8][tx] = W[(size_t)(by + ty + rep * 8) * DD + bx + tx];
  __syncthreads();
#pragma unroll
  for (int rep = 0; rep < 4; rep++)
    wthi[(size_t)(bx + ty + rep * 8) * DD + by + tx] =
        __float2half(t[tx][ty + rep * 8]);
}

// rows x D fp32 GEMV, 2 RHS: o1 = M@v1, o2 = M@v2 (one warp per row)
__global__ __launch_bounds__(256) void gemv2(const float* __restrict__ M,
    const float* __restrict__ v1, const float* __restrict__ v2,
    float* __restrict__ o1, float* __restrict__ o2) {
  const int row = blockIdx.x * 8 + (threadIdx.x >> 5);
  const int lane = threadIdx.x & 31;
  const float4* mr = (const float4*)(M + (size_t)row * DD);
  const float4* a1 = (const float4*)v1;
  const float4* a2 = (const float4*)v2;
  float p1 = 0.f, p2 = 0.f;
#pragma unroll 4
  for (int k = lane; k < DD / 4; k += 32) {
    float4 m = mr[k], b1 = a1[k], b2 = a2[k];
    p1 = fmaf(m.x, b1.x, p1); p1 = fmaf(m.y, b1.y, p1);
    p1 = fmaf(m.z, b1.z, p1); p1 = fmaf(m.w, b1.w, p1);
    p2 = fmaf(m.x, b2.x, p2); p2 = fmaf(m.y, b2.y, p2);
    p2 = fmaf(m.z, b2.z, p2); p2 = fmaf(m.w, b2.w, p2);
  }
#pragma unroll
  for (int off = 16; off; off >>= 1) {
    p1 += __shfl_xor_sync(0xffffffffu, p1, off);
    p2 += __shfl_xor_sync(0xffffffffu, p2, off);
  }
  if (lane == 0) { o1[row] = p1; o2[row] = p2; }
}

// softmax from mask bits: e = leaky(s1[i]+s2[j]) recomputed on the fly
__global__ __launch_bounds__(256) void softmax_rows(
    const uint32_t* __restrict__ mask, const float* __restrict__ s1,
    const float* __restrict__ s2, __half* __restrict__ phi) {
  const int tid = threadIdx.x;
  const int row = blockIdx.x;
  __shared__ uint32_t mw[128];
  __shared__ float red[256];
  if (tid < 128) mw[tid] = mask[(size_t)row * 128 + tid];
  __syncthreads();
  const float s1i = s1[row];

  float vals[16];
  bool mk[16];
  float m = -INFINITY;
#pragma unroll
  for (int t = 0; t < 16; t++) {
    int j = tid + t * 256;
    bool b = (mw[j >> 5] >> (j & 31)) & 1u;
    float e = s1i + s2[j];
    e = (e > 0.f) ? e : 0.1f * e;
    mk[t] = b; vals[t] = e;
    if (b) m = fmaxf(m, e);
  }
  red[tid] = m;
  __syncthreads();
  for (int s = 128; s; s >>= 1) {
    if (tid < s) red[tid] = fmaxf(red[tid], red[tid + s]);
    __syncthreads();
  }
  m = red[0];
  __syncthreads();
  float sum = 0.f;
#pragma unroll
  for (int t = 0; t < 16; t++) {
    float ev = mk[t] ? __expf(vals[t] - m) : 0.f;
    vals[t] = ev;
    sum += ev;
  }
  red[tid] = sum;
  __syncthreads();
  for (int s = 128; s; s >>= 1) {
    if (tid < s) red[tid] += red[tid + s];
    __syncthreads();
  }
  const float tot = red[0];
  const float inv = (tot > 0.f) ? 1.f / tot : 0.f;
  const float uni = 1.f / (float)NN;
#pragma unroll
  for (int t = 0; t < 16; t++) {
    float att = (tot > 0.f) ? vals[t] * inv : uni;
    phi[(size_t)row * NN + tid + t * 256] = __float2half(att);
  }
}

// ================= launch ====================================================
extern "C" void kernel_launch(void* const* d_in, const int* in_sizes, int n_in,
                              void* d_out, int out_size) {
  const float* x   = (const float*)d_in[0];  // (4096, 2048)
  const float* adj = (const float*)d_in[1];  // (4096, 4096)
  const float* W   = (const float*)d_in[2];  // (2048, 2048)
  const float* a   = (const float*)d_in[3];  // (4096, 1)
  float* out = (float*)d_out;                // (4096, 2048)

  __half *xhi, *wthi, *hthi, *phi;
  uint32_t* mask;
  float *s1, *s2, *wa1, *wa2;
  cudaGetSymbolAddress((void**)&xhi,  g_xhi);
  cudaGetSymbolAddress((void**)&wthi, g_wthi);
  cudaGetSymbolAddress((void**)&hthi, g_hthi);
  cudaGetSymbolAddress((void**)&mask, g_mask);
  cudaGetSymbolAddress((void**)&phi,  g_phi);
  cudaGetSymbolAddress((void**)&s1,   g_s1);
  cudaGetSymbolAddress((void**)&s2,   g_s2);
  cudaGetSymbolAddress((void**)&wa1,  g_wa1);
  cudaGetSymbolAddress((void**)&wa2,  g_wa2);

  cudaFuncSetAttribute(gemm_fused, cudaFuncAttributeMaxDynamicSharedMemorySize, SMEM_BYTES);
  cudaFuncSetAttribute(gemm_out,   cudaFuncAttributeMaxDynamicSharedMemorySize, SMEM_BYTES);

  // 1) W -> W^T fp16
  trans_w<<<dim3(DD / 32, DD / 32), dim3(32, 8)>>>(W, wthi);
  // 2) wa = W@a
  gemv2<<<DD / 8, 256>>>(W, a, a + DD, wa1, wa2);
  // 3) x -> fp16 AND s1 = x@wa1, s2 = x@wa2 (fused single pass over x)
  split_s<<<NN, 256>>>(x, wa1, wa2, xhi, s1, s2);
  // 4) fused: logits -> mask bits (triangular x@x^T) AND h = x@W
  gemm_fused<<<528 + 512, NT, SMEM_BYTES>>>(xhi, wthi, adj, mask, hthi);
  // 4b) exact fp32 recompute of near-zero dots -> fix mask bits
  fixup_kernel<<<1024, 256>>>(x, adj, mask);
  // 5) softmax from mask + s1/s2 -> attention fp16
  softmax_rows<<<NN, 256>>>(mask, s1, s2, phi);
  // 6) out = elu(attention @ h), 1-pass BK32 4-stage, swizzled smem
  gemm_out<<<512, NT, SMEM_BYTES>>>(phi, hthi, out);
}